// round 7
// baseline (speedup 1.0000x reference)
#include <cuda_runtime.h>
#include <math.h>
#include <stdint.h>

#define NN 100000
#define EE 1600000
#define IN_CH 64
#define HH 128
#define H3 384
#define GG 4096
#define FULL 0xffffffffu

// sgemm dynamic smem layout (bytes)
#define RAW_A_OFF 0
#define RAW_B_OFF 20480
#define SA_OFF 40960
#define SB_OFF 57856
#define SMEM_TOTAL 74752

// ---------------- scratch (no allocations allowed) ----------------
__device__ float d_x0[NN * HH];
__device__ float d_xw[NN * HH];
__device__ float d_h[NN * HH];
__device__ float d_xc[NN * HH];
__device__ float d_gi[NN * H3];
__device__ float d_gh[NN * H3];
__device__ float d_asrc[NN];
__device__ float d_adst[NN];
__device__ float d_outG[GG * HH];
__device__ float d_hG[GG * HH];
__device__ float d_giG[GG * H3];
__device__ float d_ghG[GG * H3];
__device__ float d_vvec[HH];
__device__ int d_deg[NN];
__device__ int d_ptr[NN + 1];
__device__ int d_cur[NN];
__device__ int d_csr_src[EE];
__device__ int d_bsum[128];
__device__ int d_gptr[GG + 1];

// ---------------- helpers ----------------
__device__ __forceinline__ float warp_sum_all(float v) {
#pragma unroll
    for (int o = 16; o > 0; o >>= 1) v += __shfl_xor_sync(FULL, v, o);
    return v;
}
__device__ __forceinline__ float warp_max_all(float v) {
#pragma unroll
    for (int o = 16; o > 0; o >>= 1) v = fmaxf(v, __shfl_xor_sync(FULL, v, o));
    return v;
}

__device__ __forceinline__ uint32_t f2tf32(float f) {
    uint32_t o;
    asm("cvt.rna.tf32.f32 %0, %1;" : "=r"(o) : "f"(f));
    return o;
}

__device__ __forceinline__ void mma_tf32(float* c, const uint32_t* a, const uint32_t* b) {
    asm volatile(
        "mma.sync.aligned.m16n8k8.row.col.f32.tf32.tf32.f32 "
        "{%0,%1,%2,%3}, {%4,%5,%6,%7}, {%8,%9}, {%0,%1,%2,%3};"
        : "+f"(c[0]), "+f"(c[1]), "+f"(c[2]), "+f"(c[3])
        : "r"(a[0]), "r"(a[1]), "r"(a[2]), "r"(a[3]), "r"(b[0]), "r"(b[1]));
}

__device__ __forceinline__ void cp_async16(uint32_t dst, const void* src, bool pred) {
    asm volatile("cp.async.cg.shared.global [%0], [%1], 16, %2;"
                 :: "r"(dst), "l"(src), "r"(pred ? 16 : 0));
}

// ---------------- pipelined tensor-core fp32 GEMM ----------------
// 3 phases per k16 chunk: cp.async raw -> single shared hi/lo split pass -> pure LDS+MMA.
// C[M,N] = act(A[M,K] @ B[N,K]^T + bias). N % 128 == 0, K % 16 == 0.
__device__ __forceinline__ void gemm_prefetch(const float* __restrict__ A,
                                              const float* __restrict__ B,
                                              int M, int K, int ldb, bool b_vec,
                                              int row0, int col0, int tid, int k0,
                                              float (*rA)[20], float (*rB)[20]) {
#pragma unroll
    for (int it = 0; it < 2; it++) {
        int seg = tid * 2 + it;          // 0..511
        int r = seg >> 2;                // 0..127
        int kg = (seg & 3) << 2;         // 0,4,8,12
        int ar = row0 + r;
        uint32_t da = (uint32_t)__cvta_generic_to_shared(&rA[r][kg]);
        cp_async16(da, A + (size_t)ar * K + k0 + kg, ar < M);
        if (b_vec) {
            uint32_t db = (uint32_t)__cvta_generic_to_shared(&rB[r][kg]);
            cp_async16(db, B + (size_t)(col0 + r) * ldb + k0 + kg, true);
        } else {
            const float* bp = B + (size_t)(col0 + r) * ldb + k0 + kg;
#pragma unroll
            for (int j = 0; j < 4; j++) rB[r][kg + j] = bp[j];
        }
    }
    asm volatile("cp.async.commit_group;");
}

__global__ void __launch_bounds__(256) sgemm(const float* __restrict__ A,
                                             const float* __restrict__ B,
                                             const float* __restrict__ bias,
                                             float* __restrict__ C,
                                             int M, int N, int K, int ldb, int act) {
    extern __shared__ char smem_raw[];
    float (*rawA)[128][20] = (float (*)[128][20])(smem_raw + RAW_A_OFF);
    float (*rawB)[128][20] = (float (*)[128][20])(smem_raw + RAW_B_OFF);
    uint2 (*sA)[132] = (uint2 (*)[132])(smem_raw + SA_OFF);
    uint2 (*sB)[132] = (uint2 (*)[132])(smem_raw + SB_OFF);

    const int tid = threadIdx.x;
    const int lane = tid & 31;
    const int warp = tid >> 5;
    const int g = lane >> 2;
    const int t = lane & 3;
    const int wrow = (warp & 1) * 64;
    const int wcol = (warp >> 1) * 32;
    const int row0 = blockIdx.y * 128;
    const int col0 = blockIdx.x * 128;

    float acc[4][4][4];
#pragma unroll
    for (int mt = 0; mt < 4; mt++)
#pragma unroll
        for (int nt = 0; nt < 4; nt++)
#pragma unroll
            for (int i = 0; i < 4; i++) acc[mt][nt][i] = 0.f;

    const bool b_vec = ((ldb & 3) == 0);
    const int nk = K >> 4;

    gemm_prefetch(A, B, M, K, ldb, b_vec, row0, col0, tid, 0, rawA[0], rawB[0]);

    for (int c = 0; c < nk; c++) {
        asm volatile("cp.async.wait_group 0;");
        __syncthreads();
        if (c + 1 < nk)
            gemm_prefetch(A, B, M, K, ldb, b_vec, row0, col0, tid, (c + 1) << 4,
                          rawA[(c + 1) & 1], rawB[(c + 1) & 1]);
        // --- shared split pass: each element converted exactly once ---
        {
            const float (*rA)[20] = rawA[c & 1];
            const float (*rB)[20] = rawB[c & 1];
#pragma unroll
            for (int j = 0; j < 2; j++) {
                int i = tid * 2 + j;           // 0..511
                int r = i >> 2;                // 0..127
                int kg = (i & 3) << 2;         // 0,4,8,12
                float4 va = *(const float4*)&rA[r][kg];
                float4 vb = *(const float4*)&rB[r][kg];
                const float* ap = &va.x;
                const float* bp = &vb.x;
#pragma unroll
                for (int jj = 0; jj < 4; jj++) {
                    uint32_t hi = f2tf32(ap[jj]);
                    sA[kg + jj][r] = make_uint2(hi, f2tf32(ap[jj] - __uint_as_float(hi)));
                    uint32_t bh = f2tf32(bp[jj]);
                    sB[kg + jj][r] = make_uint2(bh, f2tf32(bp[jj] - __uint_as_float(bh)));
                }
            }
        }
        __syncthreads();
        // --- pure LDS + MMA ---
#pragma unroll
        for (int kk = 0; kk < 2; kk++) {
            const int k8 = kk * 8;
            uint2 a2[4][4];
#pragma unroll
            for (int mt = 0; mt < 4; mt++) {
                int r = wrow + mt * 16 + g;
                a2[mt][0] = sA[k8 + t][r];
                a2[mt][1] = sA[k8 + t][r + 8];
                a2[mt][2] = sA[k8 + t + 4][r];
                a2[mt][3] = sA[k8 + t + 4][r + 8];
            }
            uint2 b2[4][2];
#pragma unroll
            for (int nt = 0; nt < 4; nt++) {
                int cc = wcol + nt * 8 + g;
                b2[nt][0] = sB[k8 + t][cc];
                b2[nt][1] = sB[k8 + t + 4][cc];
            }
#pragma unroll
            for (int mt = 0; mt < 4; mt++) {
                uint32_t ahi[4] = {a2[mt][0].x, a2[mt][1].x, a2[mt][2].x, a2[mt][3].x};
                uint32_t alo[4] = {a2[mt][0].y, a2[mt][1].y, a2[mt][2].y, a2[mt][3].y};
#pragma unroll
                for (int nt = 0; nt < 4; nt++) {
                    uint32_t bhi[2] = {b2[nt][0].x, b2[nt][1].x};
                    uint32_t blo[2] = {b2[nt][0].y, b2[nt][1].y};
                    mma_tf32(acc[mt][nt], alo, bhi);
                    mma_tf32(acc[mt][nt], ahi, blo);
                    mma_tf32(acc[mt][nt], ahi, bhi);
                }
            }
        }
        __syncthreads();
    }

#pragma unroll
    for (int mt = 0; mt < 4; mt++) {
#pragma unroll
        for (int nt = 0; nt < 4; nt++) {
            int r0 = row0 + wrow + mt * 16 + g;
            int c = col0 + wcol + nt * 8 + 2 * t;
            float b0 = bias ? bias[c] : 0.f;
            float b1 = bias ? bias[c + 1] : 0.f;
            float v00 = acc[mt][nt][0] + b0, v01 = acc[mt][nt][1] + b1;
            float v10 = acc[mt][nt][2] + b0, v11 = acc[mt][nt][3] + b1;
            if (act == 1) {
                v00 = v00 > 0.f ? v00 : 0.01f * v00;
                v01 = v01 > 0.f ? v01 : 0.01f * v01;
                v10 = v10 > 0.f ? v10 : 0.01f * v10;
                v11 = v11 > 0.f ? v11 : 0.01f * v11;
            }
            if (r0 < M) {
                C[(size_t)r0 * N + c] = v00;
                C[(size_t)r0 * N + c + 1] = v01;
            }
            if (r0 + 8 < M) {
                C[(size_t)(r0 + 8) * N + c] = v10;
                C[(size_t)(r0 + 8) * N + c + 1] = v11;
            }
        }
    }
}

// ---------------- CSR build ----------------
__global__ void hist_kernel(const int* __restrict__ dst, int* __restrict__ deg, int n_e) {
    int e = blockIdx.x * blockDim.x + threadIdx.x;
    if (e < n_e) atomicAdd(&deg[dst[e]], 1);
}

__global__ void scan_block(const int* __restrict__ in, int* __restrict__ out,
                           int* __restrict__ bsum, int n) {
    __shared__ int s[256];
    int t = threadIdx.x;
    int base = blockIdx.x * 1024 + t * 4;
    int v[4];
#pragma unroll
    for (int j = 0; j < 4; j++) v[j] = (base + j < n) ? in[base + j] : 0;
    int tsum = v[0] + v[1] + v[2] + v[3];
    s[t] = tsum;
    __syncthreads();
    for (int off = 1; off < 256; off <<= 1) {
        int x = (t >= off) ? s[t - off] : 0;
        __syncthreads();
        s[t] += x;
        __syncthreads();
    }
    int exc = s[t] - tsum;
    if (t == 255) bsum[blockIdx.x] = s[t];
    int run = exc;
#pragma unroll
    for (int j = 0; j < 4; j++) {
        if (base + j < n) out[base + j] = run;
        run += v[j];
    }
}

__global__ void scan_bsum(int* __restrict__ bsum, int nb) {
    __shared__ int s[128];
    int t = threadIdx.x;
    int orig = (t < nb) ? bsum[t] : 0;
    s[t] = orig;
    __syncthreads();
    for (int off = 1; off < 128; off <<= 1) {
        int x = (t >= off) ? s[t - off] : 0;
        __syncthreads();
        s[t] += x;
        __syncthreads();
    }
    if (t < nb) bsum[t] = s[t] - orig;
}

__global__ void scan_fixup(int* __restrict__ ptr, const int* __restrict__ bsum,
                           int* __restrict__ cur, int n, int total) {
    int i = blockIdx.x * blockDim.x + threadIdx.x;
    if (i < n) {
        int p = ptr[i] + bsum[i >> 10];
        ptr[i] = p;
        cur[i] = p;
    }
    if (i == 0) ptr[n] = total;
}

__global__ void scatter_csr(const int* __restrict__ src, const int* __restrict__ dst,
                            int* __restrict__ cur, int* __restrict__ csr_src, int n_e) {
    int e = blockIdx.x * blockDim.x + threadIdx.x;
    if (e >= n_e) return;
    int p = atomicAdd(&cur[dst[e]], 1);
    csr_src[p] = src[e];
}

__global__ void build_gptr(const int* __restrict__ batch, int* __restrict__ gptr, int n) {
    int i = blockIdx.x * blockDim.x + threadIdx.x;
    if (i >= n) return;
    int b = batch[i];
    int prev = (i == 0) ? -1 : batch[i - 1];
    for (int g = prev + 1; g <= b; g++) gptr[g] = i;
    if (i == n - 1)
        for (int g = b + 1; g <= GG; g++) gptr[g] = n;
}

// ---------------- fused GAT aggregation (warp per destination node) ----------------
__global__ void gat_aggregate(const int* __restrict__ ptr, const int* __restrict__ csr,
                              const float* __restrict__ asrc, const float* __restrict__ adst,
                              const float* __restrict__ xw, const float* __restrict__ bias,
                              float* __restrict__ h, int n_rows) {
    int row = blockIdx.x * 8 + (threadIdx.x >> 5);
    int lane = threadIdx.x & 31;
    if (row >= n_rows) return;
    int start = ptr[row], end = ptr[row + 1];
    float ad = adst[row];

    float m = -INFINITY;
    for (int e = start + lane; e < end; e += 32) {
        float a = asrc[csr[e]] + ad;
        a = a > 0.f ? a : 0.01f * a;
        m = fmaxf(m, a);
    }
    m = warp_max_all(m);

    float4 acc = make_float4(0.f, 0.f, 0.f, 0.f);
    float sum = 0.f;
    for (int base = start; base < end; base += 32) {
        int e = base + lane;
        float w = 0.f;
        int s = 0;
        if (e < end) {
            s = csr[e];
            float a = asrc[s] + ad;
            a = a > 0.f ? a : 0.01f * a;
            w = expf(a - m);
            sum += w;
        }
        int cnt = min(32, end - base);
        for (int j = 0; j < cnt; j++) {
            float wj = __shfl_sync(FULL, w, j);
            int sj = __shfl_sync(FULL, s, j);
            float4 v = ((const float4*)(xw + (size_t)sj * HH))[lane];
            acc.x += wj * v.x;
            acc.y += wj * v.y;
            acc.z += wj * v.z;
            acc.w += wj * v.w;
        }
    }
    sum = warp_sum_all(sum);
    float rinv = 1.f / (sum + 1e-16f);
    float4 b4 = ((const float4*)bias)[lane];
    float4 o;
    o.x = acc.x * rinv + b4.x;
    o.y = acc.y * rinv + b4.y;
    o.z = acc.z * rinv + b4.z;
    o.w = acc.w * rinv + b4.w;
    o.x = o.x > 0.f ? o.x : expf(o.x) - 1.f;
    o.y = o.y > 0.f ? o.y : expf(o.y) - 1.f;
    o.z = o.z > 0.f ? o.z : expf(o.z) - 1.f;
    o.w = o.w > 0.f ? o.w : expf(o.w) - 1.f;
    ((float4*)(h + (size_t)row * HH))[lane] = o;
}

// ---------------- GATEConv per-node attention scalars ----------------
__global__ void gate_node_atts(const float* __restrict__ tmp, const float* __restrict__ W1,
                               const float* __restrict__ att_l, const float* __restrict__ x0,
                               const float* __restrict__ att_r, float* __restrict__ asrc,
                               float* __restrict__ adst, int n_rows) {
    int w = (blockIdx.x * blockDim.x + threadIdx.x) >> 5;
    int lane = threadIdx.x & 31;
    if (w >= n_rows) return;
    float4 tv = ((const float4*)(tmp + (size_t)w * HH))[lane];
    float4 xv = ((const float4*)(x0 + (size_t)w * HH))[lane];
    float s1 = 0.f, s2 = 0.f;
    const float* t = &tv.x;
    const float* xp = &xv.x;
#pragma unroll
    for (int j = 0; j < 4; j++) {
        int k = lane * 4 + j;
        float xe = t[j] + W1[(size_t)k * (HH + 1) + HH];
        xe = xe > 0.f ? xe : 0.01f * xe;
        s1 += xe * att_l[k];
        s2 += xp[j] * att_r[k];
    }
    s1 = warp_sum_all(s1);
    s2 = warp_sum_all(s2);
    if (lane == 0) { asrc[w] = s1; adst[w] = s2; }
}

__global__ void node_two_dots(const float* __restrict__ xw, const float* __restrict__ v1,
                              const float* __restrict__ v2, float* __restrict__ o1,
                              float* __restrict__ o2, int n_rows) {
    int w = (blockIdx.x * blockDim.x + threadIdx.x) >> 5;
    int lane = threadIdx.x & 31;
    if (w >= n_rows) return;
    float4 xv = ((const float4*)(xw + (size_t)w * HH))[lane];
    const float* xp = &xv.x;
    float s1 = 0.f, s2 = 0.f;
#pragma unroll
    for (int j = 0; j < 4; j++) {
        int k = lane * 4 + j;
        s1 += xp[j] * v1[k];
        s2 += xp[j] * v2[k];
    }
    s1 = warp_sum_all(s1);
    s2 = warp_sum_all(s2);
    if (lane == 0) { o1[w] = s1; o2[w] = s2; }
}

__global__ void node_one_dot(const float* __restrict__ xw, const float* __restrict__ v1,
                             float* __restrict__ o1, int n_rows) {
    int w = (blockIdx.x * blockDim.x + threadIdx.x) >> 5;
    int lane = threadIdx.x & 31;
    if (w >= n_rows) return;
    float4 xv = ((const float4*)(xw + (size_t)w * HH))[lane];
    const float* xp = &xv.x;
    float s1 = 0.f;
#pragma unroll
    for (int j = 0; j < 4; j++) s1 += xp[j] * v1[lane * 4 + j];
    s1 = warp_sum_all(s1);
    if (lane == 0) o1[w] = s1;
}

// ---------------- GRU combine + relu ----------------
__global__ void gru_combine(const float* __restrict__ gi, const float* __restrict__ gh,
                            const float* __restrict__ hprev, float* __restrict__ outp, int rows) {
    int idx = blockIdx.x * blockDim.x + threadIdx.x;
    if (idx >= rows * HH) return;
    int r = idx / HH, c = idx - r * HH;
    const float* gir = gi + (size_t)r * H3;
    const float* ghr = gh + (size_t)r * H3;
    float ir = gir[c], iz = gir[c + HH], in_ = gir[c + 2 * HH];
    float hr = ghr[c], hz = ghr[c + HH], hn = ghr[c + 2 * HH];
    float rr = 1.f / (1.f + expf(-(ir + hr)));
    float z = 1.f / (1.f + expf(-(iz + hz)));
    float n = tanhf(in_ + rr * hn);
    float o = (1.f - z) * n + z * hprev[idx];
    outp[idx] = o > 0.f ? o : 0.f;
}

// ---------------- molecule readout (warp per graph) ----------------
__global__ void graph_sum(const float* __restrict__ xc, const int* __restrict__ gptr,
                          float* __restrict__ outG, int n_g) {
    int g = blockIdx.x * 8 + (threadIdx.x >> 5);
    int lane = threadIdx.x & 31;
    if (g >= n_g) return;
    int start = gptr[g], end = gptr[g + 1];
    float4 acc = make_float4(0.f, 0.f, 0.f, 0.f);
    for (int i = start; i < end; i++) {
        float4 v = ((const float4*)(xc + (size_t)i * HH))[lane];
        acc.x += v.x; acc.y += v.y; acc.z += v.z; acc.w += v.w;
    }
    acc.x = fmaxf(acc.x, 0.f);
    acc.y = fmaxf(acc.y, 0.f);
    acc.z = fmaxf(acc.z, 0.f);
    acc.w = fmaxf(acc.w, 0.f);
    ((float4*)(outG + (size_t)g * HH))[lane] = acc;
}

__global__ void compute_vvec(const float* __restrict__ molW, const float* __restrict__ attdst,
                             float* __restrict__ v) {
    int k = threadIdx.x;
    float s = 0.f;
    for (int j = 0; j < HH; j++) s += molW[(size_t)j * HH + k] * attdst[j];
    v[k] = s;
}

__global__ void mol_timestep(const float* __restrict__ outG, const float* __restrict__ vvec,
                             const int* __restrict__ gptr, const float* __restrict__ asrc,
                             const float* __restrict__ xw, const float* __restrict__ bias,
                             float* __restrict__ hG, int n_g) {
    int g = blockIdx.x * 8 + (threadIdx.x >> 5);
    int lane = threadIdx.x & 31;
    if (g >= n_g) return;
    float4 ov = ((const float4*)(outG + (size_t)g * HH))[lane];
    float4 vv = ((const float4*)vvec)[lane];
    float ad = warp_sum_all(ov.x * vv.x + ov.y * vv.y + ov.z * vv.z + ov.w * vv.w);

    int start = gptr[g], end = gptr[g + 1];
    float m = -INFINITY;
    for (int i = start + lane; i < end; i += 32) {
        float a = asrc[i] + ad;
        a = a > 0.f ? a : 0.01f * a;
        m = fmaxf(m, a);
    }
    m = warp_max_all(m);

    float4 acc = make_float4(0.f, 0.f, 0.f, 0.f);
    float sum = 0.f;
    for (int base = start; base < end; base += 32) {
        int i = base + lane;
        float w = 0.f;
        if (i < end) {
            float a = asrc[i] + ad;
            a = a > 0.f ? a : 0.01f * a;
            w = expf(a - m);
            sum += w;
        }
        int cnt = min(32, end - base);
        for (int j = 0; j < cnt; j++) {
            float wj = __shfl_sync(FULL, w, j);
            float4 v = ((const float4*)(xw + (size_t)(base + j) * HH))[lane];
            acc.x += wj * v.x;
            acc.y += wj * v.y;
            acc.z += wj * v.z;
            acc.w += wj * v.w;
        }
    }
    sum = warp_sum_all(sum);
    float rinv = 1.f / (sum + 1e-16f);
    float4 b4 = ((const float4*)bias)[lane];
    float4 o;
    o.x = acc.x * rinv + b4.x;
    o.y = acc.y * rinv + b4.y;
    o.z = acc.z * rinv + b4.z;
    o.w = acc.w * rinv + b4.w;
    o.x = o.x > 0.f ? o.x : expf(o.x) - 1.f;
    o.y = o.y > 0.f ? o.y : expf(o.y) - 1.f;
    o.z = o.z > 0.f ? o.z : expf(o.z) - 1.f;
    o.w = o.w > 0.f ? o.w : expf(o.w) - 1.f;
    ((float4*)(hG + (size_t)g * HH))[lane] = o;
}

__global__ void final_out(const float* __restrict__ outG, const float* __restrict__ W,
                          const float* __restrict__ b, float* __restrict__ y, int g_rows) {
    int g = (blockIdx.x * blockDim.x + threadIdx.x) >> 5;
    int lane = threadIdx.x & 31;
    if (g >= g_rows) return;
    float4 v = ((const float4*)(outG + (size_t)g * HH))[lane];
    const float* vp = &v.x;
    float s = 0.f;
#pragma unroll
    for (int j = 0; j < 4; j++) s += vp[j] * W[lane * 4 + j];
    s = warp_sum_all(s);
    if (lane == 0) y[g] = s + b[0];
}

// ---------------- host ----------------
static inline int cdiv(int a, int b) { return (a + b - 1) / b; }

extern "C" void kernel_launch(void* const* d_in, const int* in_sizes, int n_in,
                              void* d_out, int out_size) {
    const float* x = (const float*)d_in[0];
    const int* ei = (const int*)d_in[1];
    const int* batch = (const int*)d_in[2];
    const float* lin1_W = (const float*)d_in[3];
    const float* lin1_b = (const float*)d_in[4];
    const float* gate_W1 = (const float*)d_in[5];
    const float* gate_W2 = (const float*)d_in[6];
    const float* gate_att_l = (const float*)d_in[7];
    const float* gate_att_r = (const float*)d_in[8];
    const float* gate_bias = (const float*)d_in[9];
    const float* gru0_Wi = (const float*)d_in[10];
    const float* gru0_bi = (const float*)d_in[11];
    const float* gru0_Wh = (const float*)d_in[12];
    const float* gru0_bh = (const float*)d_in[13];
    const float* atom_W = (const float*)d_in[14];
    const float* atom_att_src = (const float*)d_in[15];
    const float* atom_att_dst = (const float*)d_in[16];
    const float* atom_bias = (const float*)d_in[17];
    const float* atom_gru_Wi = (const float*)d_in[18];
    const float* atom_gru_bi = (const float*)d_in[19];
    const float* atom_gru_Wh = (const float*)d_in[20];
    const float* atom_gru_bh = (const float*)d_in[21];
    const float* mol_W = (const float*)d_in[22];
    const float* mol_att_src = (const float*)d_in[23];
    const float* mol_att_dst = (const float*)d_in[24];
    const float* mol_bias = (const float*)d_in[25];
    const float* mol_gru_Wi = (const float*)d_in[26];
    const float* mol_gru_bi = (const float*)d_in[27];
    const float* mol_gru_Wh = (const float*)d_in[28];
    const float* mol_gru_bh = (const float*)d_in[29];
    const float* lin2_W = (const float*)d_in[30];
    const float* lin2_b = (const float*)d_in[31];

    const int* src = ei;
    const int* dst = ei + EE;

    // opt-in to >48KB dynamic shared memory (idempotent host-side call)
    cudaFuncSetAttribute(sgemm, cudaFuncAttributeMaxDynamicSharedMemorySize, SMEM_TOTAL);

    float *x0, *xw, *h, *xc, *gi, *gh, *asrc, *adst;
    float *outG, *hG, *giG, *ghG, *vvec;
    int *deg, *ptr, *cur, *csr_src, *bsum, *gptr;
    cudaGetSymbolAddress((void**)&x0, d_x0);
    cudaGetSymbolAddress((void**)&xw, d_xw);
    cudaGetSymbolAddress((void**)&h, d_h);
    cudaGetSymbolAddress((void**)&xc, d_xc);
    cudaGetSymbolAddress((void**)&gi, d_gi);
    cudaGetSymbolAddress((void**)&gh, d_gh);
    cudaGetSymbolAddress((void**)&asrc, d_asrc);
    cudaGetSymbolAddress((void**)&adst, d_adst);
    cudaGetSymbolAddress((void**)&outG, d_outG);
    cudaGetSymbolAddress((void**)&hG, d_hG);
    cudaGetSymbolAddress((void**)&giG, d_giG);
    cudaGetSymbolAddress((void**)&ghG, d_ghG);
    cudaGetSymbolAddress((void**)&vvec, d_vvec);
    cudaGetSymbolAddress((void**)&deg, d_deg);
    cudaGetSymbolAddress((void**)&ptr, d_ptr);
    cudaGetSymbolAddress((void**)&cur, d_cur);
    cudaGetSymbolAddress((void**)&csr_src, d_csr_src);
    cudaGetSymbolAddress((void**)&bsum, d_bsum);
    cudaGetSymbolAddress((void**)&gptr, d_gptr);

    dim3 g_n128(1, cdiv(NN, 128));
    dim3 g_n384(3, cdiv(NN, 128));
    dim3 g_g384(3, cdiv(GG, 128));
    int wpb_n = cdiv(NN, 8);
    int wpb_g = cdiv(GG, 8);
    const int nscan = cdiv(NN, 1024);

    // ---- CSR + graph-pointer build ----
    cudaMemsetAsync(deg, 0, NN * sizeof(int));
    hist_kernel<<<cdiv(EE, 256), 256>>>(dst, deg, EE);
    scan_block<<<nscan, 256>>>(deg, ptr, bsum, NN);
    scan_bsum<<<1, 128>>>(bsum, nscan);
    scan_fixup<<<cdiv(NN, 256), 256>>>(ptr, bsum, cur, NN, EE);
    scatter_csr<<<cdiv(EE, 256), 256>>>(src, dst, cur, csr_src, EE);
    build_gptr<<<cdiv(NN, 256), 256>>>(batch, gptr, NN);

    // x0 = lrelu(x @ lin1_W^T + b)
    sgemm<<<g_n128, 256, SMEM_TOTAL>>>(x, lin1_W, lin1_b, x0, NN, HH, IN_CH, IN_CH, 1);

    // ---- GATEConv ----
    sgemm<<<g_n128, 256, SMEM_TOTAL>>>(x0, gate_W1, nullptr, xw, NN, HH, HH, HH + 1, 0);
    gate_node_atts<<<wpb_n, 256>>>(xw, gate_W1, gate_att_l, x0, gate_att_r, asrc, adst, NN);
    sgemm<<<g_n128, 256, SMEM_TOTAL>>>(x0, gate_W2, nullptr, xw, NN, HH, HH, HH, 0);
    gat_aggregate<<<wpb_n, 256>>>(ptr, csr_src, asrc, adst, xw, gate_bias, h, NN);
    sgemm<<<g_n384, 256, SMEM_TOTAL>>>(h, gru0_Wi, gru0_bi, gi, NN, H3, HH, HH, 0);
    sgemm<<<g_n384, 256, SMEM_TOTAL>>>(x0, gru0_Wh, gru0_bh, gh, NN, H3, HH, HH, 0);
    gru_combine<<<cdiv(NN * HH, 256), 256>>>(gi, gh, x0, xc, NN);

    // ---- extra atom GAT + GRU layers ----
    for (int l = 0; l < 2; l++) {
        sgemm<<<g_n128, 256, SMEM_TOTAL>>>(xc, atom_W + (size_t)l * HH * HH, nullptr, xw, NN, HH, HH, HH, 0);
        node_two_dots<<<wpb_n, 256>>>(xw, atom_att_src + l * HH, atom_att_dst + l * HH, asrc, adst, NN);
        gat_aggregate<<<wpb_n, 256>>>(ptr, csr_src, asrc, adst, xw, atom_bias + l * HH, h, NN);
        sgemm<<<g_n384, 256, SMEM_TOTAL>>>(h, atom_gru_Wi + (size_t)l * H3 * HH, atom_gru_bi + l * H3, gi, NN, H3, HH, HH, 0);
        sgemm<<<g_n384, 256, SMEM_TOTAL>>>(xc, atom_gru_Wh + (size_t)l * H3 * HH, atom_gru_bh + l * H3, gh, NN, H3, HH, HH, 0);
        gru_combine<<<cdiv(NN * HH, 256), 256>>>(gi, gh, xc, xc, NN);
    }

    // ---- molecule readout ----
    graph_sum<<<wpb_g, 256>>>(xc, gptr, outG, GG);
    sgemm<<<g_n128, 256, SMEM_TOTAL>>>(xc, mol_W, nullptr, xw, NN, HH, HH, HH, 0);
    node_one_dot<<<wpb_n, 256>>>(xw, mol_att_src, asrc, NN);
    compute_vvec<<<1, HH>>>(mol_W, mol_att_dst, vvec);

    for (int t = 0; t < 2; t++) {
        mol_timestep<<<wpb_g, 256>>>(outG, vvec, gptr, asrc, xw, mol_bias, hG, GG);
        sgemm<<<g_g384, 256, SMEM_TOTAL>>>(hG, mol_gru_Wi, mol_gru_bi, giG, GG, H3, HH, HH, 0);
        sgemm<<<g_g384, 256, SMEM_TOTAL>>>(outG, mol_gru_Wh, mol_gru_bh, ghG, GG, H3, HH, HH, 0);
        gru_combine<<<cdiv(GG * HH, 256), 256>>>(giG, ghG, outG, outG, GG);
    }

    final_out<<<wpb_g, 256>>>(outG, lin2_W, lin2_b, (float*)d_out, GG);
}

// round 8
// speedup vs baseline: 1.1486x; 1.1486x over previous
#include <cuda_runtime.h>
#include <math.h>
#include <stdint.h>

#define NN 100000
#define EE 1600000
#define IN_CH 64
#define HH 128
#define H3 384
#define GG 4096
#define FULL 0xffffffffu

// sgemm dynamic smem: 3 stages x (A raw 128x20 + B raw 128x20) floats
#define STAGE_BYTES 10240
#define SMEM_TOTAL (3 * 2 * STAGE_BYTES)

// ---------------- scratch (no allocations allowed) ----------------
__device__ float d_x0[NN * HH];
__device__ float d_xw[NN * HH];
__device__ float d_h[NN * HH];
__device__ float d_xc[NN * HH];
__device__ float d_gi[NN * H3];
__device__ float d_gh[NN * H3];
__device__ float d_asrc[NN];
__device__ float d_adst[NN];
__device__ float d_outG[GG * HH];
__device__ float d_hG[GG * HH];
__device__ float d_giG[GG * H3];
__device__ float d_ghG[GG * H3];
__device__ float d_vvec[HH];
__device__ int d_deg[NN];
__device__ int d_ptr[NN + 1];
__device__ int d_cur[NN];
__device__ int d_csr_src[EE];
__device__ int d_bsum[128];
__device__ int d_gptr[GG + 1];

// ---------------- helpers ----------------
__device__ __forceinline__ float warp_sum_all(float v) {
#pragma unroll
    for (int o = 16; o > 0; o >>= 1) v += __shfl_xor_sync(FULL, v, o);
    return v;
}
__device__ __forceinline__ float warp_max_all(float v) {
#pragma unroll
    for (int o = 16; o > 0; o >>= 1) v = fmaxf(v, __shfl_xor_sync(FULL, v, o));
    return v;
}

__device__ __forceinline__ uint32_t f2tf32(float f) {
    uint32_t o;
    asm("cvt.rna.tf32.f32 %0, %1;" : "=r"(o) : "f"(f));
    return o;
}

__device__ __forceinline__ void mma_tf32(float* c, const uint32_t* a, const uint32_t* b) {
    asm volatile(
        "mma.sync.aligned.m16n8k8.row.col.f32.tf32.tf32.f32 "
        "{%0,%1,%2,%3}, {%4,%5,%6,%7}, {%8,%9}, {%0,%1,%2,%3};"
        : "+f"(c[0]), "+f"(c[1]), "+f"(c[2]), "+f"(c[3])
        : "r"(a[0]), "r"(a[1]), "r"(a[2]), "r"(a[3]), "r"(b[0]), "r"(b[1]));
}

__device__ __forceinline__ void cp_async16(uint32_t dst, const void* src, bool pred) {
    asm volatile("cp.async.cg.shared.global [%0], [%1], 16, %2;"
                 :: "r"(dst), "l"(src), "r"(pred ? 16 : 0));
}

// ---------------- pipelined tensor-core fp32 GEMM (3xTF32, register split, depth-3) ----
// C[M,N] = act(A[M,K] @ B[N,K]^T + bias). N % 128 == 0, K % 16 == 0, K >= 32.
// act: 0 = none, 1 = leaky_relu(0.01)
__device__ __forceinline__ void gemm_prefetch(const float* __restrict__ A,
                                              const float* __restrict__ B,
                                              int M, int K, int ldb, bool b_vec,
                                              int row0, int col0, int tid, int k0,
                                              float (*rA)[20], float (*rB)[20]) {
#pragma unroll
    for (int it = 0; it < 2; it++) {
        int seg = tid * 2 + it;          // 0..511
        int r = seg >> 2;                // 0..127
        int kg = (seg & 3) << 2;         // 0,4,8,12
        int ar = row0 + r;
        uint32_t da = (uint32_t)__cvta_generic_to_shared(&rA[r][kg]);
        cp_async16(da, A + (size_t)ar * K + k0 + kg, ar < M);
        if (b_vec) {
            uint32_t db = (uint32_t)__cvta_generic_to_shared(&rB[r][kg]);
            cp_async16(db, B + (size_t)(col0 + r) * ldb + k0 + kg, true);
        } else {
            const float* bp = B + (size_t)(col0 + r) * ldb + k0 + kg;
#pragma unroll
            for (int j = 0; j < 4; j++) rB[r][kg + j] = bp[j];
        }
    }
    asm volatile("cp.async.commit_group;");
}

__global__ void __launch_bounds__(256) sgemm(const float* __restrict__ A,
                                             const float* __restrict__ B,
                                             const float* __restrict__ bias,
                                             float* __restrict__ C,
                                             int M, int N, int K, int ldb, int act) {
    extern __shared__ char smem_dyn[];
    float (*rawA)[128][20] = (float (*)[128][20])(smem_dyn);
    float (*rawB)[128][20] = (float (*)[128][20])(smem_dyn + 3 * STAGE_BYTES);

    const int tid = threadIdx.x;
    const int lane = tid & 31;
    const int warp = tid >> 5;
    const int g = lane >> 2;
    const int t = lane & 3;
    const int wrow = (warp & 1) * 64;
    const int wcol = (warp >> 1) * 32;
    const int row0 = blockIdx.y * 128;
    const int col0 = blockIdx.x * 128;

    float acc[4][4][4];
#pragma unroll
    for (int mt = 0; mt < 4; mt++)
#pragma unroll
        for (int nt = 0; nt < 4; nt++)
#pragma unroll
            for (int i = 0; i < 4; i++) acc[mt][nt][i] = 0.f;

    const bool b_vec = ((ldb & 3) == 0);
    const int nk = K >> 4;

    gemm_prefetch(A, B, M, K, ldb, b_vec, row0, col0, tid, 0, rawA[0], rawB[0]);
    if (nk > 1)
        gemm_prefetch(A, B, M, K, ldb, b_vec, row0, col0, tid, 16, rawA[1], rawB[1]);

    int buf = 0;
    for (int c = 0; c < nk; c++) {
        if (c + 1 < nk)
            asm volatile("cp.async.wait_group 1;");
        else
            asm volatile("cp.async.wait_group 0;");
        __syncthreads();
        if (c + 2 < nk) {
            int nb = buf + 2; if (nb >= 3) nb -= 3;
            gemm_prefetch(A, B, M, K, ldb, b_vec, row0, col0, tid, (c + 2) << 4,
                          rawA[nb], rawB[nb]);
        }
        const float (*Asb)[20] = rawA[buf];
        const float (*Bsb)[20] = rawB[buf];
#pragma unroll
        for (int kk = 0; kk < 2; kk++) {
            const int k8 = kk * 8;
            uint32_t ahi[4][4], alo[4][4];
#pragma unroll
            for (int mt = 0; mt < 4; mt++) {
                int r = wrow + mt * 16 + g;
                float f0 = Asb[r][k8 + t];
                float f1 = Asb[r + 8][k8 + t];
                float f2 = Asb[r][k8 + t + 4];
                float f3 = Asb[r + 8][k8 + t + 4];
                ahi[mt][0] = f2tf32(f0); alo[mt][0] = f2tf32(f0 - __uint_as_float(ahi[mt][0]));
                ahi[mt][1] = f2tf32(f1); alo[mt][1] = f2tf32(f1 - __uint_as_float(ahi[mt][1]));
                ahi[mt][2] = f2tf32(f2); alo[mt][2] = f2tf32(f2 - __uint_as_float(ahi[mt][2]));
                ahi[mt][3] = f2tf32(f3); alo[mt][3] = f2tf32(f3 - __uint_as_float(ahi[mt][3]));
            }
            uint32_t bhi[4][2], blo[4][2];
#pragma unroll
            for (int nt = 0; nt < 4; nt++) {
                int cc = wcol + nt * 8 + g;
                float f0 = Bsb[cc][k8 + t];
                float f1 = Bsb[cc][k8 + t + 4];
                bhi[nt][0] = f2tf32(f0); blo[nt][0] = f2tf32(f0 - __uint_as_float(bhi[nt][0]));
                bhi[nt][1] = f2tf32(f1); blo[nt][1] = f2tf32(f1 - __uint_as_float(bhi[nt][1]));
            }
#pragma unroll
            for (int mt = 0; mt < 4; mt++)
#pragma unroll
                for (int nt = 0; nt < 4; nt++) {
                    mma_tf32(acc[mt][nt], alo[mt], bhi[nt]);
                    mma_tf32(acc[mt][nt], ahi[mt], blo[nt]);
                    mma_tf32(acc[mt][nt], ahi[mt], bhi[nt]);
                }
        }
        if (++buf >= 3) buf = 0;
    }

#pragma unroll
    for (int mt = 0; mt < 4; mt++) {
#pragma unroll
        for (int nt = 0; nt < 4; nt++) {
            int r0 = row0 + wrow + mt * 16 + g;
            int c = col0 + wcol + nt * 8 + 2 * t;
            float b0 = bias ? bias[c] : 0.f;
            float b1 = bias ? bias[c + 1] : 0.f;
            float v00 = acc[mt][nt][0] + b0, v01 = acc[mt][nt][1] + b1;
            float v10 = acc[mt][nt][2] + b0, v11 = acc[mt][nt][3] + b1;
            if (act == 1) {
                v00 = v00 > 0.f ? v00 : 0.01f * v00;
                v01 = v01 > 0.f ? v01 : 0.01f * v01;
                v10 = v10 > 0.f ? v10 : 0.01f * v10;
                v11 = v11 > 0.f ? v11 : 0.01f * v11;
            }
            if (r0 < M) {
                C[(size_t)r0 * N + c] = v00;
                C[(size_t)r0 * N + c + 1] = v01;
            }
            if (r0 + 8 < M) {
                C[(size_t)(r0 + 8) * N + c] = v10;
                C[(size_t)(r0 + 8) * N + c + 1] = v11;
            }
        }
    }
}

// ---------------- CSR build ----------------
__global__ void hist_kernel(const int* __restrict__ dst, int* __restrict__ deg, int n_e) {
    int e = blockIdx.x * blockDim.x + threadIdx.x;
    if (e < n_e) atomicAdd(&deg[dst[e]], 1);
}

__global__ void scan_block(const int* __restrict__ in, int* __restrict__ out,
                           int* __restrict__ bsum, int n) {
    __shared__ int s[256];
    int t = threadIdx.x;
    int base = blockIdx.x * 1024 + t * 4;
    int v[4];
#pragma unroll
    for (int j = 0; j < 4; j++) v[j] = (base + j < n) ? in[base + j] : 0;
    int tsum = v[0] + v[1] + v[2] + v[3];
    s[t] = tsum;
    __syncthreads();
    for (int off = 1; off < 256; off <<= 1) {
        int x = (t >= off) ? s[t - off] : 0;
        __syncthreads();
        s[t] += x;
        __syncthreads();
    }
    int exc = s[t] - tsum;
    if (t == 255) bsum[blockIdx.x] = s[t];
    int run = exc;
#pragma unroll
    for (int j = 0; j < 4; j++) {
        if (base + j < n) out[base + j] = run;
        run += v[j];
    }
}

__global__ void scan_bsum(int* __restrict__ bsum, int nb) {
    __shared__ int s[128];
    int t = threadIdx.x;
    int orig = (t < nb) ? bsum[t] : 0;
    s[t] = orig;
    __syncthreads();
    for (int off = 1; off < 128; off <<= 1) {
        int x = (t >= off) ? s[t - off] : 0;
        __syncthreads();
        s[t] += x;
        __syncthreads();
    }
    if (t < nb) bsum[t] = s[t] - orig;
}

__global__ void scan_fixup(int* __restrict__ ptr, const int* __restrict__ bsum,
                           int* __restrict__ cur, int n, int total) {
    int i = blockIdx.x * blockDim.x + threadIdx.x;
    if (i < n) {
        int p = ptr[i] + bsum[i >> 10];
        ptr[i] = p;
        cur[i] = p;
    }
    if (i == 0) ptr[n] = total;
}

__global__ void scatter_csr(const int* __restrict__ src, const int* __restrict__ dst,
                            int* __restrict__ cur, int* __restrict__ csr_src, int n_e) {
    int e = blockIdx.x * blockDim.x + threadIdx.x;
    if (e >= n_e) return;
    int p = atomicAdd(&cur[dst[e]], 1);
    csr_src[p] = src[e];
}

__global__ void build_gptr(const int* __restrict__ batch, int* __restrict__ gptr, int n) {
    int i = blockIdx.x * blockDim.x + threadIdx.x;
    if (i >= n) return;
    int b = batch[i];
    int prev = (i == 0) ? -1 : batch[i - 1];
    for (int g = prev + 1; g <= b; g++) gptr[g] = i;
    if (i == n - 1)
        for (int g = b + 1; g <= GG; g++) gptr[g] = n;
}

// ---------------- fused GAT aggregation (warp per destination node) ----------------
__global__ void gat_aggregate(const int* __restrict__ ptr, const int* __restrict__ csr,
                              const float* __restrict__ asrc, const float* __restrict__ adst,
                              const float* __restrict__ xw, const float* __restrict__ bias,
                              float* __restrict__ h, int n_rows) {
    int row = blockIdx.x * 8 + (threadIdx.x >> 5);
    int lane = threadIdx.x & 31;
    if (row >= n_rows) return;
    int start = ptr[row], end = ptr[row + 1];
    float ad = adst[row];

    float m = -INFINITY;
    for (int e = start + lane; e < end; e += 32) {
        float a = asrc[csr[e]] + ad;
        a = a > 0.f ? a : 0.01f * a;
        m = fmaxf(m, a);
    }
    m = warp_max_all(m);

    float4 acc = make_float4(0.f, 0.f, 0.f, 0.f);
    float sum = 0.f;
    for (int base = start; base < end; base += 32) {
        int e = base + lane;
        float w = 0.f;
        int s = 0;
        if (e < end) {
            s = csr[e];
            float a = asrc[s] + ad;
            a = a > 0.f ? a : 0.01f * a;
            w = expf(a - m);
            sum += w;
        }
        int cnt = min(32, end - base);
        for (int j = 0; j < cnt; j++) {
            float wj = __shfl_sync(FULL, w, j);
            int sj = __shfl_sync(FULL, s, j);
            float4 v = ((const float4*)(xw + (size_t)sj * HH))[lane];
            acc.x += wj * v.x;
            acc.y += wj * v.y;
            acc.z += wj * v.z;
            acc.w += wj * v.w;
        }
    }
    sum = warp_sum_all(sum);
    float rinv = 1.f / (sum + 1e-16f);
    float4 b4 = ((const float4*)bias)[lane];
    float4 o;
    o.x = acc.x * rinv + b4.x;
    o.y = acc.y * rinv + b4.y;
    o.z = acc.z * rinv + b4.z;
    o.w = acc.w * rinv + b4.w;
    o.x = o.x > 0.f ? o.x : expf(o.x) - 1.f;
    o.y = o.y > 0.f ? o.y : expf(o.y) - 1.f;
    o.z = o.z > 0.f ? o.z : expf(o.z) - 1.f;
    o.w = o.w > 0.f ? o.w : expf(o.w) - 1.f;
    ((float4*)(h + (size_t)row * HH))[lane] = o;
}

// ---------------- GATEConv per-node attention scalars ----------------
__global__ void gate_node_atts(const float* __restrict__ tmp, const float* __restrict__ W1,
                               const float* __restrict__ att_l, const float* __restrict__ x0,
                               const float* __restrict__ att_r, float* __restrict__ asrc,
                               float* __restrict__ adst, int n_rows) {
    int w = (blockIdx.x * blockDim.x + threadIdx.x) >> 5;
    int lane = threadIdx.x & 31;
    if (w >= n_rows) return;
    float4 tv = ((const float4*)(tmp + (size_t)w * HH))[lane];
    float4 xv = ((const float4*)(x0 + (size_t)w * HH))[lane];
    float s1 = 0.f, s2 = 0.f;
    const float* t = &tv.x;
    const float* xp = &xv.x;
#pragma unroll
    for (int j = 0; j < 4; j++) {
        int k = lane * 4 + j;
        float xe = t[j] + W1[(size_t)k * (HH + 1) + HH];
        xe = xe > 0.f ? xe : 0.01f * xe;
        s1 += xe * att_l[k];
        s2 += xp[j] * att_r[k];
    }
    s1 = warp_sum_all(s1);
    s2 = warp_sum_all(s2);
    if (lane == 0) { asrc[w] = s1; adst[w] = s2; }
}

__global__ void node_two_dots(const float* __restrict__ xw, const float* __restrict__ v1,
                              const float* __restrict__ v2, float* __restrict__ o1,
                              float* __restrict__ o2, int n_rows) {
    int w = (blockIdx.x * blockDim.x + threadIdx.x) >> 5;
    int lane = threadIdx.x & 31;
    if (w >= n_rows) return;
    float4 xv = ((const float4*)(xw + (size_t)w * HH))[lane];
    const float* xp = &xv.x;
    float s1 = 0.f, s2 = 0.f;
#pragma unroll
    for (int j = 0; j < 4; j++) {
        int k = lane * 4 + j;
        s1 += xp[j] * v1[k];
        s2 += xp[j] * v2[k];
    }
    s1 = warp_sum_all(s1);
    s2 = warp_sum_all(s2);
    if (lane == 0) { o1[w] = s1; o2[w] = s2; }
}

__global__ void node_one_dot(const float* __restrict__ xw, const float* __restrict__ v1,
                             float* __restrict__ o1, int n_rows) {
    int w = (blockIdx.x * blockDim.x + threadIdx.x) >> 5;
    int lane = threadIdx.x & 31;
    if (w >= n_rows) return;
    float4 xv = ((const float4*)(xw + (size_t)w * HH))[lane];
    const float* xp = &xv.x;
    float s1 = 0.f;
#pragma unroll
    for (int j = 0; j < 4; j++) s1 += xp[j] * v1[lane * 4 + j];
    s1 = warp_sum_all(s1);
    if (lane == 0) o1[w] = s1;
}

// ---------------- GRU combine + relu ----------------
__global__ void gru_combine(const float* __restrict__ gi, const float* __restrict__ gh,
                            const float* __restrict__ hprev, float* __restrict__ outp, int rows) {
    int idx = blockIdx.x * blockDim.x + threadIdx.x;
    if (idx >= rows * HH) return;
    int r = idx / HH, c = idx - r * HH;
    const float* gir = gi + (size_t)r * H3;
    const float* ghr = gh + (size_t)r * H3;
    float ir = gir[c], iz = gir[c + HH], in_ = gir[c + 2 * HH];
    float hr = ghr[c], hz = ghr[c + HH], hn = ghr[c + 2 * HH];
    float rr = 1.f / (1.f + expf(-(ir + hr)));
    float z = 1.f / (1.f + expf(-(iz + hz)));
    float n = tanhf(in_ + rr * hn);
    float o = (1.f - z) * n + z * hprev[idx];
    outp[idx] = o > 0.f ? o : 0.f;
}

// ---------------- molecule readout (warp per graph) ----------------
__global__ void graph_sum(const float* __restrict__ xc, const int* __restrict__ gptr,
                          float* __restrict__ outG, int n_g) {
    int g = blockIdx.x * 8 + (threadIdx.x >> 5);
    int lane = threadIdx.x & 31;
    if (g >= n_g) return;
    int start = gptr[g], end = gptr[g + 1];
    float4 acc = make_float4(0.f, 0.f, 0.f, 0.f);
    for (int i = start; i < end; i++) {
        float4 v = ((const float4*)(xc + (size_t)i * HH))[lane];
        acc.x += v.x; acc.y += v.y; acc.z += v.z; acc.w += v.w;
    }
    acc.x = fmaxf(acc.x, 0.f);
    acc.y = fmaxf(acc.y, 0.f);
    acc.z = fmaxf(acc.z, 0.f);
    acc.w = fmaxf(acc.w, 0.f);
    ((float4*)(outG + (size_t)g * HH))[lane] = acc;
}

__global__ void compute_vvec(const float* __restrict__ molW, const float* __restrict__ attdst,
                             float* __restrict__ v) {
    int k = threadIdx.x;
    float s = 0.f;
    for (int j = 0; j < HH; j++) s += molW[(size_t)j * HH + k] * attdst[j];
    v[k] = s;
}

__global__ void mol_timestep(const float* __restrict__ outG, const float* __restrict__ vvec,
                             const int* __restrict__ gptr, const float* __restrict__ asrc,
                             const float* __restrict__ xw, const float* __restrict__ bias,
                             float* __restrict__ hG, int n_g) {
    int g = blockIdx.x * 8 + (threadIdx.x >> 5);
    int lane = threadIdx.x & 31;
    if (g >= n_g) return;
    float4 ov = ((const float4*)(outG + (size_t)g * HH))[lane];
    float4 vv = ((const float4*)vvec)[lane];
    float ad = warp_sum_all(ov.x * vv.x + ov.y * vv.y + ov.z * vv.z + ov.w * vv.w);

    int start = gptr[g], end = gptr[g + 1];
    float m = -INFINITY;
    for (int i = start + lane; i < end; i += 32) {
        float a = asrc[i] + ad;
        a = a > 0.f ? a : 0.01f * a;
        m = fmaxf(m, a);
    }
    m = warp_max_all(m);

    float4 acc = make_float4(0.f, 0.f, 0.f, 0.f);
    float sum = 0.f;
    for (int base = start; base < end; base += 32) {
        int i = base + lane;
        float w = 0.f;
        if (i < end) {
            float a = asrc[i] + ad;
            a = a > 0.f ? a : 0.01f * a;
            w = expf(a - m);
            sum += w;
        }
        int cnt = min(32, end - base);
        for (int j = 0; j < cnt; j++) {
            float wj = __shfl_sync(FULL, w, j);
            float4 v = ((const float4*)(xw + (size_t)(base + j) * HH))[lane];
            acc.x += wj * v.x;
            acc.y += wj * v.y;
            acc.z += wj * v.z;
            acc.w += wj * v.w;
        }
    }
    sum = warp_sum_all(sum);
    float rinv = 1.f / (sum + 1e-16f);
    float4 b4 = ((const float4*)bias)[lane];
    float4 o;
    o.x = acc.x * rinv + b4.x;
    o.y = acc.y * rinv + b4.y;
    o.z = acc.z * rinv + b4.z;
    o.w = acc.w * rinv + b4.w;
    o.x = o.x > 0.f ? o.x : expf(o.x) - 1.f;
    o.y = o.y > 0.f ? o.y : expf(o.y) - 1.f;
    o.z = o.z > 0.f ? o.z : expf(o.z) - 1.f;
    o.w = o.w > 0.f ? o.w : expf(o.w) - 1.f;
    ((float4*)(hG + (size_t)g * HH))[lane] = o;
}

__global__ void final_out(const float* __restrict__ outG, const float* __restrict__ W,
                          const float* __restrict__ b, float* __restrict__ y, int g_rows) {
    int g = (blockIdx.x * blockDim.x + threadIdx.x) >> 5;
    int lane = threadIdx.x & 31;
    if (g >= g_rows) return;
    float4 v = ((const float4*)(outG + (size_t)g * HH))[lane];
    const float* vp = &v.x;
    float s = 0.f;
#pragma unroll
    for (int j = 0; j < 4; j++) s += vp[j] * W[lane * 4 + j];
    s = warp_sum_all(s);
    if (lane == 0) y[g] = s + b[0];
}

// ---------------- host ----------------
static inline int cdiv(int a, int b) { return (a + b - 1) / b; }

extern "C" void kernel_launch(void* const* d_in, const int* in_sizes, int n_in,
                              void* d_out, int out_size) {
    const float* x = (const float*)d_in[0];
    const int* ei = (const int*)d_in[1];
    const int* batch = (const int*)d_in[2];
    const float* lin1_W = (const float*)d_in[3];
    const float* lin1_b = (const float*)d_in[4];
    const float* gate_W1 = (const float*)d_in[5];
    const float* gate_W2 = (const float*)d_in[6];
    const float* gate_att_l = (const float*)d_in[7];
    const float* gate_att_r = (const float*)d_in[8];
    const float* gate_bias = (const float*)d_in[9];
    const float* gru0_Wi = (const float*)d_in[10];
    const float* gru0_bi = (const float*)d_in[11];
    const float* gru0_Wh = (const float*)d_in[12];
    const float* gru0_bh = (const float*)d_in[13];
    const float* atom_W = (const float*)d_in[14];
    const float* atom_att_src = (const float*)d_in[15];
    const float* atom_att_dst = (const float*)d_in[16];
    const float* atom_bias = (const float*)d_in[17];
    const float* atom_gru_Wi = (const float*)d_in[18];
    const float* atom_gru_bi = (const float*)d_in[19];
    const float* atom_gru_Wh = (const float*)d_in[20];
    const float* atom_gru_bh = (const float*)d_in[21];
    const float* mol_W = (const float*)d_in[22];
    const float* mol_att_src = (const float*)d_in[23];
    const float* mol_att_dst = (const float*)d_in[24];
    const float* mol_bias = (const float*)d_in[25];
    const float* mol_gru_Wi = (const float*)d_in[26];
    const float* mol_gru_bi = (const float*)d_in[27];
    const float* mol_gru_Wh = (const float*)d_in[28];
    const float* mol_gru_bh = (const float*)d_in[29];
    const float* lin2_W = (const float*)d_in[30];
    const float* lin2_b = (const float*)d_in[31];

    const int* src = ei;
    const int* dst = ei + EE;

    // opt-in to >48KB dynamic shared memory (idempotent host-side call)
    cudaFuncSetAttribute(sgemm, cudaFuncAttributeMaxDynamicSharedMemorySize, SMEM_TOTAL);

    float *x0, *xw, *h, *xc, *gi, *gh, *asrc, *adst;
    float *outG, *hG, *giG, *ghG, *vvec;
    int *deg, *ptr, *cur, *csr_src, *bsum, *gptr;
    cudaGetSymbolAddress((void**)&x0, d_x0);
    cudaGetSymbolAddress((void**)&xw, d_xw);
    cudaGetSymbolAddress((void**)&h, d_h);
    cudaGetSymbolAddress((void**)&xc, d_xc);
    cudaGetSymbolAddress((void**)&gi, d_gi);
    cudaGetSymbolAddress((void**)&gh, d_gh);
    cudaGetSymbolAddress((void**)&asrc, d_asrc);
    cudaGetSymbolAddress((void**)&adst, d_adst);
    cudaGetSymbolAddress((void**)&outG, d_outG);
    cudaGetSymbolAddress((void**)&hG, d_hG);
    cudaGetSymbolAddress((void**)&giG, d_giG);
    cudaGetSymbolAddress((void**)&ghG, d_ghG);
    cudaGetSymbolAddress((void**)&vvec, d_vvec);
    cudaGetSymbolAddress((void**)&deg, d_deg);
    cudaGetSymbolAddress((void**)&ptr, d_ptr);
    cudaGetSymbolAddress((void**)&cur, d_cur);
    cudaGetSymbolAddress((void**)&csr_src, d_csr_src);
    cudaGetSymbolAddress((void**)&bsum, d_bsum);
    cudaGetSymbolAddress((void**)&gptr, d_gptr);

    dim3 g_n128(1, cdiv(NN, 128));
    dim3 g_n384(3, cdiv(NN, 128));
    dim3 g_g384(3, cdiv(GG, 128));
    int wpb_n = cdiv(NN, 8);
    int wpb_g = cdiv(GG, 8);
    const int nscan = cdiv(NN, 1024);

    // ---- CSR + graph-pointer build ----
    cudaMemsetAsync(deg, 0, NN * sizeof(int));
    hist_kernel<<<cdiv(EE, 256), 256>>>(dst, deg, EE);
    scan_block<<<nscan, 256>>>(deg, ptr, bsum, NN);
    scan_bsum<<<1, 128>>>(bsum, nscan);
    scan_fixup<<<cdiv(NN, 256), 256>>>(ptr, bsum, cur, NN, EE);
    scatter_csr<<<cdiv(EE, 256), 256>>>(src, dst, cur, csr_src, EE);
    build_gptr<<<cdiv(NN, 256), 256>>>(batch, gptr, NN);

    // x0 = lrelu(x @ lin1_W^T + b)
    sgemm<<<g_n128, 256, SMEM_TOTAL>>>(x, lin1_W, lin1_b, x0, NN, HH, IN_CH, IN_CH, 1);

    // ---- GATEConv ----
    sgemm<<<g_n128, 256, SMEM_TOTAL>>>(x0, gate_W1, nullptr, xw, NN, HH, HH, HH + 1, 0);
    gate_node_atts<<<wpb_n, 256>>>(xw, gate_W1, gate_att_l, x0, gate_att_r, asrc, adst, NN);
    sgemm<<<g_n128, 256, SMEM_TOTAL>>>(x0, gate_W2, nullptr, xw, NN, HH, HH, HH, 0);
    gat_aggregate<<<wpb_n, 256>>>(ptr, csr_src, asrc, adst, xw, gate_bias, h, NN);
    sgemm<<<g_n384, 256, SMEM_TOTAL>>>(h, gru0_Wi, gru0_bi, gi, NN, H3, HH, HH, 0);
    sgemm<<<g_n384, 256, SMEM_TOTAL>>>(x0, gru0_Wh, gru0_bh, gh, NN, H3, HH, HH, 0);
    gru_combine<<<cdiv(NN * HH, 256), 256>>>(gi, gh, x0, xc, NN);

    // ---- extra atom GAT + GRU layers ----
    for (int l = 0; l < 2; l++) {
        sgemm<<<g_n128, 256, SMEM_TOTAL>>>(xc, atom_W + (size_t)l * HH * HH, nullptr, xw, NN, HH, HH, HH, 0);
        node_two_dots<<<wpb_n, 256>>>(xw, atom_att_src + l * HH, atom_att_dst + l * HH, asrc, adst, NN);
        gat_aggregate<<<wpb_n, 256>>>(ptr, csr_src, asrc, adst, xw, atom_bias + l * HH, h, NN);
        sgemm<<<g_n384, 256, SMEM_TOTAL>>>(h, atom_gru_Wi + (size_t)l * H3 * HH, atom_gru_bi + l * H3, gi, NN, H3, HH, HH, 0);
        sgemm<<<g_n384, 256, SMEM_TOTAL>>>(xc, atom_gru_Wh + (size_t)l * H3 * HH, atom_gru_bh + l * H3, gh, NN, H3, HH, HH, 0);
        gru_combine<<<cdiv(NN * HH, 256), 256>>>(gi, gh, xc, xc, NN);
    }

    // ---- molecule readout ----
    graph_sum<<<wpb_g, 256>>>(xc, gptr, outG, GG);
    sgemm<<<g_n128, 256, SMEM_TOTAL>>>(xc, mol_W, nullptr, xw, NN, HH, HH, HH, 0);
    node_one_dot<<<wpb_n, 256>>>(xw, mol_att_src, asrc, NN);
    compute_vvec<<<1, HH>>>(mol_W, mol_att_dst, vvec);

    for (int t = 0; t < 2; t++) {
        mol_timestep<<<wpb_g, 256>>>(outG, vvec, gptr, asrc, xw, mol_bias, hG, GG);
        sgemm<<<g_g384, 256, SMEM_TOTAL>>>(hG, mol_gru_Wi, mol_gru_bi, giG, GG, H3, HH, HH, 0);
        sgemm<<<g_g384, 256, SMEM_TOTAL>>>(outG, mol_gru_Wh, mol_gru_bh, ghG, GG, H3, HH, HH, 0);
        gru_combine<<<cdiv(GG * HH, 256), 256>>>(giG, ghG, outG, outG, GG);
    }

    final_out<<<wpb_g, 256>>>(outG, lin2_W, lin2_b, (float*)d_out, GG);
}

// round 9
// speedup vs baseline: 1.3732x; 1.1955x over previous
#include <cuda_runtime.h>
#include <cuda_bf16.h>
#include <math.h>
#include <stdint.h>

#define NN 100000
#define EE 1600000
#define IN_CH 64
#define HH 128
#define H3 384
#define GG 4096
#define FULL 0xffffffffu

// bgemm smem: 4 planes (Ahi,Alo,Bhi,Blo) x 128 rows x 12 words, 2 stages
#define PLANE 1536
#define STAGEW 6144
#define BG_SMEM (2 * STAGEW * 4)   // bytes = 49152

// ---------------- scratch (no allocations allowed) ----------------
__device__ float d_x0[NN * HH];
__device__ float d_xw[NN * HH];
__device__ float d_xc[NN * HH];
__device__ float d_gi[NN * H3];
__device__ float d_gh[NN * H3];
__device__ float d_asrc[NN];
__device__ float d_adst[NN];
__device__ float d_outG[GG * HH];
__device__ float d_giG[GG * H3];
__device__ float d_ghG[GG * H3];
__device__ float d_vvec[HH];
__device__ int d_deg[NN];
__device__ int d_ptr[NN + 1];
__device__ int d_cur[NN];
__device__ int d_csr_src[EE];
__device__ int d_bsum[128];
__device__ int d_gptr[GG + 1];
// bf16-split buffers (same bytes as fp32 originals): row r = [K/2 hi-pairs][K/2 lo-pairs]
__device__ uint32_t s_x[NN * IN_CH];
__device__ uint32_t s_x0[NN * HH];
__device__ uint32_t s_h[NN * HH];
__device__ uint32_t s_xc[NN * HH];
__device__ uint32_t s_hG[GG * HH];
__device__ uint32_t s_outG[GG * HH];
__device__ uint32_t w_lin1[HH * IN_CH];
__device__ uint32_t w_g1[HH * HH];
__device__ uint32_t w_g2[HH * HH];
__device__ uint32_t w_g0i[H3 * HH];
__device__ uint32_t w_g0h[H3 * HH];
__device__ uint32_t w_atom[2 * HH * HH];
__device__ uint32_t w_atomi[2 * H3 * HH];
__device__ uint32_t w_atomh[2 * H3 * HH];
__device__ uint32_t w_mol[HH * HH];
__device__ uint32_t w_moli[H3 * HH];
__device__ uint32_t w_molh[H3 * HH];

// ---------------- helpers ----------------
__device__ __forceinline__ float warp_sum_all(float v) {
#pragma unroll
    for (int o = 16; o > 0; o >>= 1) v += __shfl_xor_sync(FULL, v, o);
    return v;
}
__device__ __forceinline__ float warp_max_all(float v) {
#pragma unroll
    for (int o = 16; o > 0; o >>= 1) v = fmaxf(v, __shfl_xor_sync(FULL, v, o));
    return v;
}

// split pair (f0 at even k, f1 at odd k) -> hi-pair (truncated bf16) + lo-pair (rounded bf16)
__device__ __forceinline__ void split_pair(float f0, float f1, uint32_t& hp, uint32_t& lp) {
    uint32_t u0 = __float_as_uint(f0), u1 = __float_as_uint(f1);
    hp = __byte_perm(u0, u1, 0x7632);   // low16 = hi(f0), high16 = hi(f1)
    float l0 = f0 - __uint_as_float(u0 & 0xffff0000u);
    float l1 = f1 - __uint_as_float(u1 & 0xffff0000u);
    __nv_bfloat162 p = __floats2bfloat162_rn(l0, l1);  // .x (low) = l0
    lp = *reinterpret_cast<uint32_t*>(&p);
}

__device__ __forceinline__ void mma_bf16(float* c, const uint32_t* a, const uint32_t* b) {
    asm volatile(
        "mma.sync.aligned.m16n8k16.row.col.f32.bf16.bf16.f32 "
        "{%0,%1,%2,%3}, {%4,%5,%6,%7}, {%8,%9}, {%0,%1,%2,%3};"
        : "+f"(c[0]), "+f"(c[1]), "+f"(c[2]), "+f"(c[3])
        : "r"(a[0]), "r"(a[1]), "r"(a[2]), "r"(a[3]), "r"(b[0]), "r"(b[1]));
}

__device__ __forceinline__ void cp_async16(uint32_t dst, const void* src, bool pred) {
    asm volatile("cp.async.cg.shared.global [%0], [%1], 16, %2;"
                 :: "r"(dst), "l"(src), "r"(pred ? 16 : 0));
}

// ---------------- fp32 -> split converter ----------------
__global__ void to_split(const float* __restrict__ src, int ld, uint32_t* __restrict__ dst,
                         int M, int K) {
    int idx = blockIdx.x * blockDim.x + threadIdx.x;
    int kh = K >> 1;
    if (idx >= M * kh) return;
    int r = idx / kh, j = idx - r * kh;
    float f0 = src[(size_t)r * ld + 2 * j];
    float f1 = src[(size_t)r * ld + 2 * j + 1];
    uint32_t hp, lp;
    split_pair(f0, f1, hp, lp);
    dst[(size_t)r * K + j] = hp;
    dst[(size_t)r * K + kh + j] = lp;
}

// ---------------- bf16-split tensor-core GEMM ----------------
// C[M,N] = act(A[M,K] @ B[N,K]^T + bias); A,B in split format (row stride K words).
// If Cs != null, also writes C in split format (row stride N words).
__device__ __forceinline__ void bload(const uint32_t* __restrict__ Ahl,
                                      const uint32_t* __restrict__ Bhl,
                                      int M, int K, int Kh, int row0, int col0,
                                      int tid, int kc, uint32_t* sb) {
#pragma unroll
    for (int it = 0; it < 4; it++) {
        int s = tid * 4 + it;          // 0..1023
        int p = s >> 8;                // plane: 0 Ahi,1 Alo,2 Bhi,3 Blo
        int rem = s & 255;
        int r = rem >> 1;
        int j = rem & 1;
        uint32_t da = (uint32_t)__cvta_generic_to_shared(sb + p * PLANE + r * 12 + j * 4);
        const uint32_t* g;
        bool pred = true;
        if (p < 2) {
            int ar = row0 + r;
            pred = ar < M;
            g = Ahl + (size_t)(pred ? ar : 0) * K + (p == 1 ? Kh : 0) + kc * 8 + j * 4;
        } else {
            g = Bhl + (size_t)(col0 + r) * K + (p == 3 ? Kh : 0) + kc * 8 + j * 4;
        }
        cp_async16(da, g, pred);
    }
    asm volatile("cp.async.commit_group;");
}

__global__ void __launch_bounds__(256) bgemm(const uint32_t* __restrict__ Ahl,
                                             const uint32_t* __restrict__ Bhl,
                                             const float* __restrict__ bias,
                                             float* __restrict__ C,
                                             uint32_t* __restrict__ Cs,
                                             int M, int N, int K, int act) {
    extern __shared__ uint32_t sm[];
    const int tid = threadIdx.x;
    const int lane = tid & 31;
    const int warp = tid >> 5;
    const int g = lane >> 2;
    const int t = lane & 3;
    const int wrow = (warp & 1) * 64;
    const int wcol = (warp >> 1) * 32;
    const int row0 = blockIdx.y * 128;
    const int col0 = blockIdx.x * 128;
    const int Kh = K >> 1;
    const int nk = K >> 4;

    float acc[4][4][4];
#pragma unroll
    for (int mt = 0; mt < 4; mt++)
#pragma unroll
        for (int nt = 0; nt < 4; nt++)
#pragma unroll
            for (int i = 0; i < 4; i++) acc[mt][nt][i] = 0.f;

    bload(Ahl, Bhl, M, K, Kh, row0, col0, tid, 0, sm);

    for (int c = 0; c < nk; c++) {
        asm volatile("cp.async.wait_group 0;");
        __syncthreads();
        if (c + 1 < nk)
            bload(Ahl, Bhl, M, K, Kh, row0, col0, tid, c + 1, sm + ((c + 1) & 1) * STAGEW);
        const uint32_t* Sb = sm + (c & 1) * STAGEW;
        const uint32_t* Ahi = Sb;
        const uint32_t* Alo = Sb + PLANE;
        const uint32_t* Bhi = Sb + 2 * PLANE;
        const uint32_t* Blo = Sb + 3 * PLANE;

        uint32_t bhi[4][2], blo[4][2];
#pragma unroll
        for (int nt = 0; nt < 4; nt++) {
            int cc = wcol + nt * 8 + g;
            bhi[nt][0] = Bhi[cc * 12 + t];
            bhi[nt][1] = Bhi[cc * 12 + t + 4];
            blo[nt][0] = Blo[cc * 12 + t];
            blo[nt][1] = Blo[cc * 12 + t + 4];
        }
#pragma unroll
        for (int mt = 0; mt < 4; mt++) {
            int r = wrow + mt * 16 + g;
            uint32_t ahi[4], alo[4];
            ahi[0] = Ahi[r * 12 + t];
            ahi[1] = Ahi[(r + 8) * 12 + t];
            ahi[2] = Ahi[r * 12 + t + 4];
            ahi[3] = Ahi[(r + 8) * 12 + t + 4];
            alo[0] = Alo[r * 12 + t];
            alo[1] = Alo[(r + 8) * 12 + t];
            alo[2] = Alo[r * 12 + t + 4];
            alo[3] = Alo[(r + 8) * 12 + t + 4];
#pragma unroll
            for (int nt = 0; nt < 4; nt++) {
                mma_bf16(acc[mt][nt], alo, bhi[nt]);
                mma_bf16(acc[mt][nt], ahi, blo[nt]);
                mma_bf16(acc[mt][nt], ahi, bhi[nt]);
            }
        }
        __syncthreads();
    }

#pragma unroll
    for (int mt = 0; mt < 4; mt++) {
#pragma unroll
        for (int nt = 0; nt < 4; nt++) {
            int r0 = row0 + wrow + mt * 16 + g;
            int c = col0 + wcol + nt * 8 + 2 * t;
            float b0 = bias ? bias[c] : 0.f;
            float b1 = bias ? bias[c + 1] : 0.f;
            float v00 = acc[mt][nt][0] + b0, v01 = acc[mt][nt][1] + b1;
            float v10 = acc[mt][nt][2] + b0, v11 = acc[mt][nt][3] + b1;
            if (act == 1) {
                v00 = v00 > 0.f ? v00 : 0.01f * v00;
                v01 = v01 > 0.f ? v01 : 0.01f * v01;
                v10 = v10 > 0.f ? v10 : 0.01f * v10;
                v11 = v11 > 0.f ? v11 : 0.01f * v11;
            }
            if (r0 < M) {
                C[(size_t)r0 * N + c] = v00;
                C[(size_t)r0 * N + c + 1] = v01;
                if (Cs) {
                    uint32_t hp, lp;
                    split_pair(v00, v01, hp, lp);
                    Cs[(size_t)r0 * N + (c >> 1)] = hp;
                    Cs[(size_t)r0 * N + (N >> 1) + (c >> 1)] = lp;
                }
            }
            if (r0 + 8 < M) {
                C[(size_t)(r0 + 8) * N + c] = v10;
                C[(size_t)(r0 + 8) * N + c + 1] = v11;
                if (Cs) {
                    uint32_t hp, lp;
                    split_pair(v10, v11, hp, lp);
                    Cs[(size_t)(r0 + 8) * N + (c >> 1)] = hp;
                    Cs[(size_t)(r0 + 8) * N + (N >> 1) + (c >> 1)] = lp;
                }
            }
        }
    }
}

// ---------------- CSR build ----------------
__global__ void hist_kernel(const int* __restrict__ dst, int* __restrict__ deg, int n_e) {
    int e = blockIdx.x * blockDim.x + threadIdx.x;
    if (e < n_e) atomicAdd(&deg[dst[e]], 1);
}

__global__ void scan_block(const int* __restrict__ in, int* __restrict__ out,
                           int* __restrict__ bsum, int n) {
    __shared__ int s[256];
    int t = threadIdx.x;
    int base = blockIdx.x * 1024 + t * 4;
    int v[4];
#pragma unroll
    for (int j = 0; j < 4; j++) v[j] = (base + j < n) ? in[base + j] : 0;
    int tsum = v[0] + v[1] + v[2] + v[3];
    s[t] = tsum;
    __syncthreads();
    for (int off = 1; off < 256; off <<= 1) {
        int x = (t >= off) ? s[t - off] : 0;
        __syncthreads();
        s[t] += x;
        __syncthreads();
    }
    int exc = s[t] - tsum;
    if (t == 255) bsum[blockIdx.x] = s[t];
    int run = exc;
#pragma unroll
    for (int j = 0; j < 4; j++) {
        if (base + j < n) out[base + j] = run;
        run += v[j];
    }
}

__global__ void scan_bsum(int* __restrict__ bsum, int nb) {
    __shared__ int s[128];
    int t = threadIdx.x;
    int orig = (t < nb) ? bsum[t] : 0;
    s[t] = orig;
    __syncthreads();
    for (int off = 1; off < 128; off <<= 1) {
        int x = (t >= off) ? s[t - off] : 0;
        __syncthreads();
        s[t] += x;
        __syncthreads();
    }
    if (t < nb) bsum[t] = s[t] - orig;
}

__global__ void scan_fixup(int* __restrict__ ptr, const int* __restrict__ bsum,
                           int* __restrict__ cur, int n, int total) {
    int i = blockIdx.x * blockDim.x + threadIdx.x;
    if (i < n) {
        int p = ptr[i] + bsum[i >> 10];
        ptr[i] = p;
        cur[i] = p;
    }
    if (i == 0) ptr[n] = total;
}

__global__ void scatter_csr(const int* __restrict__ src, const int* __restrict__ dst,
                            int* __restrict__ cur, int* __restrict__ csr_src, int n_e) {
    int e = blockIdx.x * blockDim.x + threadIdx.x;
    if (e >= n_e) return;
    int p = atomicAdd(&cur[dst[e]], 1);
    csr_src[p] = src[e];
}

__global__ void build_gptr(const int* __restrict__ batch, int* __restrict__ gptr, int n) {
    int i = blockIdx.x * blockDim.x + threadIdx.x;
    if (i >= n) return;
    int b = batch[i];
    int prev = (i == 0) ? -1 : batch[i - 1];
    for (int g = prev + 1; g <= b; g++) gptr[g] = i;
    if (i == n - 1)
        for (int g = b + 1; g <= GG; g++) gptr[g] = n;
}

// ---------------- fused GAT aggregation (warp per destination node) ----------------
// writes h in SPLIT format only (h feeds the GRU-Wi GEMM exclusively)
__global__ void gat_aggregate(const int* __restrict__ ptr, const int* __restrict__ csr,
                              const float* __restrict__ asrc, const float* __restrict__ adst,
                              const float* __restrict__ xw, const float* __restrict__ bias,
                              uint32_t* __restrict__ hs, int n_rows) {
    int row = blockIdx.x * 8 + (threadIdx.x >> 5);
    int lane = threadIdx.x & 31;
    if (row >= n_rows) return;
    int start = ptr[row], end = ptr[row + 1];
    float ad = adst[row];

    float m = -INFINITY;
    for (int e = start + lane; e < end; e += 32) {
        float a = asrc[csr[e]] + ad;
        a = a > 0.f ? a : 0.01f * a;
        m = fmaxf(m, a);
    }
    m = warp_max_all(m);

    float4 acc = make_float4(0.f, 0.f, 0.f, 0.f);
    float sum = 0.f;
    for (int base = start; base < end; base += 32) {
        int e = base + lane;
        float w = 0.f;
        int s = 0;
        if (e < end) {
            s = csr[e];
            float a = asrc[s] + ad;
            a = a > 0.f ? a : 0.01f * a;
            w = expf(a - m);
            sum += w;
        }
        int cnt = min(32, end - base);
        for (int j = 0; j < cnt; j++) {
            float wj = __shfl_sync(FULL, w, j);
            int sj = __shfl_sync(FULL, s, j);
            float4 v = ((const float4*)(xw + (size_t)sj * HH))[lane];
            acc.x += wj * v.x;
            acc.y += wj * v.y;
            acc.z += wj * v.z;
            acc.w += wj * v.w;
        }
    }
    sum = warp_sum_all(sum);
    float rinv = 1.f / (sum + 1e-16f);
    float4 b4 = ((const float4*)bias)[lane];
    float o0 = acc.x * rinv + b4.x;
    float o1 = acc.y * rinv + b4.y;
    float o2 = acc.z * rinv + b4.z;
    float o3 = acc.w * rinv + b4.w;
    o0 = o0 > 0.f ? o0 : expf(o0) - 1.f;
    o1 = o1 > 0.f ? o1 : expf(o1) - 1.f;
    o2 = o2 > 0.f ? o2 : expf(o2) - 1.f;
    o3 = o3 > 0.f ? o3 : expf(o3) - 1.f;
    uint32_t hp0, lp0, hp1, lp1;
    split_pair(o0, o1, hp0, lp0);
    split_pair(o2, o3, hp1, lp1);
    uint32_t* hr = hs + (size_t)row * HH;
    hr[2 * lane] = hp0;
    hr[2 * lane + 1] = hp1;
    hr[64 + 2 * lane] = lp0;
    hr[64 + 2 * lane + 1] = lp1;
}

// ---------------- GATEConv per-node attention scalars ----------------
__global__ void gate_node_atts(const float* __restrict__ tmp, const float* __restrict__ W1,
                               const float* __restrict__ att_l, const float* __restrict__ x0,
                               const float* __restrict__ att_r, float* __restrict__ asrc,
                               float* __restrict__ adst, int n_rows) {
    int w = (blockIdx.x * blockDim.x + threadIdx.x) >> 5;
    int lane = threadIdx.x & 31;
    if (w >= n_rows) return;
    float4 tv = ((const float4*)(tmp + (size_t)w * HH))[lane];
    float4 xv = ((const float4*)(x0 + (size_t)w * HH))[lane];
    float s1 = 0.f, s2 = 0.f;
    const float* t = &tv.x;
    const float* xp = &xv.x;
#pragma unroll
    for (int j = 0; j < 4; j++) {
        int k = lane * 4 + j;
        float xe = t[j] + W1[(size_t)k * (HH + 1) + HH];
        xe = xe > 0.f ? xe : 0.01f * xe;
        s1 += xe * att_l[k];
        s2 += xp[j] * att_r[k];
    }
    s1 = warp_sum_all(s1);
    s2 = warp_sum_all(s2);
    if (lane == 0) { asrc[w] = s1; adst[w] = s2; }
}

__global__ void node_two_dots(const float* __restrict__ xw, const float* __restrict__ v1,
                              const float* __restrict__ v2, float* __restrict__ o1,
                              float* __restrict__ o2, int n_rows) {
    int w = (blockIdx.x * blockDim.x + threadIdx.x) >> 5;
    int lane = threadIdx.x & 31;
    if (w >= n_rows) return;
    float4 xv = ((const float4*)(xw + (size_t)w * HH))[lane];
    const float* xp = &xv.x;
    float s1 = 0.f, s2 = 0.f;
#pragma unroll
    for (int j = 0; j < 4; j++) {
        int k = lane * 4 + j;
        s1 += xp[j] * v1[k];
        s2 += xp[j] * v2[k];
    }
    s1 = warp_sum_all(s1);
    s2 = warp_sum_all(s2);
    if (lane == 0) { o1[w] = s1; o2[w] = s2; }
}

__global__ void node_one_dot(const float* __restrict__ xw, const float* __restrict__ v1,
                             float* __restrict__ o1, int n_rows) {
    int w = (blockIdx.x * blockDim.x + threadIdx.x) >> 5;
    int lane = threadIdx.x & 31;
    if (w >= n_rows) return;
    float4 xv = ((const float4*)(xw + (size_t)w * HH))[lane];
    const float* xp = &xv.x;
    float s1 = 0.f;
#pragma unroll
    for (int j = 0; j < 4; j++) s1 += xp[j] * v1[lane * 4 + j];
    s1 = warp_sum_all(s1);
    if (lane == 0) o1[w] = s1;
}

// ---------------- GRU combine + relu (2 cols/thread; dual fp32 + split write) ----------
__global__ void gru_combine(const float* __restrict__ gi, const float* __restrict__ gh,
                            const float* __restrict__ hprev, float* __restrict__ outp,
                            uint32_t* __restrict__ outs, int rows) {
    int idx = blockIdx.x * blockDim.x + threadIdx.x;
    if (idx >= rows * 64) return;
    int r = idx >> 6, cp = idx & 63;
    int c = cp * 2;
    const float* gir = gi + (size_t)r * H3;
    const float* ghr = gh + (size_t)r * H3;
    float o[2];
#pragma unroll
    for (int j = 0; j < 2; j++) {
        int cc = c + j;
        float ir = gir[cc], iz = gir[cc + HH], in_ = gir[cc + 2 * HH];
        float hr = ghr[cc], hz = ghr[cc + HH], hn = ghr[cc + 2 * HH];
        float rr = 1.f / (1.f + expf(-(ir + hr)));
        float z = 1.f / (1.f + expf(-(iz + hz)));
        float n = tanhf(in_ + rr * hn);
        float v = (1.f - z) * n + z * hprev[(size_t)r * HH + cc];
        o[j] = v > 0.f ? v : 0.f;
    }
    ((float2*)(outp + (size_t)r * HH))[cp] = make_float2(o[0], o[1]);
    uint32_t hp, lp;
    split_pair(o[0], o[1], hp, lp);
    outs[(size_t)r * HH + cp] = hp;
    outs[(size_t)r * HH + 64 + cp] = lp;
}

// ---------------- molecule readout (warp per graph) ----------------
__global__ void graph_sum(const float* __restrict__ xc, const int* __restrict__ gptr,
                          float* __restrict__ outG, uint32_t* __restrict__ outGs, int n_g) {
    int g = blockIdx.x * 8 + (threadIdx.x >> 5);
    int lane = threadIdx.x & 31;
    if (g >= n_g) return;
    int start = gptr[g], end = gptr[g + 1];
    float4 acc = make_float4(0.f, 0.f, 0.f, 0.f);
    for (int i = start; i < end; i++) {
        float4 v = ((const float4*)(xc + (size_t)i * HH))[lane];
        acc.x += v.x; acc.y += v.y; acc.z += v.z; acc.w += v.w;
    }
    acc.x = fmaxf(acc.x, 0.f);
    acc.y = fmaxf(acc.y, 0.f);
    acc.z = fmaxf(acc.z, 0.f);
    acc.w = fmaxf(acc.w, 0.f);
    ((float4*)(outG + (size_t)g * HH))[lane] = acc;
    uint32_t hp0, lp0, hp1, lp1;
    split_pair(acc.x, acc.y, hp0, lp0);
    split_pair(acc.z, acc.w, hp1, lp1);
    uint32_t* orow = outGs + (size_t)g * HH;
    orow[2 * lane] = hp0;
    orow[2 * lane + 1] = hp1;
    orow[64 + 2 * lane] = lp0;
    orow[64 + 2 * lane + 1] = lp1;
}

__global__ void compute_vvec(const float* __restrict__ molW, const float* __restrict__ attdst,
                             float* __restrict__ v) {
    int k = threadIdx.x;
    float s = 0.f;
    for (int j = 0; j < HH; j++) s += molW[(size_t)j * HH + k] * attdst[j];
    v[k] = s;
}

// writes hG split-only (consumed only by mol gru Wi GEMM)
__global__ void mol_timestep(const float* __restrict__ outG, const float* __restrict__ vvec,
                             const int* __restrict__ gptr, const float* __restrict__ asrc,
                             const float* __restrict__ xw, const float* __restrict__ bias,
                             uint32_t* __restrict__ hGs, int n_g) {
    int g = blockIdx.x * 8 + (threadIdx.x >> 5);
    int lane = threadIdx.x & 31;
    if (g >= n_g) return;
    float4 ov = ((const float4*)(outG + (size_t)g * HH))[lane];
    float4 vv = ((const float4*)vvec)[lane];
    float ad = warp_sum_all(ov.x * vv.x + ov.y * vv.y + ov.z * vv.z + ov.w * vv.w);

    int start = gptr[g], end = gptr[g + 1];
    float m = -INFINITY;
    for (int i = start + lane; i < end; i += 32) {
        float a = asrc[i] + ad;
        a = a > 0.f ? a : 0.01f * a;
        m = fmaxf(m, a);
    }
    m = warp_max_all(m);

    float4 acc = make_float4(0.f, 0.f, 0.f, 0.f);
    float sum = 0.f;
    for (int base = start; base < end; base += 32) {
        int i = base + lane;
        float w = 0.f;
        if (i < end) {
            float a = asrc[i] + ad;
            a = a > 0.f ? a : 0.01f * a;
            w = expf(a - m);
            sum += w;
        }
        int cnt = min(32, end - base);
        for (int j = 0; j < cnt; j++) {
            float wj = __shfl_sync(FULL, w, j);
            float4 v = ((const float4*)(xw + (size_t)(base + j) * HH))[lane];
            acc.x += wj * v.x;
            acc.y += wj * v.y;
            acc.z += wj * v.z;
            acc.w += wj * v.w;
        }
    }
    sum = warp_sum_all(sum);
    float rinv = 1.f / (sum + 1e-16f);
    float4 b4 = ((const float4*)bias)[lane];
    float o0 = acc.x * rinv + b4.x;
    float o1 = acc.y * rinv + b4.y;
    float o2 = acc.z * rinv + b4.z;
    float o3 = acc.w * rinv + b4.w;
    o0 = o0 > 0.f ? o0 : expf(o0) - 1.f;
    o1 = o1 > 0.f ? o1 : expf(o1) - 1.f;
    o2 = o2 > 0.f ? o2 : expf(o2) - 1.f;
    o3 = o3 > 0.f ? o3 : expf(o3) - 1.f;
    uint32_t hp0, lp0, hp1, lp1;
    split_pair(o0, o1, hp0, lp0);
    split_pair(o2, o3, hp1, lp1);
    uint32_t* hrow = hGs + (size_t)g * HH;
    hrow[2 * lane] = hp0;
    hrow[2 * lane + 1] = hp1;
    hrow[64 + 2 * lane] = lp0;
    hrow[64 + 2 * lane + 1] = lp1;
}

__global__ void final_out(const float* __restrict__ outG, const float* __restrict__ W,
                          const float* __restrict__ b, float* __restrict__ y, int g_rows) {
    int g = (blockIdx.x * blockDim.x + threadIdx.x) >> 5;
    int lane = threadIdx.x & 31;
    if (g >= g_rows) return;
    float4 v = ((const float4*)(outG + (size_t)g * HH))[lane];
    const float* vp = &v.x;
    float s = 0.f;
#pragma unroll
    for (int j = 0; j < 4; j++) s += vp[j] * W[lane * 4 + j];
    s = warp_sum_all(s);
    if (lane == 0) y[g] = s + b[0];
}

// ---------------- host ----------------
static inline int cdiv(int a, int b) { return (a + b - 1) / b; }

extern "C" void kernel_launch(void* const* d_in, const int* in_sizes, int n_in,
                              void* d_out, int out_size) {
    const float* x = (const float*)d_in[0];
    const int* ei = (const int*)d_in[1];
    const int* batch = (const int*)d_in[2];
    const float* lin1_W = (const float*)d_in[3];
    const float* lin1_b = (const float*)d_in[4];
    const float* gate_W1 = (const float*)d_in[5];
    const float* gate_W2 = (const float*)d_in[6];
    const float* gate_att_l = (const float*)d_in[7];
    const float* gate_att_r = (const float*)d_in[8];
    const float* gate_bias = (const float*)d_in[9];
    const float* gru0_Wi = (const float*)d_in[10];
    const float* gru0_bi = (const float*)d_in[11];
    const float* gru0_Wh = (const float*)d_in[12];
    const float* gru0_bh = (const float*)d_in[13];
    const float* atom_W = (const float*)d_in[14];
    const float* atom_att_src = (const float*)d_in[15];
    const float* atom_att_dst = (const float*)d_in[16];
    const float* atom_bias = (const float*)d_in[17];
    const float* atom_gru_Wi = (const float*)d_in[18];
    const float* atom_gru_bi = (const float*)d_in[19];
    const float* atom_gru_Wh = (const float*)d_in[20];
    const float* atom_gru_bh = (const float*)d_in[21];
    const float* mol_W = (const float*)d_in[22];
    const float* mol_att_src = (const float*)d_in[23];
    const float* mol_att_dst = (const float*)d_in[24];
    const float* mol_bias = (const float*)d_in[25];
    const float* mol_gru_Wi = (const float*)d_in[26];
    const float* mol_gru_bi = (const float*)d_in[27];
    const float* mol_gru_Wh = (const float*)d_in[28];
    const float* mol_gru_bh = (const float*)d_in[29];
    const float* lin2_W = (const float*)d_in[30];
    const float* lin2_b = (const float*)d_in[31];

    const int* src = ei;
    const int* dst = ei + EE;

    cudaFuncSetAttribute(bgemm, cudaFuncAttributeMaxDynamicSharedMemorySize, BG_SMEM);

    float *x0, *xw, *xc, *gi, *gh, *asrc, *adst, *outG, *giG, *ghG, *vvec;
    int *deg, *ptr, *cur, *csr_src, *bsum, *gptr;
    uint32_t *sx, *sx0, *sh, *sxc, *shG, *soutG;
    uint32_t *wl1, *wg1, *wg2, *wg0i, *wg0h, *watom, *watomi, *watomh, *wmol, *wmoli, *wmolh;
    cudaGetSymbolAddress((void**)&x0, d_x0);
    cudaGetSymbolAddress((void**)&xw, d_xw);
    cudaGetSymbolAddress((void**)&xc, d_xc);
    cudaGetSymbolAddress((void**)&gi, d_gi);
    cudaGetSymbolAddress((void**)&gh, d_gh);
    cudaGetSymbolAddress((void**)&asrc, d_asrc);
    cudaGetSymbolAddress((void**)&adst, d_adst);
    cudaGetSymbolAddress((void**)&outG, d_outG);
    cudaGetSymbolAddress((void**)&giG, d_giG);
    cudaGetSymbolAddress((void**)&ghG, d_ghG);
    cudaGetSymbolAddress((void**)&vvec, d_vvec);
    cudaGetSymbolAddress((void**)&deg, d_deg);
    cudaGetSymbolAddress((void**)&ptr, d_ptr);
    cudaGetSymbolAddress((void**)&cur, d_cur);
    cudaGetSymbolAddress((void**)&csr_src, d_csr_src);
    cudaGetSymbolAddress((void**)&bsum, d_bsum);
    cudaGetSymbolAddress((void**)&gptr, d_gptr);
    cudaGetSymbolAddress((void**)&sx, s_x);
    cudaGetSymbolAddress((void**)&sx0, s_x0);
    cudaGetSymbolAddress((void**)&sh, s_h);
    cudaGetSymbolAddress((void**)&sxc, s_xc);
    cudaGetSymbolAddress((void**)&shG, s_hG);
    cudaGetSymbolAddress((void**)&soutG, s_outG);
    cudaGetSymbolAddress((void**)&wl1, w_lin1);
    cudaGetSymbolAddress((void**)&wg1, w_g1);
    cudaGetSymbolAddress((void**)&wg2, w_g2);
    cudaGetSymbolAddress((void**)&wg0i, w_g0i);
    cudaGetSymbolAddress((void**)&wg0h, w_g0h);
    cudaGetSymbolAddress((void**)&watom, w_atom);
    cudaGetSymbolAddress((void**)&watomi, w_atomi);
    cudaGetSymbolAddress((void**)&watomh, w_atomh);
    cudaGetSymbolAddress((void**)&wmol, w_mol);
    cudaGetSymbolAddress((void**)&wmoli, w_moli);
    cudaGetSymbolAddress((void**)&wmolh, w_molh);

    dim3 g_n128(1, cdiv(NN, 128));
    dim3 g_n384(3, cdiv(NN, 128));
    dim3 g_g384(3, cdiv(GG, 128));
    int wpb_n = cdiv(NN, 8);
    int wpb_g = cdiv(GG, 8);
    const int nscan = cdiv(NN, 1024);

    // ---- weight + input pre-split ----
    to_split<<<cdiv(NN * 32, 256), 256>>>(x, IN_CH, sx, NN, IN_CH);
    to_split<<<cdiv(HH * 32, 256), 256>>>(lin1_W, IN_CH, wl1, HH, IN_CH);
    to_split<<<cdiv(HH * 64, 256), 256>>>(gate_W1, HH + 1, wg1, HH, HH);
    to_split<<<cdiv(HH * 64, 256), 256>>>(gate_W2, HH, wg2, HH, HH);
    to_split<<<cdiv(H3 * 64, 256), 256>>>(gru0_Wi, HH, wg0i, H3, HH);
    to_split<<<cdiv(H3 * 64, 256), 256>>>(gru0_Wh, HH, wg0h, H3, HH);
    for (int l = 0; l < 2; l++) {
        to_split<<<cdiv(HH * 64, 256), 256>>>(atom_W + (size_t)l * HH * HH, HH, watom + (size_t)l * HH * HH, HH, HH);
        to_split<<<cdiv(H3 * 64, 256), 256>>>(atom_gru_Wi + (size_t)l * H3 * HH, HH, watomi + (size_t)l * H3 * HH, H3, HH);
        to_split<<<cdiv(H3 * 64, 256), 256>>>(atom_gru_Wh + (size_t)l * H3 * HH, HH, watomh + (size_t)l * H3 * HH, H3, HH);
    }
    to_split<<<cdiv(HH * 64, 256), 256>>>(mol_W, HH, wmol, HH, HH);
    to_split<<<cdiv(H3 * 64, 256), 256>>>(mol_gru_Wi, HH, wmoli, H3, HH);
    to_split<<<cdiv(H3 * 64, 256), 256>>>(mol_gru_Wh, HH, wmolh, H3, HH);

    // ---- CSR + graph-pointer build ----
    cudaMemsetAsync(deg, 0, NN * sizeof(int));
    hist_kernel<<<cdiv(EE, 256), 256>>>(dst, deg, EE);
    scan_block<<<nscan, 256>>>(deg, ptr, bsum, NN);
    scan_bsum<<<1, 128>>>(bsum, nscan);
    scan_fixup<<<cdiv(NN, 256), 256>>>(ptr, bsum, cur, NN, EE);
    scatter_csr<<<cdiv(EE, 256), 256>>>(src, dst, cur, csr_src, EE);
    build_gptr<<<cdiv(NN, 256), 256>>>(batch, gptr, NN);

    // x0 = lrelu(x @ lin1_W^T + b)   (fp32 + split)
    bgemm<<<g_n128, 256, BG_SMEM>>>(sx, wl1, lin1_b, x0, sx0, NN, HH, IN_CH, 1);

    // ---- GATEConv ----
    bgemm<<<g_n128, 256, BG_SMEM>>>(sx0, wg1, nullptr, xw, nullptr, NN, HH, HH, 0);
    gate_node_atts<<<wpb_n, 256>>>(xw, gate_W1, gate_att_l, x0, gate_att_r, asrc, adst, NN);
    bgemm<<<g_n128, 256, BG_SMEM>>>(sx0, wg2, nullptr, xw, nullptr, NN, HH, HH, 0);
    gat_aggregate<<<wpb_n, 256>>>(ptr, csr_src, asrc, adst, xw, gate_bias, sh, NN);
    bgemm<<<g_n384, 256, BG_SMEM>>>(sh, wg0i, gru0_bi, gi, nullptr, NN, H3, HH, 0);
    bgemm<<<g_n384, 256, BG_SMEM>>>(sx0, wg0h, gru0_bh, gh, nullptr, NN, H3, HH, 0);
    gru_combine<<<cdiv(NN * 64, 256), 256>>>(gi, gh, x0, xc, sxc, NN);

    // ---- extra atom GAT + GRU layers ----
    for (int l = 0; l < 2; l++) {
        bgemm<<<g_n128, 256, BG_SMEM>>>(sxc, watom + (size_t)l * HH * HH, nullptr, xw, nullptr, NN, HH, HH, 0);
        node_two_dots<<<wpb_n, 256>>>(xw, atom_att_src + l * HH, atom_att_dst + l * HH, asrc, adst, NN);
        gat_aggregate<<<wpb_n, 256>>>(ptr, csr_src, asrc, adst, xw, atom_bias + l * HH, sh, NN);
        bgemm<<<g_n384, 256, BG_SMEM>>>(sh, watomi + (size_t)l * H3 * HH, atom_gru_bi + l * H3, gi, nullptr, NN, H3, HH, 0);
        bgemm<<<g_n384, 256, BG_SMEM>>>(sxc, watomh + (size_t)l * H3 * HH, atom_gru_bh + l * H3, gh, nullptr, NN, H3, HH, 0);
        gru_combine<<<cdiv(NN * 64, 256), 256>>>(gi, gh, xc, xc, sxc, NN);
    }

    // ---- molecule readout ----
    graph_sum<<<wpb_g, 256>>>(xc, gptr, outG, soutG, GG);
    bgemm<<<g_n128, 256, BG_SMEM>>>(sxc, wmol, nullptr, xw, nullptr, NN, HH, HH, 0);
    node_one_dot<<<wpb_n, 256>>>(xw, mol_att_src, asrc, NN);
    compute_vvec<<<1, HH>>>(mol_W, mol_att_dst, vvec);

    for (int t = 0; t < 2; t++) {
        mol_timestep<<<wpb_g, 256>>>(outG, vvec, gptr, asrc, xw, mol_bias, shG, GG);
        bgemm<<<g_g384, 256, BG_SMEM>>>(shG, wmoli, mol_gru_bi, giG, nullptr, GG, H3, HH, 0);
        bgemm<<<g_g384, 256, BG_SMEM>>>(soutG, wmolh, mol_gru_bh, ghG, nullptr, GG, H3, HH, 0);
        gru_combine<<<cdiv(GG * 64, 256), 256>>>(giG, ghG, outG, outG, soutG, GG);
    }

    final_out<<<wpb_g, 256>>>(outG, lin2_W, lin2_b, (float*)d_out, GG);
}

// round 10
// speedup vs baseline: 1.3811x; 1.0058x over previous
#include <cuda_runtime.h>
#include <cuda_bf16.h>
#include <math.h>
#include <stdint.h>

#define NN 100000
#define EE 1600000
#define IN_CH 64
#define HH 128
#define H3 384
#define GG 4096
#define FULL 0xffffffffu

// ---------------- scratch (no allocations allowed) ----------------
__device__ float d_x0[NN * HH];
__device__ float d_xw[NN * HH];
__device__ float d_xc[NN * HH];
__device__ float d_gi[NN * H3];
__device__ float d_gh[NN * H3];
__device__ float d_asrc[NN];
__device__ float d_adst[NN];
__device__ float d_outG[GG * HH];
__device__ float d_giG[GG * H3];
__device__ float d_ghG[GG * H3];
__device__ float d_vvec[HH];
__device__ int d_deg[NN];
__device__ int d_ptr[NN + 1];
__device__ int d_cur[NN];
__device__ int d_csr_src[EE];
__device__ int d_bsum[128];
__device__ int d_gptr[GG + 1];
// bf16-split buffers, chunk-interleaved: per k16 chunk, 16 words [h_t,h_{t+4},l_t,l_{t+4}]x4
__device__ uint32_t s_x[NN * IN_CH];
__device__ uint32_t s_x0[NN * HH];
__device__ uint32_t s_h[NN * HH];
__device__ uint32_t s_xc[NN * HH];
__device__ uint32_t s_hG[GG * HH];
__device__ uint32_t s_outG[GG * HH];
__device__ uint32_t w_lin1[HH * IN_CH];
__device__ uint32_t w_g1[HH * HH];
__device__ uint32_t w_g2[HH * HH];
__device__ uint32_t w_g0i[H3 * HH];
__device__ uint32_t w_g0h[H3 * HH];
__device__ uint32_t w_atom[2 * HH * HH];
__device__ uint32_t w_atomi[2 * H3 * HH];
__device__ uint32_t w_atomh[2 * H3 * HH];
__device__ uint32_t w_mol[HH * HH];
__device__ uint32_t w_moli[H3 * HH];
__device__ uint32_t w_molh[H3 * HH];

// ---------------- helpers ----------------
__device__ __forceinline__ float warp_sum_all(float v) {
#pragma unroll
    for (int o = 16; o > 0; o >>= 1) v += __shfl_xor_sync(FULL, v, o);
    return v;
}
__device__ __forceinline__ float warp_max_all(float v) {
#pragma unroll
    for (int o = 16; o > 0; o >>= 1) v = fmaxf(v, __shfl_xor_sync(FULL, v, o));
    return v;
}

// interleave map: k-pair index cp -> word offset of its hi word within the row
__device__ __forceinline__ int ilv(int cp) {
    int c = cp >> 3, p = cp & 7;
    return (c << 4) + ((p < 4) ? (p << 2) : (((p - 4) << 2) + 1));
}

// split pair (f0 even k, f1 odd k) -> hi-pair (truncated bf16) + lo-pair (rounded bf16)
__device__ __forceinline__ void split_pair(float f0, float f1, uint32_t& hp, uint32_t& lp) {
    uint32_t u0 = __float_as_uint(f0), u1 = __float_as_uint(f1);
    hp = __byte_perm(u0, u1, 0x7632);
    float l0 = f0 - __uint_as_float(u0 & 0xffff0000u);
    float l1 = f1 - __uint_as_float(u1 & 0xffff0000u);
    __nv_bfloat162 p = __floats2bfloat162_rn(l0, l1);
    lp = *reinterpret_cast<uint32_t*>(&p);
}

__device__ __forceinline__ void mma_bf16(float* c, const uint32_t* a, const uint32_t* b) {
    asm volatile(
        "mma.sync.aligned.m16n8k16.row.col.f32.bf16.bf16.f32 "
        "{%0,%1,%2,%3}, {%4,%5,%6,%7}, {%8,%9}, {%0,%1,%2,%3};"
        : "+f"(c[0]), "+f"(c[1]), "+f"(c[2]), "+f"(c[3])
        : "r"(a[0]), "r"(a[1]), "r"(a[2]), "r"(a[3]), "r"(b[0]), "r"(b[1]));
}

__device__ __forceinline__ void cp_async16(uint32_t dst, const void* src, bool pred) {
    asm volatile("cp.async.cg.shared.global [%0], [%1], 16, %2;"
                 :: "r"(dst), "l"(src), "r"(pred ? 16 : 0));
}

// ---------------- fp32 -> split converter (chunk-interleaved) ----------------
__global__ void to_split(const float* __restrict__ src, int ld, uint32_t* __restrict__ dst,
                         int M, int K) {
    int idx = blockIdx.x * blockDim.x + threadIdx.x;
    int kh = K >> 1;
    if (idx >= M * kh) return;
    int r = idx / kh, j = idx - r * kh;
    float f0 = src[(size_t)r * ld + 2 * j];
    float f1 = src[(size_t)r * ld + 2 * j + 1];
    uint32_t hp, lp;
    split_pair(f0, f1, hp, lp);
    int w = ilv(j);
    dst[(size_t)r * K + w] = hp;
    dst[(size_t)r * K + w + 2] = lp;
}

// ---------------- bf16-split tensor-core GEMM (64x64 warp tiles) ----------------
// C[M,N] = act(A[M,K] @ B[N,K]^T + bias); A,B chunk-interleaved split (row stride K words).
// If Cs != null, also writes C in split format (row stride N words).
__device__ __forceinline__ void bload(const uint32_t* __restrict__ Ahl,
                                      const uint32_t* __restrict__ Bhl,
                                      int M, int K, int row0, int col0,
                                      int tid, int kc, uint32_t* sb) {
#pragma unroll
    for (int it = 0; it < 8; it++) {
        int s = tid * 8 + it;             // 0..1023
        int r = (s >> 2) & 127;
        int j = s & 3;
        bool isB = s >= 512;
        uint32_t da = (uint32_t)__cvta_generic_to_shared(sb + (isB ? 2048 : 0) + r * 16 + 4 * j);
        const uint32_t* g;
        bool pred = true;
        if (!isB) {
            int ar = row0 + r;
            pred = ar < M;
            g = Ahl + (size_t)(pred ? ar : 0) * K + kc * 16 + 4 * j;
        } else {
            g = Bhl + (size_t)(col0 + r) * K + kc * 16 + 4 * j;
        }
        cp_async16(da, g, pred);
    }
    asm volatile("cp.async.commit_group;");
}

__global__ void __launch_bounds__(128) bgemm(const uint32_t* __restrict__ Ahl,
                                             const uint32_t* __restrict__ Bhl,
                                             const float* __restrict__ bias,
                                             float* __restrict__ C,
                                             uint32_t* __restrict__ Cs,
                                             int M, int N, int K, int act) {
    __shared__ uint32_t sm[2][4096];
    const int tid = threadIdx.x;
    const int lane = tid & 31;
    const int warp = tid >> 5;
    const int g = lane >> 2;
    const int t = lane & 3;
    const int wrow = (warp >> 1) * 64;
    const int wcol = (warp & 1) * 64;
    const int row0 = blockIdx.y * 128;
    const int col0 = blockIdx.x * 128;
    const int nk = K >> 4;

    float acc[4][8][4];
#pragma unroll
    for (int mt = 0; mt < 4; mt++)
#pragma unroll
        for (int nt = 0; nt < 8; nt++)
#pragma unroll
            for (int i = 0; i < 4; i++) acc[mt][nt][i] = 0.f;

    bload(Ahl, Bhl, M, K, row0, col0, tid, 0, sm[0]);

    for (int c = 0; c < nk; c++) {
        asm volatile("cp.async.wait_group 0;");
        __syncthreads();
        if (c + 1 < nk)
            bload(Ahl, Bhl, M, K, row0, col0, tid, c + 1, sm[(c + 1) & 1]);
        const uint32_t* As = sm[c & 1];
        const uint32_t* Bs = As + 2048;

        uint32_t bhi[8][2], blo[8][2];
#pragma unroll
        for (int nt = 0; nt < 8; nt++) {
            int cc = wcol + nt * 8 + g;
            uint4 bb = *(const uint4*)(Bs + cc * 16 + 4 * t);
            bhi[nt][0] = bb.x; bhi[nt][1] = bb.y;
            blo[nt][0] = bb.z; blo[nt][1] = bb.w;
        }
#pragma unroll
        for (int mt = 0; mt < 4; mt++) {
            int r = wrow + mt * 16 + g;
            uint4 a0 = *(const uint4*)(As + r * 16 + 4 * t);
            uint4 a8 = *(const uint4*)(As + (r + 8) * 16 + 4 * t);
            uint32_t ahi[4] = {a0.x, a8.x, a0.y, a8.y};
            uint32_t alo[4] = {a0.z, a8.z, a0.w, a8.w};
#pragma unroll
            for (int nt = 0; nt < 8; nt++) {
                mma_bf16(acc[mt][nt], alo, bhi[nt]);
                mma_bf16(acc[mt][nt], ahi, blo[nt]);
                mma_bf16(acc[mt][nt], ahi, bhi[nt]);
            }
        }
    }

#pragma unroll
    for (int mt = 0; mt < 4; mt++) {
#pragma unroll
        for (int nt = 0; nt < 8; nt++) {
            int r0 = row0 + wrow + mt * 16 + g;
            int c = col0 + wcol + nt * 8 + 2 * t;
            float b0 = bias ? bias[c] : 0.f;
            float b1 = bias ? bias[c + 1] : 0.f;
            float v00 = acc[mt][nt][0] + b0, v01 = acc[mt][nt][1] + b1;
            float v10 = acc[mt][nt][2] + b0, v11 = acc[mt][nt][3] + b1;
            if (act == 1) {
                v00 = v00 > 0.f ? v00 : 0.01f * v00;
                v01 = v01 > 0.f ? v01 : 0.01f * v01;
                v10 = v10 > 0.f ? v10 : 0.01f * v10;
                v11 = v11 > 0.f ? v11 : 0.01f * v11;
            }
            if (r0 < M) {
                C[(size_t)r0 * N + c] = v00;
                C[(size_t)r0 * N + c + 1] = v01;
                if (Cs) {
                    uint32_t hp, lp;
                    split_pair(v00, v01, hp, lp);
                    int w = ilv(c >> 1);
                    Cs[(size_t)r0 * N + w] = hp;
                    Cs[(size_t)r0 * N + w + 2] = lp;
                }
            }
            if (r0 + 8 < M) {
                C[(size_t)(r0 + 8) * N + c] = v10;
                C[(size_t)(r0 + 8) * N + c + 1] = v11;
                if (Cs) {
                    uint32_t hp, lp;
                    split_pair(v10, v11, hp, lp);
                    int w = ilv(c >> 1);
                    Cs[(size_t)(r0 + 8) * N + w] = hp;
                    Cs[(size_t)(r0 + 8) * N + w + 2] = lp;
                }
            }
        }
    }
}

// ---------------- CSR build ----------------
__global__ void hist_kernel(const int* __restrict__ dst, int* __restrict__ deg, int n_e) {
    int e = blockIdx.x * blockDim.x + threadIdx.x;
    if (e < n_e) atomicAdd(&deg[dst[e]], 1);
}

__global__ void scan_block(const int* __restrict__ in, int* __restrict__ out,
                           int* __restrict__ bsum, int n) {
    __shared__ int s[256];
    int t = threadIdx.x;
    int base = blockIdx.x * 1024 + t * 4;
    int v[4];
#pragma unroll
    for (int j = 0; j < 4; j++) v[j] = (base + j < n) ? in[base + j] : 0;
    int tsum = v[0] + v[1] + v[2] + v[3];
    s[t] = tsum;
    __syncthreads();
    for (int off = 1; off < 256; off <<= 1) {
        int x = (t >= off) ? s[t - off] : 0;
        __syncthreads();
        s[t] += x;
        __syncthreads();
    }
    int exc = s[t] - tsum;
    if (t == 255) bsum[blockIdx.x] = s[t];
    int run = exc;
#pragma unroll
    for (int j = 0; j < 4; j++) {
        if (base + j < n) out[base + j] = run;
        run += v[j];
    }
}

__global__ void scan_bsum(int* __restrict__ bsum, int nb) {
    __shared__ int s[128];
    int t = threadIdx.x;
    int orig = (t < nb) ? bsum[t] : 0;
    s[t] = orig;
    __syncthreads();
    for (int off = 1; off < 128; off <<= 1) {
        int x = (t >= off) ? s[t - off] : 0;
        __syncthreads();
        s[t] += x;
        __syncthreads();
    }
    if (t < nb) bsum[t] = s[t] - orig;
}

__global__ void scan_fixup(int* __restrict__ ptr, const int* __restrict__ bsum,
                           int* __restrict__ cur, int n, int total) {
    int i = blockIdx.x * blockDim.x + threadIdx.x;
    if (i < n) {
        int p = ptr[i] + bsum[i >> 10];
        ptr[i] = p;
        cur[i] = p;
    }
    if (i == 0) ptr[n] = total;
}

__global__ void scatter_csr(const int* __restrict__ src, const int* __restrict__ dst,
                            int* __restrict__ cur, int* __restrict__ csr_src, int n_e) {
    int e = blockIdx.x * blockDim.x + threadIdx.x;
    if (e >= n_e) return;
    int p = atomicAdd(&cur[dst[e]], 1);
    csr_src[p] = src[e];
}

__global__ void build_gptr(const int* __restrict__ batch, int* __restrict__ gptr, int n) {
    int i = blockIdx.x * blockDim.x + threadIdx.x;
    if (i >= n) return;
    int b = batch[i];
    int prev = (i == 0) ? -1 : batch[i - 1];
    for (int g = prev + 1; g <= b; g++) gptr[g] = i;
    if (i == n - 1)
        for (int g = b + 1; g <= GG; g++) gptr[g] = n;
}

// ---------------- fused GAT aggregation (warp per destination node) ----------------
__global__ void gat_aggregate(const int* __restrict__ ptr, const int* __restrict__ csr,
                              const float* __restrict__ asrc, const float* __restrict__ adst,
                              const float* __restrict__ xw, const float* __restrict__ bias,
                              uint32_t* __restrict__ hs, int n_rows) {
    int row = blockIdx.x * 8 + (threadIdx.x >> 5);
    int lane = threadIdx.x & 31;
    if (row >= n_rows) return;
    int start = ptr[row], end = ptr[row + 1];
    float ad = adst[row];

    float m = -INFINITY;
    for (int e = start + lane; e < end; e += 32) {
        float a = asrc[csr[e]] + ad;
        a = a > 0.f ? a : 0.01f * a;
        m = fmaxf(m, a);
    }
    m = warp_max_all(m);

    float4 acc = make_float4(0.f, 0.f, 0.f, 0.f);
    float sum = 0.f;
    for (int base = start; base < end; base += 32) {
        int e = base + lane;
        float w = 0.f;
        int s = 0;
        if (e < end) {
            s = csr[e];
            float a = asrc[s] + ad;
            a = a > 0.f ? a : 0.01f * a;
            w = expf(a - m);
            sum += w;
        }
        int cnt = min(32, end - base);
        for (int j = 0; j < cnt; j++) {
            float wj = __shfl_sync(FULL, w, j);
            int sj = __shfl_sync(FULL, s, j);
            float4 v = ((const float4*)(xw + (size_t)sj * HH))[lane];
            acc.x += wj * v.x;
            acc.y += wj * v.y;
            acc.z += wj * v.z;
            acc.w += wj * v.w;
        }
    }
    sum = warp_sum_all(sum);
    float rinv = 1.f / (sum + 1e-16f);
    float4 b4 = ((const float4*)bias)[lane];
    float o0 = acc.x * rinv + b4.x;
    float o1 = acc.y * rinv + b4.y;
    float o2 = acc.z * rinv + b4.z;
    float o3 = acc.w * rinv + b4.w;
    o0 = o0 > 0.f ? o0 : expf(o0) - 1.f;
    o1 = o1 > 0.f ? o1 : expf(o1) - 1.f;
    o2 = o2 > 0.f ? o2 : expf(o2) - 1.f;
    o3 = o3 > 0.f ? o3 : expf(o3) - 1.f;
    uint32_t hp0, lp0, hp1, lp1;
    split_pair(o0, o1, hp0, lp0);
    split_pair(o2, o3, hp1, lp1);
    uint32_t* hr = hs + (size_t)row * HH;
    int w0 = ilv(2 * lane), w1 = ilv(2 * lane + 1);
    hr[w0] = hp0;
    hr[w0 + 2] = lp0;
    hr[w1] = hp1;
    hr[w1 + 2] = lp1;
}

// ---------------- GATEConv per-node attention scalars ----------------
__global__ void gate_node_atts(const float* __restrict__ tmp, const float* __restrict__ W1,
                               const float* __restrict__ att_l, const float* __restrict__ x0,
                               const float* __restrict__ att_r, float* __restrict__ asrc,
                               float* __restrict__ adst, int n_rows) {
    int w = (blockIdx.x * blockDim.x + threadIdx.x) >> 5;
    int lane = threadIdx.x & 31;
    if (w >= n_rows) return;
    float4 tv = ((const float4*)(tmp + (size_t)w * HH))[lane];
    float4 xv = ((const float4*)(x0 + (size_t)w * HH))[lane];
    float s1 = 0.f, s2 = 0.f;
    const float* t = &tv.x;
    const float* xp = &xv.x;
#pragma unroll
    for (int j = 0; j < 4; j++) {
        int k = lane * 4 + j;
        float xe = t[j] + W1[(size_t)k * (HH + 1) + HH];
        xe = xe > 0.f ? xe : 0.01f * xe;
        s1 += xe * att_l[k];
        s2 += xp[j] * att_r[k];
    }
    s1 = warp_sum_all(s1);
    s2 = warp_sum_all(s2);
    if (lane == 0) { asrc[w] = s1; adst[w] = s2; }
}

__global__ void node_two_dots(const float* __restrict__ xw, const float* __restrict__ v1,
                              const float* __restrict__ v2, float* __restrict__ o1,
                              float* __restrict__ o2, int n_rows) {
    int w = (blockIdx.x * blockDim.x + threadIdx.x) >> 5;
    int lane = threadIdx.x & 31;
    if (w >= n_rows) return;
    float4 xv = ((const float4*)(xw + (size_t)w * HH))[lane];
    const float* xp = &xv.x;
    float s1 = 0.f, s2 = 0.f;
#pragma unroll
    for (int j = 0; j < 4; j++) {
        int k = lane * 4 + j;
        s1 += xp[j] * v1[k];
        s2 += xp[j] * v2[k];
    }
    s1 = warp_sum_all(s1);
    s2 = warp_sum_all(s2);
    if (lane == 0) { o1[w] = s1; o2[w] = s2; }
}

__global__ void node_one_dot(const float* __restrict__ xw, const float* __restrict__ v1,
                             float* __restrict__ o1, int n_rows) {
    int w = (blockIdx.x * blockDim.x + threadIdx.x) >> 5;
    int lane = threadIdx.x & 31;
    if (w >= n_rows) return;
    float4 xv = ((const float4*)(xw + (size_t)w * HH))[lane];
    const float* xp = &xv.x;
    float s1 = 0.f;
#pragma unroll
    for (int j = 0; j < 4; j++) s1 += xp[j] * v1[lane * 4 + j];
    s1 = warp_sum_all(s1);
    if (lane == 0) o1[w] = s1;
}

// ---------------- GRU combine + relu (2 cols/thread; dual fp32 + split write) ----------
__global__ void gru_combine(const float* __restrict__ gi, const float* __restrict__ gh,
                            const float* __restrict__ hprev, float* __restrict__ outp,
                            uint32_t* __restrict__ outs, int rows) {
    int idx = blockIdx.x * blockDim.x + threadIdx.x;
    if (idx >= rows * 64) return;
    int r = idx >> 6, cp = idx & 63;
    int c = cp * 2;
    const float* gir = gi + (size_t)r * H3;
    const float* ghr = gh + (size_t)r * H3;
    float o[2];
#pragma unroll
    for (int j = 0; j < 2; j++) {
        int cc = c + j;
        float ir = gir[cc], iz = gir[cc + HH], in_ = gir[cc + 2 * HH];
        float hr = ghr[cc], hz = ghr[cc + HH], hn = ghr[cc + 2 * HH];
        float rr = 1.f / (1.f + expf(-(ir + hr)));
        float z = 1.f / (1.f + expf(-(iz + hz)));
        float n = tanhf(in_ + rr * hn);
        float v = (1.f - z) * n + z * hprev[(size_t)r * HH + cc];
        o[j] = v > 0.f ? v : 0.f;
    }
    ((float2*)(outp + (size_t)r * HH))[cp] = make_float2(o[0], o[1]);
    uint32_t hp, lp;
    split_pair(o[0], o[1], hp, lp);
    int w = ilv(cp);
    outs[(size_t)r * HH + w] = hp;
    outs[(size_t)r * HH + w + 2] = lp;
}

// ---------------- molecule readout (warp per graph) ----------------
__global__ void graph_sum(const float* __restrict__ xc, const int* __restrict__ gptr,
                          float* __restrict__ outG, uint32_t* __restrict__ outGs, int n_g) {
    int g = blockIdx.x * 8 + (threadIdx.x >> 5);
    int lane = threadIdx.x & 31;
    if (g >= n_g) return;
    int start = gptr[g], end = gptr[g + 1];
    float4 acc = make_float4(0.f, 0.f, 0.f, 0.f);
    for (int i = start; i < end; i++) {
        float4 v = ((const float4*)(xc + (size_t)i * HH))[lane];
        acc.x += v.x; acc.y += v.y; acc.z += v.z; acc.w += v.w;
    }
    acc.x = fmaxf(acc.x, 0.f);
    acc.y = fmaxf(acc.y, 0.f);
    acc.z = fmaxf(acc.z, 0.f);
    acc.w = fmaxf(acc.w, 0.f);
    ((float4*)(outG + (size_t)g * HH))[lane] = acc;
    uint32_t hp0, lp0, hp1, lp1;
    split_pair(acc.x, acc.y, hp0, lp0);
    split_pair(acc.z, acc.w, hp1, lp1);
    uint32_t* orow = outGs + (size_t)g * HH;
    int w0 = ilv(2 * lane), w1 = ilv(2 * lane + 1);
    orow[w0] = hp0;
    orow[w0 + 2] = lp0;
    orow[w1] = hp1;
    orow[w1 + 2] = lp1;
}

__global__ void compute_vvec(const float* __restrict__ molW, const float* __restrict__ attdst,
                             float* __restrict__ v) {
    int k = threadIdx.x;
    float s = 0.f;
    for (int j = 0; j < HH; j++) s += molW[(size_t)j * HH + k] * attdst[j];
    v[k] = s;
}

__global__ void mol_timestep(const float* __restrict__ outG, const float* __restrict__ vvec,
                             const int* __restrict__ gptr, const float* __restrict__ asrc,
                             const float* __restrict__ xw, const float* __restrict__ bias,
                             uint32_t* __restrict__ hGs, int n_g) {
    int g = blockIdx.x * 8 + (threadIdx.x >> 5);
    int lane = threadIdx.x & 31;
    if (g >= n_g) return;
    float4 ov = ((const float4*)(outG + (size_t)g * HH))[lane];
    float4 vv = ((const float4*)vvec)[lane];
    float ad = warp_sum_all(ov.x * vv.x + ov.y * vv.y + ov.z * vv.z + ov.w * vv.w);

    int start = gptr[g], end = gptr[g + 1];
    float m = -INFINITY;
    for (int i = start + lane; i < end; i += 32) {
        float a = asrc[i] + ad;
        a = a > 0.f ? a : 0.01f * a;
        m = fmaxf(m, a);
    }
    m = warp_max_all(m);

    float4 acc = make_float4(0.f, 0.f, 0.f, 0.f);
    float sum = 0.f;
    for (int base = start; base < end; base += 32) {
        int i = base + lane;
        float w = 0.f;
        if (i < end) {
            float a = asrc[i] + ad;
            a = a > 0.f ? a : 0.01f * a;
            w = expf(a - m);
            sum += w;
        }
        int cnt = min(32, end - base);
        for (int j = 0; j < cnt; j++) {
            float wj = __shfl_sync(FULL, w, j);
            float4 v = ((const float4*)(xw + (size_t)(base + j) * HH))[lane];
            acc.x += wj * v.x;
            acc.y += wj * v.y;
            acc.z += wj * v.z;
            acc.w += wj * v.w;
        }
    }
    sum = warp_sum_all(sum);
    float rinv = 1.f / (sum + 1e-16f);
    float4 b4 = ((const float4*)bias)[lane];
    float o0 = acc.x * rinv + b4.x;
    float o1 = acc.y * rinv + b4.y;
    float o2 = acc.z * rinv + b4.z;
    float o3 = acc.w * rinv + b4.w;
    o0 = o0 > 0.f ? o0 : expf(o0) - 1.f;
    o1 = o1 > 0.f ? o1 : expf(o1) - 1.f;
    o2 = o2 > 0.f ? o2 : expf(o2) - 1.f;
    o3 = o3 > 0.f ? o3 : expf(o3) - 1.f;
    uint32_t hp0, lp0, hp1, lp1;
    split_pair(o0, o1, hp0, lp0);
    split_pair(o2, o3, hp1, lp1);
    uint32_t* hrow = hGs + (size_t)g * HH;
    int w0 = ilv(2 * lane), w1 = ilv(2 * lane + 1);
    hrow[w0] = hp0;
    hrow[w0 + 2] = lp0;
    hrow[w1] = hp1;
    hrow[w1 + 2] = lp1;
}

__global__ void final_out(const float* __restrict__ outG, const float* __restrict__ W,
                          const float* __restrict__ b, float* __restrict__ y, int g_rows) {
    int g = (blockIdx.x * blockDim.x + threadIdx.x) >> 5;
    int lane = threadIdx.x & 31;
    if (g >= g_rows) return;
    float4 v = ((const float4*)(outG + (size_t)g * HH))[lane];
    const float* vp = &v.x;
    float s = 0.f;
#pragma unroll
    for (int j = 0; j < 4; j++) s += vp[j] * W[lane * 4 + j];
    s = warp_sum_all(s);
    if (lane == 0) y[g] = s + b[0];
}

// ---------------- host ----------------
static inline int cdiv(int a, int b) { return (a + b - 1) / b; }

extern "C" void kernel_launch(void* const* d_in, const int* in_sizes, int n_in,
                              void* d_out, int out_size) {
    const float* x = (const float*)d_in[0];
    const int* ei = (const int*)d_in[1];
    const int* batch = (const int*)d_in[2];
    const float* lin1_W = (const float*)d_in[3];
    const float* lin1_b = (const float*)d_in[4];
    const float* gate_W1 = (const float*)d_in[5];
    const float* gate_W2 = (const float*)d_in[6];
    const float* gate_att_l = (const float*)d_in[7];
    const float* gate_att_r = (const float*)d_in[8];
    const float* gate_bias = (const float*)d_in[9];
    const float* gru0_Wi = (const float*)d_in[10];
    const float* gru0_bi = (const float*)d_in[11];
    const float* gru0_Wh = (const float*)d_in[12];
    const float* gru0_bh = (const float*)d_in[13];
    const float* atom_W = (const float*)d_in[14];
    const float* atom_att_src = (const float*)d_in[15];
    const float* atom_att_dst = (const float*)d_in[16];
    const float* atom_bias = (const float*)d_in[17];
    const float* atom_gru_Wi = (const float*)d_in[18];
    const float* atom_gru_bi = (const float*)d_in[19];
    const float* atom_gru_Wh = (const float*)d_in[20];
    const float* atom_gru_bh = (const float*)d_in[21];
    const float* mol_W = (const float*)d_in[22];
    const float* mol_att_src = (const float*)d_in[23];
    const float* mol_att_dst = (const float*)d_in[24];
    const float* mol_bias = (const float*)d_in[25];
    const float* mol_gru_Wi = (const float*)d_in[26];
    const float* mol_gru_bi = (const float*)d_in[27];
    const float* mol_gru_Wh = (const float*)d_in[28];
    const float* mol_gru_bh = (const float*)d_in[29];
    const float* lin2_W = (const float*)d_in[30];
    const float* lin2_b = (const float*)d_in[31];

    const int* src = ei;
    const int* dst = ei + EE;

    float *x0, *xw, *xc, *gi, *gh, *asrc, *adst, *outG, *giG, *ghG, *vvec;
    int *deg, *ptr, *cur, *csr_src, *bsum, *gptr;
    uint32_t *sx, *sx0, *sh, *sxc, *shG, *soutG;
    uint32_t *wl1, *wg1, *wg2, *wg0i, *wg0h, *watom, *watomi, *watomh, *wmol, *wmoli, *wmolh;
    cudaGetSymbolAddress((void**)&x0, d_x0);
    cudaGetSymbolAddress((void**)&xw, d_xw);
    cudaGetSymbolAddress((void**)&xc, d_xc);
    cudaGetSymbolAddress((void**)&gi, d_gi);
    cudaGetSymbolAddress((void**)&gh, d_gh);
    cudaGetSymbolAddress((void**)&asrc, d_asrc);
    cudaGetSymbolAddress((void**)&adst, d_adst);
    cudaGetSymbolAddress((void**)&outG, d_outG);
    cudaGetSymbolAddress((void**)&giG, d_giG);
    cudaGetSymbolAddress((void**)&ghG, d_ghG);
    cudaGetSymbolAddress((void**)&vvec, d_vvec);
    cudaGetSymbolAddress((void**)&deg, d_deg);
    cudaGetSymbolAddress((void**)&ptr, d_ptr);
    cudaGetSymbolAddress((void**)&cur, d_cur);
    cudaGetSymbolAddress((void**)&csr_src, d_csr_src);
    cudaGetSymbolAddress((void**)&bsum, d_bsum);
    cudaGetSymbolAddress((void**)&gptr, d_gptr);
    cudaGetSymbolAddress((void**)&sx, s_x);
    cudaGetSymbolAddress((void**)&sx0, s_x0);
    cudaGetSymbolAddress((void**)&sh, s_h);
    cudaGetSymbolAddress((void**)&sxc, s_xc);
    cudaGetSymbolAddress((void**)&shG, s_hG);
    cudaGetSymbolAddress((void**)&soutG, s_outG);
    cudaGetSymbolAddress((void**)&wl1, w_lin1);
    cudaGetSymbolAddress((void**)&wg1, w_g1);
    cudaGetSymbolAddress((void**)&wg2, w_g2);
    cudaGetSymbolAddress((void**)&wg0i, w_g0i);
    cudaGetSymbolAddress((void**)&wg0h, w_g0h);
    cudaGetSymbolAddress((void**)&watom, w_atom);
    cudaGetSymbolAddress((void**)&watomi, w_atomi);
    cudaGetSymbolAddress((void**)&watomh, w_atomh);
    cudaGetSymbolAddress((void**)&wmol, w_mol);
    cudaGetSymbolAddress((void**)&wmoli, w_moli);
    cudaGetSymbolAddress((void**)&wmolh, w_molh);

    dim3 g_n128(1, cdiv(NN, 128));
    dim3 g_n384(3, cdiv(NN, 128));
    dim3 g_g384(3, cdiv(GG, 128));
    int wpb_n = cdiv(NN, 8);
    int wpb_g = cdiv(GG, 8);
    const int nscan = cdiv(NN, 1024);

    // ---- weight + input pre-split ----
    to_split<<<cdiv(NN * 32, 256), 256>>>(x, IN_CH, sx, NN, IN_CH);
    to_split<<<cdiv(HH * 32, 256), 256>>>(lin1_W, IN_CH, wl1, HH, IN_CH);
    to_split<<<cdiv(HH * 64, 256), 256>>>(gate_W1, HH + 1, wg1, HH, HH);
    to_split<<<cdiv(HH * 64, 256), 256>>>(gate_W2, HH, wg2, HH, HH);
    to_split<<<cdiv(H3 * 64, 256), 256>>>(gru0_Wi, HH, wg0i, H3, HH);
    to_split<<<cdiv(H3 * 64, 256), 256>>>(gru0_Wh, HH, wg0h, H3, HH);
    for (int l = 0; l < 2; l++) {
        to_split<<<cdiv(HH * 64, 256), 256>>>(atom_W + (size_t)l * HH * HH, HH, watom + (size_t)l * HH * HH, HH, HH);
        to_split<<<cdiv(H3 * 64, 256), 256>>>(atom_gru_Wi + (size_t)l * H3 * HH, HH, watomi + (size_t)l * H3 * HH, H3, HH);
        to_split<<<cdiv(H3 * 64, 256), 256>>>(atom_gru_Wh + (size_t)l * H3 * HH, HH, watomh + (size_t)l * H3 * HH, H3, HH);
    }
    to_split<<<cdiv(HH * 64, 256), 256>>>(mol_W, HH, wmol, HH, HH);
    to_split<<<cdiv(H3 * 64, 256), 256>>>(mol_gru_Wi, HH, wmoli, H3, HH);
    to_split<<<cdiv(H3 * 64, 256), 256>>>(mol_gru_Wh, HH, wmolh, H3, HH);

    // ---- CSR + graph-pointer build ----
    cudaMemsetAsync(deg, 0, NN * sizeof(int));
    hist_kernel<<<cdiv(EE, 256), 256>>>(dst, deg, EE);
    scan_block<<<nscan, 256>>>(deg, ptr, bsum, NN);
    scan_bsum<<<1, 128>>>(bsum, nscan);
    scan_fixup<<<cdiv(NN, 256), 256>>>(ptr, bsum, cur, NN, EE);
    scatter_csr<<<cdiv(EE, 256), 256>>>(src, dst, cur, csr_src, EE);
    build_gptr<<<cdiv(NN, 256), 256>>>(batch, gptr, NN);

    // x0 = lrelu(x @ lin1_W^T + b)   (fp32 + split)
    bgemm<<<g_n128, 128>>>(sx, wl1, lin1_b, x0, sx0, NN, HH, IN_CH, 1);

    // ---- GATEConv ----
    bgemm<<<g_n128, 128>>>(sx0, wg1, nullptr, xw, nullptr, NN, HH, HH, 0);
    gate_node_atts<<<wpb_n, 256>>>(xw, gate_W1, gate_att_l, x0, gate_att_r, asrc, adst, NN);
    bgemm<<<g_n128, 128>>>(sx0, wg2, nullptr, xw, nullptr, NN, HH, HH, 0);
    gat_aggregate<<<wpb_n, 256>>>(ptr, csr_src, asrc, adst, xw, gate_bias, sh, NN);
    bgemm<<<g_n384, 128>>>(sh, wg0i, gru0_bi, gi, nullptr, NN, H3, HH, 0);
    bgemm<<<g_n384, 128>>>(sx0, wg0h, gru0_bh, gh, nullptr, NN, H3, HH, 0);
    gru_combine<<<cdiv(NN * 64, 256), 256>>>(gi, gh, x0, xc, sxc, NN);

    // ---- extra atom GAT + GRU layers ----
    for (int l = 0; l < 2; l++) {
        bgemm<<<g_n128, 128>>>(sxc, watom + (size_t)l * HH * HH, nullptr, xw, nullptr, NN, HH, HH, 0);
        node_two_dots<<<wpb_n, 256>>>(xw, atom_att_src + l * HH, atom_att_dst + l * HH, asrc, adst, NN);
        gat_aggregate<<<wpb_n, 256>>>(ptr, csr_src, asrc, adst, xw, atom_bias + l * HH, sh, NN);
        bgemm<<<g_n384, 128>>>(sh, watomi + (size_t)l * H3 * HH, atom_gru_bi + l * H3, gi, nullptr, NN, H3, HH, 0);
        bgemm<<<g_n384, 128>>>(sxc, watomh + (size_t)l * H3 * HH, atom_gru_bh + l * H3, gh, nullptr, NN, H3, HH, 0);
        gru_combine<<<cdiv(NN * 64, 256), 256>>>(gi, gh, xc, xc, sxc, NN);
    }

    // ---- molecule readout ----
    graph_sum<<<wpb_g, 256>>>(xc, gptr, outG, soutG, GG);
    bgemm<<<g_n128, 128>>>(sxc, wmol, nullptr, xw, nullptr, NN, HH, HH, 0);
    node_one_dot<<<wpb_n, 256>>>(xw, mol_att_src, asrc, NN);
    compute_vvec<<<1, HH>>>(mol_W, mol_att_dst, vvec);

    for (int t = 0; t < 2; t++) {
        mol_timestep<<<wpb_g, 256>>>(outG, vvec, gptr, asrc, xw, mol_bias, shG, GG);
        bgemm<<<g_g384, 128>>>(shG, wmoli, mol_gru_bi, giG, nullptr, GG, H3, HH, 0);
        bgemm<<<g_g384, 128>>>(soutG, wmolh, mol_gru_bh, ghG, nullptr, GG, H3, HH, 0);
        gru_combine<<<cdiv(GG * 64, 256), 256>>>(giG, ghG, outG, outG, soutG, GG);
    }

    final_out<<<wpb_g, 256>>>(outG, lin2_W, lin2_b, (float*)d_out, GG);
}

// round 11
// speedup vs baseline: 1.4408x; 1.0432x over previous
#include <cuda_runtime.h>
#include <cuda_bf16.h>
#include <math.h>
#include <stdint.h>

#define NN 100000
#define EE 1600000
#define IN_CH 64
#define HH 128
#define H3 384
#define GG 4096
#define FULL 0xffffffffu

// ---------------- scratch (no allocations allowed) ----------------
__device__ float d_x0[NN * HH];
__device__ float d_xw[NN * HH];
__device__ float d_xc[NN * HH];
__device__ float d_gi[NN * H3];     // used as grz (NN x 256)
__device__ float d_gh[NN * H3];     // used as gih (NN x 256: [in | hn])
__device__ float d_asrc[NN];
__device__ float d_adst[NN];
__device__ float d_outG[GG * HH];
__device__ float d_giG[GG * H3];
__device__ float d_ghG[GG * H3];
__device__ float d_vvec[HH];
__device__ int d_deg[NN];
__device__ int d_ptr[NN + 1];
__device__ int d_cur[NN];
__device__ int d_csr_src[EE];
__device__ int d_bsum[128];
__device__ int d_gptr[GG + 1];
// combined split activation buffers: row = 256 words = [h split | x split]
__device__ uint32_t s_hx[NN * 256];
__device__ uint32_t s_hxG[GG * 256];
__device__ uint32_t s_x[NN * IN_CH];
// split weights
__device__ uint32_t w_lin1[HH * IN_CH];
__device__ uint32_t w_g1[HH * HH];
__device__ uint32_t w_g2[HH * HH];
__device__ uint32_t w_atom[2 * HH * HH];
__device__ uint32_t w_mol[HH * HH];
__device__ uint32_t w_rz0[256 * 256];
__device__ uint32_t w_rza[2 * 256 * 256];
__device__ uint32_t w_rzm[256 * 256];
__device__ uint32_t w_in0[HH * HH];
__device__ uint32_t w_hn0[HH * HH];
__device__ uint32_t w_ina[2 * HH * HH];
__device__ uint32_t w_hna[2 * HH * HH];
__device__ uint32_t w_inm[HH * HH];
__device__ uint32_t w_hnm[HH * HH];
__device__ float b_rz0[256];
__device__ float b_rza[2 * 256];
__device__ float b_rzm[256];

// ---------------- helpers ----------------
__device__ __forceinline__ float warp_sum_all(float v) {
#pragma unroll
    for (int o = 16; o > 0; o >>= 1) v += __shfl_xor_sync(FULL, v, o);
    return v;
}
__device__ __forceinline__ float warp_max_all(float v) {
#pragma unroll
    for (int o = 16; o > 0; o >>= 1) v = fmaxf(v, __shfl_xor_sync(FULL, v, o));
    return v;
}

// interleave map: k-pair index cp -> word offset of its hi word (lo word at +2)
__device__ __forceinline__ int ilv(int cp) {
    int c = cp >> 3, p = cp & 7;
    return (c << 4) + ((p < 4) ? (p << 2) : (((p - 4) << 2) + 1));
}

__device__ __forceinline__ void split_pair(float f0, float f1, uint32_t& hp, uint32_t& lp) {
    uint32_t u0 = __float_as_uint(f0), u1 = __float_as_uint(f1);
    hp = __byte_perm(u0, u1, 0x7632);
    float l0 = f0 - __uint_as_float(u0 & 0xffff0000u);
    float l1 = f1 - __uint_as_float(u1 & 0xffff0000u);
    __nv_bfloat162 p = __floats2bfloat162_rn(l0, l1);
    lp = *reinterpret_cast<uint32_t*>(&p);
}

__device__ __forceinline__ void mma_bf16(float* c, const uint32_t* a, const uint32_t* b) {
    asm volatile(
        "mma.sync.aligned.m16n8k16.row.col.f32.bf16.bf16.f32 "
        "{%0,%1,%2,%3}, {%4,%5,%6,%7}, {%8,%9}, {%0,%1,%2,%3};"
        : "+f"(c[0]), "+f"(c[1]), "+f"(c[2]), "+f"(c[3])
        : "r"(a[0]), "r"(a[1]), "r"(a[2]), "r"(a[3]), "r"(b[0]), "r"(b[1]));
}

__device__ __forceinline__ void cp_async16(uint32_t dst, const void* src, bool pred) {
    asm volatile("cp.async.cg.shared.global [%0], [%1], 16, %2;"
                 :: "r"(dst), "l"(src), "r"(pred ? 16 : 0));
}

// ---------------- batched weight split ----------------
struct SDesc { const float* src; uint32_t* dst; int ld, M, K; };
struct SDescs { SDesc d[14]; };

__global__ void to_split_batch(SDescs ds) {
    SDesc d = ds.d[blockIdx.x];
    int kh = d.K >> 1;
    int total = d.M * kh;
    for (int idx = blockIdx.y * 256 + threadIdx.x; idx < total; idx += gridDim.y * 256) {
        int r = idx / kh, j = idx - r * kh;
        float f0 = d.src[(size_t)r * d.ld + 2 * j];
        float f1 = d.src[(size_t)r * d.ld + 2 * j + 1];
        uint32_t hp, lp;
        split_pair(f0, f1, hp, lp);
        int w = ilv(j);
        d.dst[(size_t)r * d.K + w] = hp;
        d.dst[(size_t)r * d.K + w + 2] = lp;
    }
}

// rz concat-split: out row n (256 rows) = [Wi[n][0:128] | Wh[n][0:128]], K=256
struct CDesc { const float* wi; const float* wh; uint32_t* dst; const float* bi; const float* bh; float* brz; };
struct CDescs { CDesc d[4]; };

__global__ void concat_rz_batch(CDescs ds) {
    CDesc d = ds.d[blockIdx.x];
    for (int idx = blockIdx.y * 256 + threadIdx.x; idx < 256 * 128; idx += gridDim.y * 256) {
        int n = idx >> 7, j = idx & 127;
        float f0, f1;
        if (j < 64) {
            f0 = d.wi[(size_t)n * HH + 2 * j];
            f1 = d.wi[(size_t)n * HH + 2 * j + 1];
        } else {
            f0 = d.wh[(size_t)n * HH + 2 * (j - 64)];
            f1 = d.wh[(size_t)n * HH + 2 * (j - 64) + 1];
        }
        uint32_t hp, lp;
        split_pair(f0, f1, hp, lp);
        int w = ilv(j);
        d.dst[(size_t)n * 256 + w] = hp;
        d.dst[(size_t)n * 256 + w + 2] = lp;
        if (j == 0) d.brz[n] = d.bi[n] + d.bh[n];
    }
}

__global__ void to_split_x(const float* __restrict__ src, uint32_t* __restrict__ dst) {
    int idx = blockIdx.x * blockDim.x + threadIdx.x;
    if (idx >= NN * 32) return;
    int r = idx >> 5, j = idx & 31;
    float f0 = src[(size_t)r * IN_CH + 2 * j];
    float f1 = src[(size_t)r * IN_CH + 2 * j + 1];
    uint32_t hp, lp;
    split_pair(f0, f1, hp, lp);
    int w = ilv(j);
    dst[(size_t)r * IN_CH + w] = hp;
    dst[(size_t)r * IN_CH + w + 2] = lp;
}

// ---------------- bf16-split tensor-core GEMM (64x64 warp tiles) ----------------
// C[r, coff + col] = act(A[r, aoff:aoff+K] @ B^T + bias[col0+c]); N tiles via grid.x.
// Cs (if set, requires grid.x==1): split write at row*csld + csoff.
__device__ __forceinline__ void bload(const uint32_t* __restrict__ Ahl, int lda, int aoff,
                                      const uint32_t* __restrict__ Bhl, int K,
                                      int M, int row0, int col0,
                                      int tid, int kc, uint32_t* sb) {
#pragma unroll
    for (int it = 0; it < 8; it++) {
        int s = tid * 8 + it;
        int r = (s >> 2) & 127;
        int j = s & 3;
        bool isB = s >= 512;
        uint32_t da = (uint32_t)__cvta_generic_to_shared(sb + (isB ? 2048 : 0) + r * 16 + 4 * j);
        const uint32_t* g;
        bool pred = true;
        if (!isB) {
            int ar = row0 + r;
            pred = ar < M;
            g = Ahl + (size_t)(pred ? ar : 0) * lda + aoff + kc * 16 + 4 * j;
        } else {
            g = Bhl + (size_t)(col0 + r) * K + kc * 16 + 4 * j;
        }
        cp_async16(da, g, pred);
    }
    asm volatile("cp.async.commit_group;");
}

__global__ void __launch_bounds__(128) bgemm(const uint32_t* __restrict__ Ahl, int lda, int aoff,
                                             const uint32_t* __restrict__ Bhl,
                                             const float* __restrict__ bias,
                                             float* __restrict__ C, int ldc, int coff,
                                             uint32_t* __restrict__ Cs, int csld, int csoff,
                                             int M, int K, int act) {
    __shared__ uint32_t sm[2][4096];
    const int tid = threadIdx.x;
    const int lane = tid & 31;
    const int warp = tid >> 5;
    const int g = lane >> 2;
    const int t = lane & 3;
    const int wrow = (warp >> 1) * 64;
    const int wcol = (warp & 1) * 64;
    const int row0 = blockIdx.y * 128;
    const int col0 = blockIdx.x * 128;
    const int nk = K >> 4;

    float acc[4][8][4];
#pragma unroll
    for (int mt = 0; mt < 4; mt++)
#pragma unroll
        for (int nt = 0; nt < 8; nt++)
#pragma unroll
            for (int i = 0; i < 4; i++) acc[mt][nt][i] = 0.f;

    bload(Ahl, lda, aoff, Bhl, K, M, row0, col0, tid, 0, sm[0]);

    for (int c = 0; c < nk; c++) {
        asm volatile("cp.async.wait_group 0;");
        __syncthreads();
        if (c + 1 < nk)
            bload(Ahl, lda, aoff, Bhl, K, M, row0, col0, tid, c + 1, sm[(c + 1) & 1]);
        const uint32_t* As = sm[c & 1];
        const uint32_t* Bs = As + 2048;

        uint32_t bhi[8][2], blo[8][2];
#pragma unroll
        for (int nt = 0; nt < 8; nt++) {
            int cc = wcol + nt * 8 + g;
            uint4 bb = *(const uint4*)(Bs + cc * 16 + 4 * t);
            bhi[nt][0] = bb.x; bhi[nt][1] = bb.y;
            blo[nt][0] = bb.z; blo[nt][1] = bb.w;
        }
#pragma unroll
        for (int mt = 0; mt < 4; mt++) {
            int r = wrow + mt * 16 + g;
            uint4 a0 = *(const uint4*)(As + r * 16 + 4 * t);
            uint4 a8 = *(const uint4*)(As + (r + 8) * 16 + 4 * t);
            uint32_t ahi[4] = {a0.x, a8.x, a0.y, a8.y};
            uint32_t alo[4] = {a0.z, a8.z, a0.w, a8.w};
#pragma unroll
            for (int nt = 0; nt < 8; nt++) {
                mma_bf16(acc[mt][nt], alo, bhi[nt]);
                mma_bf16(acc[mt][nt], ahi, blo[nt]);
                mma_bf16(acc[mt][nt], ahi, bhi[nt]);
            }
        }
    }

#pragma unroll
    for (int mt = 0; mt < 4; mt++) {
#pragma unroll
        for (int nt = 0; nt < 8; nt++) {
            int r0 = row0 + wrow + mt * 16 + g;
            int cl = wcol + nt * 8 + 2 * t;      // local col within 128-tile
            int cg = col0 + cl;                  // col within this launch's N
            float b0 = bias ? bias[cg] : 0.f;
            float b1 = bias ? bias[cg + 1] : 0.f;
            float v00 = acc[mt][nt][0] + b0, v01 = acc[mt][nt][1] + b1;
            float v10 = acc[mt][nt][2] + b0, v11 = acc[mt][nt][3] + b1;
            if (act == 1) {
                v00 = v00 > 0.f ? v00 : 0.01f * v00;
                v01 = v01 > 0.f ? v01 : 0.01f * v01;
                v10 = v10 > 0.f ? v10 : 0.01f * v10;
                v11 = v11 > 0.f ? v11 : 0.01f * v11;
            }
            if (r0 < M) {
                C[(size_t)r0 * ldc + coff + cg] = v00;
                C[(size_t)r0 * ldc + coff + cg + 1] = v01;
                if (Cs) {
                    uint32_t hp, lp;
                    split_pair(v00, v01, hp, lp);
                    int w = csoff + ilv(cl >> 1);
                    Cs[(size_t)r0 * csld + w] = hp;
                    Cs[(size_t)r0 * csld + w + 2] = lp;
                }
            }
            if (r0 + 8 < M) {
                C[(size_t)(r0 + 8) * ldc + coff + cg] = v10;
                C[(size_t)(r0 + 8) * ldc + coff + cg + 1] = v11;
                if (Cs) {
                    uint32_t hp, lp;
                    split_pair(v10, v11, hp, lp);
                    int w = csoff + ilv(cl >> 1);
                    Cs[(size_t)(r0 + 8) * csld + w] = hp;
                    Cs[(size_t)(r0 + 8) * csld + w + 2] = lp;
                }
            }
        }
    }
}

// ---------------- CSR build ----------------
__global__ void hist_kernel(const int* __restrict__ dst, int* __restrict__ deg, int n_e) {
    int e = blockIdx.x * blockDim.x + threadIdx.x;
    if (e < n_e) atomicAdd(&deg[dst[e]], 1);
}

__global__ void scan_block(const int* __restrict__ in, int* __restrict__ out,
                           int* __restrict__ bsum, int n) {
    __shared__ int s[256];
    int t = threadIdx.x;
    int base = blockIdx.x * 1024 + t * 4;
    int v[4];
#pragma unroll
    for (int j = 0; j < 4; j++) v[j] = (base + j < n) ? in[base + j] : 0;
    int tsum = v[0] + v[1] + v[2] + v[3];
    s[t] = tsum;
    __syncthreads();
    for (int off = 1; off < 256; off <<= 1) {
        int x = (t >= off) ? s[t - off] : 0;
        __syncthreads();
        s[t] += x;
        __syncthreads();
    }
    int exc = s[t] - tsum;
    if (t == 255) bsum[blockIdx.x] = s[t];
    int run = exc;
#pragma unroll
    for (int j = 0; j < 4; j++) {
        if (base + j < n) out[base + j] = run;
        run += v[j];
    }
}

__global__ void scan_bsum(int* __restrict__ bsum, int nb) {
    __shared__ int s[128];
    int t = threadIdx.x;
    int orig = (t < nb) ? bsum[t] : 0;
    s[t] = orig;
    __syncthreads();
    for (int off = 1; off < 128; off <<= 1) {
        int x = (t >= off) ? s[t - off] : 0;
        __syncthreads();
        s[t] += x;
        __syncthreads();
    }
    if (t < nb) bsum[t] = s[t] - orig;
}

__global__ void scan_fixup(int* __restrict__ ptr, const int* __restrict__ bsum,
                           int* __restrict__ cur, int n, int total) {
    int i = blockIdx.x * blockDim.x + threadIdx.x;
    if (i < n) {
        int p = ptr[i] + bsum[i >> 10];
        ptr[i] = p;
        cur[i] = p;
    }
    if (i == 0) ptr[n] = total;
}

__global__ void scatter_csr(const int* __restrict__ src, const int* __restrict__ dst,
                            int* __restrict__ cur, int* __restrict__ csr_src, int n_e) {
    int e = blockIdx.x * blockDim.x + threadIdx.x;
    if (e >= n_e) return;
    int p = atomicAdd(&cur[dst[e]], 1);
    csr_src[p] = src[e];
}

__global__ void build_gptr(const int* __restrict__ batch, int* __restrict__ gptr, int n) {
    int i = blockIdx.x * blockDim.x + threadIdx.x;
    if (i >= n) return;
    int b = batch[i];
    int prev = (i == 0) ? -1 : batch[i - 1];
    for (int g = prev + 1; g <= b; g++) gptr[g] = i;
    if (i == n - 1)
        for (int g = b + 1; g <= GG; g++) gptr[g] = n;
}

// ---------------- fused GAT aggregation (warp per destination node) ----------------
// writes h split into s_hx cols [0,128) (row stride 256)
__global__ void gat_aggregate(const int* __restrict__ ptr, const int* __restrict__ csr,
                              const float* __restrict__ asrc, const float* __restrict__ adst,
                              const float* __restrict__ xw, const float* __restrict__ bias,
                              uint32_t* __restrict__ hs, int n_rows) {
    int row = blockIdx.x * 8 + (threadIdx.x >> 5);
    int lane = threadIdx.x & 31;
    if (row >= n_rows) return;
    int start = ptr[row], end = ptr[row + 1];
    float ad = adst[row];

    float m = -INFINITY;
    for (int e = start + lane; e < end; e += 32) {
        float a = asrc[csr[e]] + ad;
        a = a > 0.f ? a : 0.01f * a;
        m = fmaxf(m, a);
    }
    m = warp_max_all(m);

    float4 acc = make_float4(0.f, 0.f, 0.f, 0.f);
    float sum = 0.f;
    for (int base = start; base < end; base += 32) {
        int e = base + lane;
        float w = 0.f;
        int s = 0;
        if (e < end) {
            s = csr[e];
            float a = asrc[s] + ad;
            a = a > 0.f ? a : 0.01f * a;
            w = expf(a - m);
            sum += w;
        }
        int cnt = min(32, end - base);
        for (int j = 0; j < cnt; j++) {
            float wj = __shfl_sync(FULL, w, j);
            int sj = __shfl_sync(FULL, s, j);
            float4 v = ((const float4*)(xw + (size_t)sj * HH))[lane];
            acc.x += wj * v.x;
            acc.y += wj * v.y;
            acc.z += wj * v.z;
            acc.w += wj * v.w;
        }
    }
    sum = warp_sum_all(sum);
    float rinv = 1.f / (sum + 1e-16f);
    float4 b4 = ((const float4*)bias)[lane];
    float o0 = acc.x * rinv + b4.x;
    float o1 = acc.y * rinv + b4.y;
    float o2 = acc.z * rinv + b4.z;
    float o3 = acc.w * rinv + b4.w;
    o0 = o0 > 0.f ? o0 : expf(o0) - 1.f;
    o1 = o1 > 0.f ? o1 : expf(o1) - 1.f;
    o2 = o2 > 0.f ? o2 : expf(o2) - 1.f;
    o3 = o3 > 0.f ? o3 : expf(o3) - 1.f;
    uint32_t hp0, lp0, hp1, lp1;
    split_pair(o0, o1, hp0, lp0);
    split_pair(o2, o3, hp1, lp1);
    uint32_t* hr = hs + (size_t)row * 256;
    int w0 = ilv(2 * lane), w1 = ilv(2 * lane + 1);
    hr[w0] = hp0;
    hr[w0 + 2] = lp0;
    hr[w1] = hp1;
    hr[w1 + 2] = lp1;
}

// ---------------- GATEConv per-node attention scalars ----------------
__global__ void gate_node_atts(const float* __restrict__ tmp, const float* __restrict__ W1,
                               const float* __restrict__ att_l, const float* __restrict__ x0,
                               const float* __restrict__ att_r, float* __restrict__ asrc,
                               float* __restrict__ adst, int n_rows) {
    int w = (blockIdx.x * blockDim.x + threadIdx.x) >> 5;
    int lane = threadIdx.x & 31;
    if (w >= n_rows) return;
    float4 tv = ((const float4*)(tmp + (size_t)w * HH))[lane];
    float4 xv = ((const float4*)(x0 + (size_t)w * HH))[lane];
    float s1 = 0.f, s2 = 0.f;
    const float* t = &tv.x;
    const float* xp = &xv.x;
#pragma unroll
    for (int j = 0; j < 4; j++) {
        int k = lane * 4 + j;
        float xe = t[j] + W1[(size_t)k * (HH + 1) + HH];
        xe = xe > 0.f ? xe : 0.01f * xe;
        s1 += xe * att_l[k];
        s2 += xp[j] * att_r[k];
    }
    s1 = warp_sum_all(s1);
    s2 = warp_sum_all(s2);
    if (lane == 0) { asrc[w] = s1; adst[w] = s2; }
}

__global__ void node_two_dots(const float* __restrict__ xw, const float* __restrict__ v1,
                              const float* __restrict__ v2, float* __restrict__ o1,
                              float* __restrict__ o2, int n_rows) {
    int w = (blockIdx.x * blockDim.x + threadIdx.x) >> 5;
    int lane = threadIdx.x & 31;
    if (w >= n_rows) return;
    float4 xv = ((const float4*)(xw + (size_t)w * HH))[lane];
    const float* xp = &xv.x;
    float s1 = 0.f, s2 = 0.f;
#pragma unroll
    for (int j = 0; j < 4; j++) {
        int k = lane * 4 + j;
        s1 += xp[j] * v1[k];
        s2 += xp[j] * v2[k];
    }
    s1 = warp_sum_all(s1);
    s2 = warp_sum_all(s2);
    if (lane == 0) { o1[w] = s1; o2[w] = s2; }
}

__global__ void node_one_dot(const float* __restrict__ xw, const float* __restrict__ v1,
                             float* __restrict__ o1, int n_rows) {
    int w = (blockIdx.x * blockDim.x + threadIdx.x) >> 5;
    int lane = threadIdx.x & 31;
    if (w >= n_rows) return;
    float4 xv = ((const float4*)(xw + (size_t)w * HH))[lane];
    const float* xp = &xv.x;
    float s1 = 0.f;
#pragma unroll
    for (int j = 0; j < 4; j++) s1 += xp[j] * v1[lane * 4 + j];
    s1 = warp_sum_all(s1);
    if (lane == 0) o1[w] = s1;
}

// ---------------- GRU combine (rz-concat form) ----------------
// grz[r][c] = ir+hr+b (c<128), grz[r][c+128] = iz+hz+b
// gih[r][c] = in + bi_n, gih[r][c+128] = hn + bh_n
// out fp32 (stride HH) + split into outs cols [128,256) (stride 256)
__global__ void gru_combine2(const float* __restrict__ grz, const float* __restrict__ gih,
                             const float* __restrict__ hprev, float* __restrict__ outp,
                             uint32_t* __restrict__ outs, int rows) {
    int idx = blockIdx.x * blockDim.x + threadIdx.x;
    if (idx >= rows * 64) return;
    int r = idx >> 6, cp = idx & 63;
    float2 vr = *(const float2*)(grz + (size_t)r * 256 + 2 * cp);
    float2 vz = *(const float2*)(grz + (size_t)r * 256 + 128 + 2 * cp);
    float2 vin = *(const float2*)(gih + (size_t)r * 256 + 2 * cp);
    float2 vhn = *(const float2*)(gih + (size_t)r * 256 + 128 + 2 * cp);
    float2 hp2 = *(const float2*)(hprev + (size_t)r * HH + 2 * cp);
    float o[2];
    {
        float rr = 1.f / (1.f + expf(-vr.x));
        float z = 1.f / (1.f + expf(-vz.x));
        float n = tanhf(vin.x + rr * vhn.x);
        float v = (1.f - z) * n + z * hp2.x;
        o[0] = v > 0.f ? v : 0.f;
    }
    {
        float rr = 1.f / (1.f + expf(-vr.y));
        float z = 1.f / (1.f + expf(-vz.y));
        float n = tanhf(vin.y + rr * vhn.y);
        float v = (1.f - z) * n + z * hp2.y;
        o[1] = v > 0.f ? v : 0.f;
    }
    ((float2*)(outp + (size_t)r * HH))[cp] = make_float2(o[0], o[1]);
    uint32_t hp, lp;
    split_pair(o[0], o[1], hp, lp);
    int w = 128 + ilv(cp);
    outs[(size_t)r * 256 + w] = hp;
    outs[(size_t)r * 256 + w + 2] = lp;
}

// ---------------- molecule readout (warp per graph) ----------------
__global__ void graph_sum(const float* __restrict__ xc, const int* __restrict__ gptr,
                          float* __restrict__ outG, uint32_t* __restrict__ outGs, int n_g) {
    int g = blockIdx.x * 8 + (threadIdx.x >> 5);
    int lane = threadIdx.x & 31;
    if (g >= n_g) return;
    int start = gptr[g], end = gptr[g + 1];
    float4 acc = make_float4(0.f, 0.f, 0.f, 0.f);
    for (int i = start; i < end; i++) {
        float4 v = ((const float4*)(xc + (size_t)i * HH))[lane];
        acc.x += v.x; acc.y += v.y; acc.z += v.z; acc.w += v.w;
    }
    acc.x = fmaxf(acc.x, 0.f);
    acc.y = fmaxf(acc.y, 0.f);
    acc.z = fmaxf(acc.z, 0.f);
    acc.w = fmaxf(acc.w, 0.f);
    ((float4*)(outG + (size_t)g * HH))[lane] = acc;
    uint32_t hp0, lp0, hp1, lp1;
    split_pair(acc.x, acc.y, hp0, lp0);
    split_pair(acc.z, acc.w, hp1, lp1);
    uint32_t* orow = outGs + (size_t)g * 256;
    int w0 = 128 + ilv(2 * lane), w1 = 128 + ilv(2 * lane + 1);
    orow[w0] = hp0;
    orow[w0 + 2] = lp0;
    orow[w1] = hp1;
    orow[w1 + 2] = lp1;
}

__global__ void compute_vvec(const float* __restrict__ molW, const float* __restrict__ attdst,
                             float* __restrict__ v) {
    int k = threadIdx.x;
    float s = 0.f;
    for (int j = 0; j < HH; j++) s += molW[(size_t)j * HH + k] * attdst[j];
    v[k] = s;
}

// writes hG split into s_hxG cols [0,128)
__global__ void mol_timestep(const float* __restrict__ outG, const float* __restrict__ vvec,
                             const int* __restrict__ gptr, const float* __restrict__ asrc,
                             const float* __restrict__ xw, const float* __restrict__ bias,
                             uint32_t* __restrict__ hGs, int n_g) {
    int g = blockIdx.x * 8 + (threadIdx.x >> 5);
    int lane = threadIdx.x & 31;
    if (g >= n_g) return;
    float4 ov = ((const float4*)(outG + (size_t)g * HH))[lane];
    float4 vv = ((const float4*)vvec)[lane];
    float ad = warp_sum_all(ov.x * vv.x + ov.y * vv.y + ov.z * vv.z + ov.w * vv.w);

    int start = gptr[g], end = gptr[g + 1];
    float m = -INFINITY;
    for (int i = start + lane; i < end; i += 32) {
        float a = asrc[i] + ad;
        a = a > 0.f ? a : 0.01f * a;
        m = fmaxf(m, a);
    }
    m = warp_max_all(m);

    float4 acc = make_float4(0.f, 0.f, 0.f, 0.f);
    float sum = 0.f;
    for (int base = start; base < end; base += 32) {
        int i = base + lane;
        float w = 0.f;
        if (i < end) {
            float a = asrc[i] + ad;
            a = a > 0.f ? a : 0.01f * a;
            w = expf(a - m);
            sum += w;
        }
        int cnt = min(32, end - base);
        for (int j = 0; j < cnt; j++) {
            float wj = __shfl_sync(FULL, w, j);
            float4 v = ((const float4*)(xw + (size_t)(base + j) * HH))[lane];
            acc.x += wj * v.x;
            acc.y += wj * v.y;
            acc.z += wj * v.z;
            acc.w += wj * v.w;
        }
    }
    sum = warp_sum_all(sum);
    float rinv = 1.f / (sum + 1e-16f);
    float4 b4 = ((const float4*)bias)[lane];
    float o0 = acc.x * rinv + b4.x;
    float o1 = acc.y * rinv + b4.y;
    float o2 = acc.z * rinv + b4.z;
    float o3 = acc.w * rinv + b4.w;
    o0 = o0 > 0.f ? o0 : expf(o0) - 1.f;
    o1 = o1 > 0.f ? o1 : expf(o1) - 1.f;
    o2 = o2 > 0.f ? o2 : expf(o2) - 1.f;
    o3 = o3 > 0.f ? o3 : expf(o3) - 1.f;
    uint32_t hp0, lp0, hp1, lp1;
    split_pair(o0, o1, hp0, lp0);
    split_pair(o2, o3, hp1, lp1);
    uint32_t* hrow = hGs + (size_t)g * 256;
    int w0 = ilv(2 * lane), w1 = ilv(2 * lane + 1);
    hrow[w0] = hp0;
    hrow[w0 + 2] = lp0;
    hrow[w1] = hp1;
    hrow[w1 + 2] = lp1;
}

__global__ void final_out(const float* __restrict__ outG, const float* __restrict__ W,
                          const float* __restrict__ b, float* __restrict__ y, int g_rows) {
    int g = (blockIdx.x * blockDim.x + threadIdx.x) >> 5;
    int lane = threadIdx.x & 31;
    if (g >= g_rows) return;
    float4 v = ((const float4*)(outG + (size_t)g * HH))[lane];
    const float* vp = &v.x;
    float s = 0.f;
#pragma unroll
    for (int j = 0; j < 4; j++) s += vp[j] * W[lane * 4 + j];
    s = warp_sum_all(s);
    if (lane == 0) y[g] = s + b[0];
}

// ---------------- host ----------------
static inline int cdiv(int a, int b) { return (a + b - 1) / b; }

extern "C" void kernel_launch(void* const* d_in, const int* in_sizes, int n_in,
                              void* d_out, int out_size) {
    const float* x = (const float*)d_in[0];
    const int* ei = (const int*)d_in[1];
    const int* batch = (const int*)d_in[2];
    const float* lin1_W = (const float*)d_in[3];
    const float* lin1_b = (const float*)d_in[4];
    const float* gate_W1 = (const float*)d_in[5];
    const float* gate_W2 = (const float*)d_in[6];
    const float* gate_att_l = (const float*)d_in[7];
    const float* gate_att_r = (const float*)d_in[8];
    const float* gate_bias = (const float*)d_in[9];
    const float* gru0_Wi = (const float*)d_in[10];
    const float* gru0_bi = (const float*)d_in[11];
    const float* gru0_Wh = (const float*)d_in[12];
    const float* gru0_bh = (const float*)d_in[13];
    const float* atom_W = (const float*)d_in[14];
    const float* atom_att_src = (const float*)d_in[15];
    const float* atom_att_dst = (const float*)d_in[16];
    const float* atom_bias = (const float*)d_in[17];
    const float* atom_gru_Wi = (const float*)d_in[18];
    const float* atom_gru_bi = (const float*)d_in[19];
    const float* atom_gru_Wh = (const float*)d_in[20];
    const float* atom_gru_bh = (const float*)d_in[21];
    const float* mol_W = (const float*)d_in[22];
    const float* mol_att_src = (const float*)d_in[23];
    const float* mol_att_dst = (const float*)d_in[24];
    const float* mol_bias = (const float*)d_in[25];
    const float* mol_gru_Wi = (const float*)d_in[26];
    const float* mol_gru_bi = (const float*)d_in[27];
    const float* mol_gru_Wh = (const float*)d_in[28];
    const float* mol_gru_bh = (const float*)d_in[29];
    const float* lin2_W = (const float*)d_in[30];
    const float* lin2_b = (const float*)d_in[31];

    const int* src = ei;
    const int* dst = ei + EE;

    float *x0, *xw, *xc, *grz, *gih, *asrc, *adst, *outG, *grzG, *gihG, *vvec;
    int *deg, *ptr, *cur, *csr_src, *bsum, *gptr;
    uint32_t *sx, *shx, *shxG;
    uint32_t *wl1, *wg1, *wg2, *watom, *wmol;
    uint32_t *wrz0, *wrza, *wrzm, *win0, *whn0, *wina, *whna, *winm, *whnm;
    float *brz0, *brza, *brzm;
    cudaGetSymbolAddress((void**)&x0, d_x0);
    cudaGetSymbolAddress((void**)&xw, d_xw);
    cudaGetSymbolAddress((void**)&xc, d_xc);
    cudaGetSymbolAddress((void**)&grz, d_gi);
    cudaGetSymbolAddress((void**)&gih, d_gh);
    cudaGetSymbolAddress((void**)&asrc, d_asrc);
    cudaGetSymbolAddress((void**)&adst, d_adst);
    cudaGetSymbolAddress((void**)&outG, d_outG);
    cudaGetSymbolAddress((void**)&grzG, d_giG);
    cudaGetSymbolAddress((void**)&gihG, d_ghG);
    cudaGetSymbolAddress((void**)&vvec, d_vvec);
    cudaGetSymbolAddress((void**)&deg, d_deg);
    cudaGetSymbolAddress((void**)&ptr, d_ptr);
    cudaGetSymbolAddress((void**)&cur, d_cur);
    cudaGetSymbolAddress((void**)&csr_src, d_csr_src);
    cudaGetSymbolAddress((void**)&bsum, d_bsum);
    cudaGetSymbolAddress((void**)&gptr, d_gptr);
    cudaGetSymbolAddress((void**)&sx, s_x);
    cudaGetSymbolAddress((void**)&shx, s_hx);
    cudaGetSymbolAddress((void**)&shxG, s_hxG);
    cudaGetSymbolAddress((void**)&wl1, w_lin1);
    cudaGetSymbolAddress((void**)&wg1, w_g1);
    cudaGetSymbolAddress((void**)&wg2, w_g2);
    cudaGetSymbolAddress((void**)&watom, w_atom);
    cudaGetSymbolAddress((void**)&wmol, w_mol);
    cudaGetSymbolAddress((void**)&wrz0, w_rz0);
    cudaGetSymbolAddress((void**)&wrza, w_rza);
    cudaGetSymbolAddress((void**)&wrzm, w_rzm);
    cudaGetSymbolAddress((void**)&win0, w_in0);
    cudaGetSymbolAddress((void**)&whn0, w_hn0);
    cudaGetSymbolAddress((void**)&wina, w_ina);
    cudaGetSymbolAddress((void**)&whna, w_hna);
    cudaGetSymbolAddress((void**)&winm, w_inm);
    cudaGetSymbolAddress((void**)&whnm, w_hnm);
    cudaGetSymbolAddress((void**)&brz0, b_rz0);
    cudaGetSymbolAddress((void**)&brza, b_rza);
    cudaGetSymbolAddress((void**)&brzm, b_rzm);

    dim3 g_n128(1, cdiv(NN, 128));
    dim3 g_n256(2, cdiv(NN, 128));
    dim3 g_g128(1, cdiv(GG, 128));
    dim3 g_g256(2, cdiv(GG, 128));
    int wpb_n = cdiv(NN, 8);
    int wpb_g = cdiv(GG, 8);
    const int nscan = cdiv(NN, 1024);

    // ---- batched weight prep (3 launches) ----
    SDescs sd;
    sd.d[0] = {lin1_W, wl1, IN_CH, HH, IN_CH};
    sd.d[1] = {gate_W1, wg1, HH + 1, HH, HH};
    sd.d[2] = {gate_W2, wg2, HH, HH, HH};
    sd.d[3] = {mol_W, wmol, HH, HH, HH};
    sd.d[4] = {atom_W, watom, HH, HH, HH};
    sd.d[5] = {atom_W + (size_t)HH * HH, watom + (size_t)HH * HH, HH, HH, HH};
    sd.d[6] = {gru0_Wi + 256 * HH, win0, HH, HH, HH};
    sd.d[7] = {gru0_Wh + 256 * HH, whn0, HH, HH, HH};
    sd.d[8] = {atom_gru_Wi + 256 * HH, wina, HH, HH, HH};
    sd.d[9] = {atom_gru_Wi + (size_t)H3 * HH + 256 * HH, wina + (size_t)HH * HH, HH, HH, HH};
    sd.d[10] = {atom_gru_Wh + 256 * HH, whna, HH, HH, HH};
    sd.d[11] = {atom_gru_Wh + (size_t)H3 * HH + 256 * HH, whna + (size_t)HH * HH, HH, HH, HH};
    sd.d[12] = {mol_gru_Wi + 256 * HH, winm, HH, HH, HH};
    sd.d[13] = {mol_gru_Wh + 256 * HH, whnm, HH, HH, HH};
    to_split_batch<<<dim3(14, 8), 256>>>(sd);

    CDescs cd;
    cd.d[0] = {gru0_Wi, gru0_Wh, wrz0, gru0_bi, gru0_bh, brz0};
    cd.d[1] = {atom_gru_Wi, atom_gru_Wh, wrza, atom_gru_bi, atom_gru_bh, brza};
    cd.d[2] = {atom_gru_Wi + (size_t)H3 * HH, atom_gru_Wh + (size_t)H3 * HH,
               wrza + 256 * 256, atom_gru_bi + H3, atom_gru_bh + H3, brza + 256};
    cd.d[3] = {mol_gru_Wi, mol_gru_Wh, wrzm, mol_gru_bi, mol_gru_bh, brzm};
    concat_rz_batch<<<dim3(4, 16), 256>>>(cd);

    to_split_x<<<cdiv(NN * 32, 256), 256>>>(x, sx);

    // ---- CSR + graph-pointer build ----
    cudaMemsetAsync(deg, 0, NN * sizeof(int));
    hist_kernel<<<cdiv(EE, 256), 256>>>(dst, deg, EE);
    scan_block<<<nscan, 256>>>(deg, ptr, bsum, NN);
    scan_bsum<<<1, 128>>>(bsum, nscan);
    scan_fixup<<<cdiv(NN, 256), 256>>>(ptr, bsum, cur, NN, EE);
    scatter_csr<<<cdiv(EE, 256), 256>>>(src, dst, cur, csr_src, EE);
    build_gptr<<<cdiv(NN, 256), 256>>>(batch, gptr, NN);

    // x0 = lrelu(x @ lin1_W^T + b): fp32 + split into s_hx x-part
    bgemm<<<g_n128, 128>>>(sx, IN_CH, 0, wl1, lin1_b, x0, HH, 0, shx, 256, 128, NN, IN_CH, 1);

    // ---- GATEConv ----
    bgemm<<<g_n128, 128>>>(shx, 256, 128, wg1, nullptr, xw, HH, 0, nullptr, 0, 0, NN, HH, 0);
    gate_node_atts<<<wpb_n, 256>>>(xw, gate_W1, gate_att_l, x0, gate_att_r, asrc, adst, NN);
    bgemm<<<g_n128, 128>>>(shx, 256, 128, wg2, nullptr, xw, HH, 0, nullptr, 0, 0, NN, HH, 0);
    gat_aggregate<<<wpb_n, 256>>>(ptr, csr_src, asrc, adst, xw, gate_bias, shx, NN);
    bgemm<<<g_n256, 128>>>(shx, 256, 0, wrz0, brz0, grz, 256, 0, nullptr, 0, 0, NN, 256, 0);
    bgemm<<<g_n128, 128>>>(shx, 256, 0, win0, gru0_bi + 256, gih, 256, 0, nullptr, 0, 0, NN, HH, 0);
    bgemm<<<g_n128, 128>>>(shx, 256, 128, whn0, gru0_bh + 256, gih, 256, 128, nullptr, 0, 0, NN, HH, 0);
    gru_combine2<<<cdiv(NN * 64, 256), 256>>>(grz, gih, x0, xc, shx, NN);

    // ---- extra atom GAT + GRU layers ----
    for (int l = 0; l < 2; l++) {
        bgemm<<<g_n128, 128>>>(shx, 256, 128, watom + (size_t)l * HH * HH, nullptr, xw, HH, 0, nullptr, 0, 0, NN, HH, 0);
        node_two_dots<<<wpb_n, 256>>>(xw, atom_att_src + l * HH, atom_att_dst + l * HH, asrc, adst, NN);
        gat_aggregate<<<wpb_n, 256>>>(ptr, csr_src, asrc, adst, xw, atom_bias + l * HH, shx, NN);
        bgemm<<<g_n256, 128>>>(shx, 256, 0, wrza + (size_t)l * 256 * 256, brza + l * 256, grz, 256, 0, nullptr, 0, 0, NN, 256, 0);
        bgemm<<<g_n128, 128>>>(shx, 256, 0, wina + (size_t)l * HH * HH, atom_gru_bi + l * H3 + 256, gih, 256, 0, nullptr, 0, 0, NN, HH, 0);
        bgemm<<<g_n128, 128>>>(shx, 256, 128, whna + (size_t)l * HH * HH, atom_gru_bh + l * H3 + 256, gih, 256, 128, nullptr, 0, 0, NN, HH, 0);
        gru_combine2<<<cdiv(NN * 64, 256), 256>>>(grz, gih, xc, xc, shx, NN);
    }

    // ---- molecule readout ----
    graph_sum<<<wpb_g, 256>>>(xc, gptr, outG, shxG, GG);
    bgemm<<<g_n128, 128>>>(shx, 256, 128, wmol, nullptr, xw, HH, 0, nullptr, 0, 0, NN, HH, 0);
    node_one_dot<<<wpb_n, 256>>>(xw, mol_att_src, asrc, NN);
    compute_vvec<<<1, HH>>>(mol_W, mol_att_dst, vvec);

    for (int t = 0; t < 2; t++) {
        mol_timestep<<<wpb_g, 256>>>(outG, vvec, gptr, asrc, xw, mol_bias, shxG, GG);
        bgemm<<<g_g256, 128>>>(shxG, 256, 0, wrzm, brzm, grzG, 256, 0, nullptr, 0, 0, GG, 256, 0);
        bgemm<<<g_g128, 128>>>(shxG, 256, 0, winm, mol_gru_bi + 256, gihG, 256, 0, nullptr, 0, 0, GG, HH, 0);
        bgemm<<<g_g128, 128>>>(shxG, 256, 128, whnm, mol_gru_bh + 256, gihG, 256, 128, nullptr, 0, 0, GG, HH, 0);
        gru_combine2<<<cdiv(GG * 64, 256), 256>>>(grzG, gihG, outG, outG, shxG, GG);
    }

    final_out<<<wpb_g, 256>>>(outG, lin2_W, lin2_b, (float*)d_out, GG);
}

// round 12
// speedup vs baseline: 1.4841x; 1.0300x over previous
#include <cuda_runtime.h>
#include <cuda_bf16.h>
#include <math.h>
#include <stdint.h>

#define NN 100000
#define EE 1600000
#define IN_CH 64
#define HH 128
#define H3 384
#define GG 4096
#define FULL 0xffffffffu
#define BG_SMEM 49152   // 3 stages x 4096 words

// ---------------- scratch (no allocations allowed) ----------------
__device__ float d_x0[NN * HH];
__device__ float d_xw[NN * HH];
__device__ float d_xc[NN * HH];
__device__ float d_gi[NN * H3];     // grz (NN x 256)
__device__ float d_gh[NN * H3];     // gih (NN x 256) / wg1 temp
__device__ float d_asrc[NN];
__device__ float d_adst[NN];
__device__ float d_outG[GG * HH];
__device__ float d_giG[GG * H3];
__device__ float d_ghG[GG * H3];
__device__ float d_vvec[HH];
__device__ int d_deg[NN];
__device__ int d_ptr[NN + 1];
__device__ int d_cur[NN];
__device__ int d_csr_src[EE];
__device__ int d_bsum[128];
__device__ int d_gptr[GG + 1];
// combined split activation buffers: row = 256 words = [h split | x split]
__device__ uint32_t s_hx[NN * 256];
__device__ uint32_t s_hxG[GG * 256];
__device__ uint32_t s_x[NN * IN_CH];
// split weights
__device__ uint32_t w_lin1[HH * IN_CH];
__device__ uint32_t w_g1[HH * HH];
__device__ uint32_t w_g2[HH * HH];
__device__ uint32_t w_atom[2 * HH * HH];
__device__ uint32_t w_mol[HH * HH];
__device__ uint32_t w_rz0[256 * 256];
__device__ uint32_t w_rza[2 * 256 * 256];
__device__ uint32_t w_rzm[256 * 256];
__device__ uint32_t w_in0[HH * HH];
__device__ uint32_t w_hn0[HH * HH];
__device__ uint32_t w_ina[2 * HH * HH];
__device__ uint32_t w_hna[2 * HH * HH];
__device__ uint32_t w_inm[HH * HH];
__device__ uint32_t w_hnm[HH * HH];
__device__ float b_rz0[256];
__device__ float b_rza[2 * 256];
__device__ float b_rzm[256];

// ---------------- helpers ----------------
__device__ __forceinline__ float warp_sum_all(float v) {
#pragma unroll
    for (int o = 16; o > 0; o >>= 1) v += __shfl_xor_sync(FULL, v, o);
    return v;
}
__device__ __forceinline__ float warp_max_all(float v) {
#pragma unroll
    for (int o = 16; o > 0; o >>= 1) v = fmaxf(v, __shfl_xor_sync(FULL, v, o));
    return v;
}

__device__ __forceinline__ int ilv(int cp) {
    int c = cp >> 3, p = cp & 7;
    return (c << 4) + ((p < 4) ? (p << 2) : (((p - 4) << 2) + 1));
}

__device__ __forceinline__ void split_pair(float f0, float f1, uint32_t& hp, uint32_t& lp) {
    uint32_t u0 = __float_as_uint(f0), u1 = __float_as_uint(f1);
    hp = __byte_perm(u0, u1, 0x7632);
    float l0 = f0 - __uint_as_float(u0 & 0xffff0000u);
    float l1 = f1 - __uint_as_float(u1 & 0xffff0000u);
    __nv_bfloat162 p = __floats2bfloat162_rn(l0, l1);
    lp = *reinterpret_cast<uint32_t*>(&p);
}

__device__ __forceinline__ void mma_bf16(float* c, const uint32_t* a, const uint32_t* b) {
    asm volatile(
        "mma.sync.aligned.m16n8k16.row.col.f32.bf16.bf16.f32 "
        "{%0,%1,%2,%3}, {%4,%5,%6,%7}, {%8,%9}, {%0,%1,%2,%3};"
        : "+f"(c[0]), "+f"(c[1]), "+f"(c[2]), "+f"(c[3])
        : "r"(a[0]), "r"(a[1]), "r"(a[2]), "r"(a[3]), "r"(b[0]), "r"(b[1]));
}

__device__ __forceinline__ void cp_async16(uint32_t dst, const void* src, bool pred) {
    asm volatile("cp.async.cg.shared.global [%0], [%1], 16, %2;"
                 :: "r"(dst), "l"(src), "r"(pred ? 16 : 0));
}

// ---------------- batched weight split ----------------
struct SDesc { const float* src; uint32_t* dst; int ld, M, K; };
struct SDescs { SDesc d[14]; };

__global__ void to_split_batch(SDescs ds) {
    SDesc d = ds.d[blockIdx.x];
    int kh = d.K >> 1;
    int total = d.M * kh;
    for (int idx = blockIdx.y * 256 + threadIdx.x; idx < total; idx += gridDim.y * 256) {
        int r = idx / kh, j = idx - r * kh;
        float f0 = d.src[(size_t)r * d.ld + 2 * j];
        float f1 = d.src[(size_t)r * d.ld + 2 * j + 1];
        uint32_t hp, lp;
        split_pair(f0, f1, hp, lp);
        int w = ilv(j);
        d.dst[(size_t)r * d.K + w] = hp;
        d.dst[(size_t)r * d.K + w + 2] = lp;
    }
}

struct CDesc { const float* wi; const float* wh; uint32_t* dst; const float* bi; const float* bh; float* brz; };
struct CDescs { CDesc d[4]; };

__global__ void concat_rz_batch(CDescs ds) {
    CDesc d = ds.d[blockIdx.x];
    for (int idx = blockIdx.y * 256 + threadIdx.x; idx < 256 * 128; idx += gridDim.y * 256) {
        int n = idx >> 7, j = idx & 127;
        float f0, f1;
        if (j < 64) {
            f0 = d.wi[(size_t)n * HH + 2 * j];
            f1 = d.wi[(size_t)n * HH + 2 * j + 1];
        } else {
            f0 = d.wh[(size_t)n * HH + 2 * (j - 64)];
            f1 = d.wh[(size_t)n * HH + 2 * (j - 64) + 1];
        }
        uint32_t hp, lp;
        split_pair(f0, f1, hp, lp);
        int w = ilv(j);
        d.dst[(size_t)n * 256 + w] = hp;
        d.dst[(size_t)n * 256 + w + 2] = lp;
        if (j == 0) d.brz[n] = d.bi[n] + d.bh[n];
    }
}

__global__ void to_split_x(const float* __restrict__ src, uint32_t* __restrict__ dst) {
    int idx = blockIdx.x * blockDim.x + threadIdx.x;
    if (idx >= NN * 32) return;
    int r = idx >> 5, j = idx & 31;
    float f0 = src[(size_t)r * IN_CH + 2 * j];
    float f1 = src[(size_t)r * IN_CH + 2 * j + 1];
    uint32_t hp, lp;
    split_pair(f0, f1, hp, lp);
    int w = ilv(j);
    dst[(size_t)r * IN_CH + w] = hp;
    dst[(size_t)r * IN_CH + w + 2] = lp;
}

// ---------------- bf16-split tensor-core GEMM: multi-job, depth-3 pipeline ----------------
struct GJob {
    const uint32_t* B;
    const float* bias;
    float* C;
    uint32_t* Cs;
    int aoff, K, ldc, coff, csld, csoff, act;
};
struct GLaunch {
    GJob j[3];
    int jid[4];
    int ctile[4];
};

__device__ __forceinline__ void bload(const uint32_t* __restrict__ Ahl, int lda, int aoff,
                                      const uint32_t* __restrict__ Bhl, int K,
                                      int M, int row0, int col0,
                                      int tid, int kc, uint32_t* sb) {
#pragma unroll
    for (int it = 0; it < 8; it++) {
        int s = tid * 8 + it;
        int r = (s >> 2) & 127;
        int j = s & 3;
        bool isB = s >= 512;
        uint32_t da = (uint32_t)__cvta_generic_to_shared(sb + (isB ? 2048 : 0) + r * 16 + 4 * j);
        const uint32_t* g;
        bool pred = true;
        if (!isB) {
            int ar = row0 + r;
            pred = ar < M;
            g = Ahl + (size_t)(pred ? ar : 0) * lda + aoff + kc * 16 + 4 * j;
        } else {
            g = Bhl + (size_t)(col0 + r) * K + kc * 16 + 4 * j;
        }
        cp_async16(da, g, pred);
    }
    asm volatile("cp.async.commit_group;");
}

__global__ void __launch_bounds__(128) bgemm(GLaunch L, const uint32_t* __restrict__ Ahl,
                                             int lda, int M) {
    extern __shared__ uint32_t sm[];
    const GJob J = L.j[L.jid[blockIdx.x]];
    const int col0 = L.ctile[blockIdx.x] * 128;
    const int tid = threadIdx.x;
    const int lane = tid & 31;
    const int warp = tid >> 5;
    const int g = lane >> 2;
    const int t = lane & 3;
    const int wrow = (warp >> 1) * 64;
    const int wcol = (warp & 1) * 64;
    const int row0 = blockIdx.y * 128;
    const int nk = J.K >> 4;

    float acc[4][8][4];
#pragma unroll
    for (int mt = 0; mt < 4; mt++)
#pragma unroll
        for (int nt = 0; nt < 8; nt++)
#pragma unroll
            for (int i = 0; i < 4; i++) acc[mt][nt][i] = 0.f;

    bload(Ahl, lda, J.aoff, J.B, J.K, M, row0, col0, tid, 0, sm);
    bload(Ahl, lda, J.aoff, J.B, J.K, M, row0, col0, tid, 1, sm + 4096);

    for (int c = 0; c < nk; c++) {
        if (c + 1 < nk)
            asm volatile("cp.async.wait_group 1;");
        else
            asm volatile("cp.async.wait_group 0;");
        __syncthreads();
        if (c + 2 < nk) {
            int nb = c + 2; nb -= (nb / 3) * 3;
            bload(Ahl, lda, J.aoff, J.B, J.K, M, row0, col0, tid, c + 2, sm + nb * 4096);
        }
        int cb = c; cb -= (cb / 3) * 3;
        const uint32_t* As = sm + cb * 4096;
        const uint32_t* Bs = As + 2048;

        uint32_t bhi[8][2], blo[8][2];
#pragma unroll
        for (int nt = 0; nt < 8; nt++) {
            int cc = wcol + nt * 8 + g;
            uint4 bb = *(const uint4*)(Bs + cc * 16 + 4 * t);
            bhi[nt][0] = bb.x; bhi[nt][1] = bb.y;
            blo[nt][0] = bb.z; blo[nt][1] = bb.w;
        }
#pragma unroll
        for (int mt = 0; mt < 4; mt++) {
            int r = wrow + mt * 16 + g;
            uint4 a0 = *(const uint4*)(As + r * 16 + 4 * t);
            uint4 a8 = *(const uint4*)(As + (r + 8) * 16 + 4 * t);
            uint32_t ahi[4] = {a0.x, a8.x, a0.y, a8.y};
            uint32_t alo[4] = {a0.z, a8.z, a0.w, a8.w};
#pragma unroll
            for (int nt = 0; nt < 8; nt++) {
                mma_bf16(acc[mt][nt], alo, bhi[nt]);
                mma_bf16(acc[mt][nt], ahi, blo[nt]);
                mma_bf16(acc[mt][nt], ahi, bhi[nt]);
            }
        }
    }

#pragma unroll
    for (int mt = 0; mt < 4; mt++) {
#pragma unroll
        for (int nt = 0; nt < 8; nt++) {
            int r0 = row0 + wrow + mt * 16 + g;
            int cl = wcol + nt * 8 + 2 * t;
            int cg = col0 + cl;
            float b0 = J.bias ? J.bias[cg] : 0.f;
            float b1 = J.bias ? J.bias[cg + 1] : 0.f;
            float v00 = acc[mt][nt][0] + b0, v01 = acc[mt][nt][1] + b1;
            float v10 = acc[mt][nt][2] + b0, v11 = acc[mt][nt][3] + b1;
            if (J.act == 1) {
                v00 = v00 > 0.f ? v00 : 0.01f * v00;
                v01 = v01 > 0.f ? v01 : 0.01f * v01;
                v10 = v10 > 0.f ? v10 : 0.01f * v10;
                v11 = v11 > 0.f ? v11 : 0.01f * v11;
            }
            if (r0 < M) {
                J.C[(size_t)r0 * J.ldc + J.coff + cg] = v00;
                J.C[(size_t)r0 * J.ldc + J.coff + cg + 1] = v01;
                if (J.Cs) {
                    uint32_t hp, lp;
                    split_pair(v00, v01, hp, lp);
                    int w = J.csoff + ilv(cl >> 1);
                    J.Cs[(size_t)r0 * J.csld + w] = hp;
                    J.Cs[(size_t)r0 * J.csld + w + 2] = lp;
                }
            }
            if (r0 + 8 < M) {
                J.C[(size_t)(r0 + 8) * J.ldc + J.coff + cg] = v10;
                J.C[(size_t)(r0 + 8) * J.ldc + J.coff + cg + 1] = v11;
                if (J.Cs) {
                    uint32_t hp, lp;
                    split_pair(v10, v11, hp, lp);
                    int w = J.csoff + ilv(cl >> 1);
                    J.Cs[(size_t)(r0 + 8) * J.csld + w] = hp;
                    J.Cs[(size_t)(r0 + 8) * J.csld + w + 2] = lp;
                }
            }
        }
    }
}

// ---------------- CSR build ----------------
__global__ void hist_kernel(const int* __restrict__ dst, int* __restrict__ deg, int n_e) {
    int e = blockIdx.x * blockDim.x + threadIdx.x;
    if (e < n_e) atomicAdd(&deg[dst[e]], 1);
}

__global__ void scan_block(const int* __restrict__ in, int* __restrict__ out,
                           int* __restrict__ bsum, int n) {
    __shared__ int s[256];
    int t = threadIdx.x;
    int base = blockIdx.x * 1024 + t * 4;
    int v[4];
#pragma unroll
    for (int j = 0; j < 4; j++) v[j] = (base + j < n) ? in[base + j] : 0;
    int tsum = v[0] + v[1] + v[2] + v[3];
    s[t] = tsum;
    __syncthreads();
    for (int off = 1; off < 256; off <<= 1) {
        int x = (t >= off) ? s[t - off] : 0;
        __syncthreads();
        s[t] += x;
        __syncthreads();
    }
    int exc = s[t] - tsum;
    if (t == 255) bsum[blockIdx.x] = s[t];
    int run = exc;
#pragma unroll
    for (int j = 0; j < 4; j++) {
        if (base + j < n) out[base + j] = run;
        run += v[j];
    }
}

__global__ void scan_bsum(int* __restrict__ bsum, int nb) {
    __shared__ int s[128];
    int t = threadIdx.x;
    int orig = (t < nb) ? bsum[t] : 0;
    s[t] = orig;
    __syncthreads();
    for (int off = 1; off < 128; off <<= 1) {
        int x = (t >= off) ? s[t - off] : 0;
        __syncthreads();
        s[t] += x;
        __syncthreads();
    }
    if (t < nb) bsum[t] = s[t] - orig;
}

__global__ void scan_fixup(int* __restrict__ ptr, const int* __restrict__ bsum,
                           int* __restrict__ cur, int n, int total) {
    int i = blockIdx.x * blockDim.x + threadIdx.x;
    if (i < n) {
        int p = ptr[i] + bsum[i >> 10];
        ptr[i] = p;
        cur[i] = p;
    }
    if (i == 0) ptr[n] = total;
}

__global__ void scatter_csr(const int* __restrict__ src, const int* __restrict__ dst,
                            int* __restrict__ cur, int* __restrict__ csr_src, int n_e) {
    int e = blockIdx.x * blockDim.x + threadIdx.x;
    if (e >= n_e) return;
    int p = atomicAdd(&cur[dst[e]], 1);
    csr_src[p] = src[e];
}

__global__ void build_gptr(const int* __restrict__ batch, int* __restrict__ gptr, int n) {
    int i = blockIdx.x * blockDim.x + threadIdx.x;
    if (i >= n) return;
    int b = batch[i];
    int prev = (i == 0) ? -1 : batch[i - 1];
    for (int g = prev + 1; g <= b; g++) gptr[g] = i;
    if (i == n - 1)
        for (int g = b + 1; g <= GG; g++) gptr[g] = n;
}

// ---------------- fused GAT aggregation (warp per destination node) ----------------
__global__ void gat_aggregate(const int* __restrict__ ptr, const int* __restrict__ csr,
                              const float* __restrict__ asrc, const float* __restrict__ adst,
                              const float* __restrict__ xw, const float* __restrict__ bias,
                              uint32_t* __restrict__ hs, int n_rows) {
    int row = blockIdx.x * 8 + (threadIdx.x >> 5);
    int lane = threadIdx.x & 31;
    if (row >= n_rows) return;
    int start = ptr[row], end = ptr[row + 1];
    float ad = adst[row];

    float m = -INFINITY;
    for (int e = start + lane; e < end; e += 32) {
        float a = asrc[csr[e]] + ad;
        a = a > 0.f ? a : 0.01f * a;
        m = fmaxf(m, a);
    }
    m = warp_max_all(m);

    float4 acc = make_float4(0.f, 0.f, 0.f, 0.f);
    float sum = 0.f;
    for (int base = start; base < end; base += 32) {
        int e = base + lane;
        float w = 0.f;
        int s = 0;
        if (e < end) {
            s = csr[e];
            float a = asrc[s] + ad;
            a = a > 0.f ? a : 0.01f * a;
            w = expf(a - m);
            sum += w;
        }
        int cnt = min(32, end - base);
        for (int j = 0; j < cnt; j++) {
            float wj = __shfl_sync(FULL, w, j);
            int sj = __shfl_sync(FULL, s, j);
            float4 v = ((const float4*)(xw + (size_t)sj * HH))[lane];
            acc.x += wj * v.x;
            acc.y += wj * v.y;
            acc.z += wj * v.z;
            acc.w += wj * v.w;
        }
    }
    sum = warp_sum_all(sum);
    float rinv = 1.f / (sum + 1e-16f);
    float4 b4 = ((const float4*)bias)[lane];
    float o0 = acc.x * rinv + b4.x;
    float o1 = acc.y * rinv + b4.y;
    float o2 = acc.z * rinv + b4.z;
    float o3 = acc.w * rinv + b4.w;
    o0 = o0 > 0.f ? o0 : expf(o0) - 1.f;
    o1 = o1 > 0.f ? o1 : expf(o1) - 1.f;
    o2 = o2 > 0.f ? o2 : expf(o2) - 1.f;
    o3 = o3 > 0.f ? o3 : expf(o3) - 1.f;
    uint32_t hp0, lp0, hp1, lp1;
    split_pair(o0, o1, hp0, lp0);
    split_pair(o2, o3, hp1, lp1);
    uint32_t* hr = hs + (size_t)row * 256;
    int w0 = ilv(2 * lane), w1 = ilv(2 * lane + 1);
    hr[w0] = hp0;
    hr[w0 + 2] = lp0;
    hr[w1] = hp1;
    hr[w1 + 2] = lp1;
}

// ---------------- GATEConv per-node attention scalars ----------------
__global__ void gate_node_atts(const float* __restrict__ tmp, const float* __restrict__ W1,
                               const float* __restrict__ att_l, const float* __restrict__ x0,
                               const float* __restrict__ att_r, float* __restrict__ asrc,
                               float* __restrict__ adst, int n_rows) {
    int w = (blockIdx.x * blockDim.x + threadIdx.x) >> 5;
    int lane = threadIdx.x & 31;
    if (w >= n_rows) return;
    float4 tv = ((const float4*)(tmp + (size_t)w * HH))[lane];
    float4 xv = ((const float4*)(x0 + (size_t)w * HH))[lane];
    float s1 = 0.f, s2 = 0.f;
    const float* t = &tv.x;
    const float* xp = &xv.x;
#pragma unroll
    for (int j = 0; j < 4; j++) {
        int k = lane * 4 + j;
        float xe = t[j] + W1[(size_t)k * (HH + 1) + HH];
        xe = xe > 0.f ? xe : 0.01f * xe;
        s1 += xe * att_l[k];
        s2 += xp[j] * att_r[k];
    }
    s1 = warp_sum_all(s1);
    s2 = warp_sum_all(s2);
    if (lane == 0) { asrc[w] = s1; adst[w] = s2; }
}

__global__ void node_two_dots(const float* __restrict__ xw, const float* __restrict__ v1,
                              const float* __restrict__ v2, float* __restrict__ o1,
                              float* __restrict__ o2, int n_rows) {
    int w = (blockIdx.x * blockDim.x + threadIdx.x) >> 5;
    int lane = threadIdx.x & 31;
    if (w >= n_rows) return;
    float4 xv = ((const float4*)(xw + (size_t)w * HH))[lane];
    const float* xp = &xv.x;
    float s1 = 0.f, s2 = 0.f;
#pragma unroll
    for (int j = 0; j < 4; j++) {
        int k = lane * 4 + j;
        s1 += xp[j] * v1[k];
        s2 += xp[j] * v2[k];
    }
    s1 = warp_sum_all(s1);
    s2 = warp_sum_all(s2);
    if (lane == 0) { o1[w] = s1; o2[w] = s2; }
}

__global__ void node_one_dot(const float* __restrict__ xw, const float* __restrict__ v1,
                             float* __restrict__ o1, int n_rows) {
    int w = (blockIdx.x * blockDim.x + threadIdx.x) >> 5;
    int lane = threadIdx.x & 31;
    if (w >= n_rows) return;
    float4 xv = ((const float4*)(xw + (size_t)w * HH))[lane];
    const float* xp = &xv.x;
    float s1 = 0.f;
#pragma unroll
    for (int j = 0; j < 4; j++) s1 += xp[j] * v1[lane * 4 + j];
    s1 = warp_sum_all(s1);
    if (lane == 0) o1[w] = s1;
}

// ---------------- GRU combine (rz-concat form) ----------------
__global__ void gru_combine2(const float* __restrict__ grz, const float* __restrict__ gih,
                             const float* __restrict__ hprev, float* __restrict__ outp,
                             uint32_t* __restrict__ outs, int rows) {
    int idx = blockIdx.x * blockDim.x + threadIdx.x;
    if (idx >= rows * 64) return;
    int r = idx >> 6, cp = idx & 63;
    float2 vr = *(const float2*)(grz + (size_t)r * 256 + 2 * cp);
    float2 vz = *(const float2*)(grz + (size_t)r * 256 + 128 + 2 * cp);
    float2 vin = *(const float2*)(gih + (size_t)r * 256 + 2 * cp);
    float2 vhn = *(const float2*)(gih + (size_t)r * 256 + 128 + 2 * cp);
    float2 hp2 = *(const float2*)(hprev + (size_t)r * HH + 2 * cp);
    float o[2];
    {
        float rr = 1.f / (1.f + expf(-vr.x));
        float z = 1.f / (1.f + expf(-vz.x));
        float n = tanhf(vin.x + rr * vhn.x);
        float v = (1.f - z) * n + z * hp2.x;
        o[0] = v > 0.f ? v : 0.f;
    }
    {
        float rr = 1.f / (1.f + expf(-vr.y));
        float z = 1.f / (1.f + expf(-vz.y));
        float n = tanhf(vin.y + rr * vhn.y);
        float v = (1.f - z) * n + z * hp2.y;
        o[1] = v > 0.f ? v : 0.f;
    }
    ((float2*)(outp + (size_t)r * HH))[cp] = make_float2(o[0], o[1]);
    uint32_t hp, lp;
    split_pair(o[0], o[1], hp, lp);
    int w = 128 + ilv(cp);
    outs[(size_t)r * 256 + w] = hp;
    outs[(size_t)r * 256 + w + 2] = lp;
}

// ---------------- molecule readout (warp per graph) ----------------
__global__ void graph_sum(const float* __restrict__ xc, const int* __restrict__ gptr,
                          float* __restrict__ outG, uint32_t* __restrict__ outGs, int n_g) {
    int g = blockIdx.x * 8 + (threadIdx.x >> 5);
    int lane = threadIdx.x & 31;
    if (g >= n_g) return;
    int start = gptr[g], end = gptr[g + 1];
    float4 acc = make_float4(0.f, 0.f, 0.f, 0.f);
    for (int i = start; i < end; i++) {
        float4 v = ((const float4*)(xc + (size_t)i * HH))[lane];
        acc.x += v.x; acc.y += v.y; acc.z += v.z; acc.w += v.w;
    }
    acc.x = fmaxf(acc.x, 0.f);
    acc.y = fmaxf(acc.y, 0.f);
    acc.z = fmaxf(acc.z, 0.f);
    acc.w = fmaxf(acc.w, 0.f);
    ((float4*)(outG + (size_t)g * HH))[lane] = acc;
    uint32_t hp0, lp0, hp1, lp1;
    split_pair(acc.x, acc.y, hp0, lp0);
    split_pair(acc.z, acc.w, hp1, lp1);
    uint32_t* orow = outGs + (size_t)g * 256;
    int w0 = 128 + ilv(2 * lane), w1 = 128 + ilv(2 * lane + 1);
    orow[w0] = hp0;
    orow[w0 + 2] = lp0;
    orow[w1] = hp1;
    orow[w1 + 2] = lp1;
}

__global__ void compute_vvec(const float* __restrict__ molW, const float* __restrict__ attdst,
                             float* __restrict__ v) {
    int k = threadIdx.x;
    float s = 0.f;
    for (int j = 0; j < HH; j++) s += molW[(size_t)j * HH + k] * attdst[j];
    v[k] = s;
}

__global__ void mol_timestep(const float* __restrict__ outG, const float* __restrict__ vvec,
                             const int* __restrict__ gptr, const float* __restrict__ asrc,
                             const float* __restrict__ xw, const float* __restrict__ bias,
                             uint32_t* __restrict__ hGs, int n_g) {
    int g = blockIdx.x * 8 + (threadIdx.x >> 5);
    int lane = threadIdx.x & 31;
    if (g >= n_g) return;
    float4 ov = ((const float4*)(outG + (size_t)g * HH))[lane];
    float4 vv = ((const float4*)vvec)[lane];
    float ad = warp_sum_all(ov.x * vv.x + ov.y * vv.y + ov.z * vv.z + ov.w * vv.w);

    int start = gptr[g], end = gptr[g + 1];
    float m = -INFINITY;
    for (int i = start + lane; i < end; i += 32) {
        float a = asrc[i] + ad;
        a = a > 0.f ? a : 0.01f * a;
        m = fmaxf(m, a);
    }
    m = warp_max_all(m);

    float4 acc = make_float4(0.f, 0.f, 0.f, 0.f);
    float sum = 0.f;
    for (int base = start; base < end; base += 32) {
        int i = base + lane;
        float w = 0.f;
        if (i < end) {
            float a = asrc[i] + ad;
            a = a > 0.f ? a : 0.01f * a;
            w = expf(a - m);
            sum += w;
        }
        int cnt = min(32, end - base);
        for (int j = 0; j < cnt; j++) {
            float wj = __shfl_sync(FULL, w, j);
            float4 v = ((const float4*)(xw + (size_t)(base + j) * HH))[lane];
            acc.x += wj * v.x;
            acc.y += wj * v.y;
            acc.z += wj * v.z;
            acc.w += wj * v.w;
        }
    }
    sum = warp_sum_all(sum);
    float rinv = 1.f / (sum + 1e-16f);
    float4 b4 = ((const float4*)bias)[lane];
    float o0 = acc.x * rinv + b4.x;
    float o1 = acc.y * rinv + b4.y;
    float o2 = acc.z * rinv + b4.z;
    float o3 = acc.w * rinv + b4.w;
    o0 = o0 > 0.f ? o0 : expf(o0) - 1.f;
    o1 = o1 > 0.f ? o1 : expf(o1) - 1.f;
    o2 = o2 > 0.f ? o2 : expf(o2) - 1.f;
    o3 = o3 > 0.f ? o3 : expf(o3) - 1.f;
    uint32_t hp0, lp0, hp1, lp1;
    split_pair(o0, o1, hp0, lp0);
    split_pair(o2, o3, hp1, lp1);
    uint32_t* hrow = hGs + (size_t)g * 256;
    int w0 = ilv(2 * lane), w1 = ilv(2 * lane + 1);
    hrow[w0] = hp0;
    hrow[w0 + 2] = lp0;
    hrow[w1] = hp1;
    hrow[w1 + 2] = lp1;
}

__global__ void final_out(const float* __restrict__ outG, const float* __restrict__ W,
                          const float* __restrict__ b, float* __restrict__ y, int g_rows) {
    int g = (blockIdx.x * blockDim.x + threadIdx.x) >> 5;
    int lane = threadIdx.x & 31;
    if (g >= g_rows) return;
    float4 v = ((const float4*)(outG + (size_t)g * HH))[lane];
    const float* vp = &v.x;
    float s = 0.f;
#pragma unroll
    for (int j = 0; j < 4; j++) s += vp[j] * W[lane * 4 + j];
    s = warp_sum_all(s);
    if (lane == 0) y[g] = s + b[0];
}

// ---------------- host ----------------
static inline int cdiv(int a, int b) { return (a + b - 1) / b; }

static inline GJob mkjob(const uint32_t* B, const float* bias, float* C, uint32_t* Cs,
                         int aoff, int K, int ldc, int coff, int csld, int csoff, int act) {
    GJob j;
    j.B = B; j.bias = bias; j.C = C; j.Cs = Cs;
    j.aoff = aoff; j.K = K; j.ldc = ldc; j.coff = coff;
    j.csld = csld; j.csoff = csoff; j.act = act;
    return j;
}

extern "C" void kernel_launch(void* const* d_in, const int* in_sizes, int n_in,
                              void* d_out, int out_size) {
    const float* x = (const float*)d_in[0];
    const int* ei = (const int*)d_in[1];
    const int* batch = (const int*)d_in[2];
    const float* lin1_W = (const float*)d_in[3];
    const float* lin1_b = (const float*)d_in[4];
    const float* gate_W1 = (const float*)d_in[5];
    const float* gate_W2 = (const float*)d_in[6];
    const float* gate_att_l = (const float*)d_in[7];
    const float* gate_att_r = (const float*)d_in[8];
    const float* gate_bias = (const float*)d_in[9];
    const float* gru0_Wi = (const float*)d_in[10];
    const float* gru0_bi = (const float*)d_in[11];
    const float* gru0_Wh = (const float*)d_in[12];
    const float* gru0_bh = (const float*)d_in[13];
    const float* atom_W = (const float*)d_in[14];
    const float* atom_att_src = (const float*)d_in[15];
    const float* atom_att_dst = (const float*)d_in[16];
    const float* atom_bias = (const float*)d_in[17];
    const float* atom_gru_Wi = (const float*)d_in[18];
    const float* atom_gru_bi = (const float*)d_in[19];
    const float* atom_gru_Wh = (const float*)d_in[20];
    const float* atom_gru_bh = (const float*)d_in[21];
    const float* mol_W = (const float*)d_in[22];
    const float* mol_att_src = (const float*)d_in[23];
    const float* mol_att_dst = (const float*)d_in[24];
    const float* mol_bias = (const float*)d_in[25];
    const float* mol_gru_Wi = (const float*)d_in[26];
    const float* mol_gru_bi = (const float*)d_in[27];
    const float* mol_gru_Wh = (const float*)d_in[28];
    const float* mol_gru_bh = (const float*)d_in[29];
    const float* lin2_W = (const float*)d_in[30];
    const float* lin2_b = (const float*)d_in[31];

    const int* src = ei;
    const int* dst = ei + EE;

    cudaFuncSetAttribute(bgemm, cudaFuncAttributeMaxDynamicSharedMemorySize, BG_SMEM);

    float *x0, *xw, *xc, *grz, *gih, *asrc, *adst, *outG, *grzG, *gihG, *vvec;
    int *deg, *ptr, *cur, *csr_src, *bsum, *gptr;
    uint32_t *sx, *shx, *shxG;
    uint32_t *wl1, *wg1, *wg2, *watom, *wmol;
    uint32_t *wrz0, *wrza, *wrzm, *win0, *whn0, *wina, *whna, *winm, *whnm;
    float *brz0, *brza, *brzm;
    cudaGetSymbolAddress((void**)&x0, d_x0);
    cudaGetSymbolAddress((void**)&xw, d_xw);
    cudaGetSymbolAddress((void**)&xc, d_xc);
    cudaGetSymbolAddress((void**)&grz, d_gi);
    cudaGetSymbolAddress((void**)&gih, d_gh);
    cudaGetSymbolAddress((void**)&asrc, d_asrc);
    cudaGetSymbolAddress((void**)&adst, d_adst);
    cudaGetSymbolAddress((void**)&outG, d_outG);
    cudaGetSymbolAddress((void**)&grzG, d_giG);
    cudaGetSymbolAddress((void**)&gihG, d_ghG);
    cudaGetSymbolAddress((void**)&vvec, d_vvec);
    cudaGetSymbolAddress((void**)&deg, d_deg);
    cudaGetSymbolAddress((void**)&ptr, d_ptr);
    cudaGetSymbolAddress((void**)&cur, d_cur);
    cudaGetSymbolAddress((void**)&csr_src, d_csr_src);
    cudaGetSymbolAddress((void**)&bsum, d_bsum);
    cudaGetSymbolAddress((void**)&gptr, d_gptr);
    cudaGetSymbolAddress((void**)&sx, s_x);
    cudaGetSymbolAddress((void**)&shx, s_hx);
    cudaGetSymbolAddress((void**)&shxG, s_hxG);
    cudaGetSymbolAddress((void**)&wl1, w_lin1);
    cudaGetSymbolAddress((void**)&wg1, w_g1);
    cudaGetSymbolAddress((void**)&wg2, w_g2);
    cudaGetSymbolAddress((void**)&watom, w_atom);
    cudaGetSymbolAddress((void**)&wmol, w_mol);
    cudaGetSymbolAddress((void**)&wrz0, w_rz0);
    cudaGetSymbolAddress((void**)&wrza, w_rza);
    cudaGetSymbolAddress((void**)&wrzm, w_rzm);
    cudaGetSymbolAddress((void**)&win0, w_in0);
    cudaGetSymbolAddress((void**)&whn0, w_hn0);
    cudaGetSymbolAddress((void**)&wina, w_ina);
    cudaGetSymbolAddress((void**)&whna, w_hna);
    cudaGetSymbolAddress((void**)&winm, w_inm);
    cudaGetSymbolAddress((void**)&whnm, w_hnm);
    cudaGetSymbolAddress((void**)&brz0, b_rz0);
    cudaGetSymbolAddress((void**)&brza, b_rza);
    cudaGetSymbolAddress((void**)&brzm, b_rzm);

    int wpb_n = cdiv(NN, 8);
    int wpb_g = cdiv(GG, 8);
    const int nscan = cdiv(NN, 1024);
    const int rt_n = cdiv(NN, 128);
    const int rt_g = cdiv(GG, 128);

    // ---- batched weight prep ----
    SDescs sd;
    sd.d[0] = {lin1_W, wl1, IN_CH, HH, IN_CH};
    sd.d[1] = {gate_W1, wg1, HH + 1, HH, HH};
    sd.d[2] = {gate_W2, wg2, HH, HH, HH};
    sd.d[3] = {mol_W, wmol, HH, HH, HH};
    sd.d[4] = {atom_W, watom, HH, HH, HH};
    sd.d[5] = {atom_W + (size_t)HH * HH, watom + (size_t)HH * HH, HH, HH, HH};
    sd.d[6] = {gru0_Wi + 256 * HH, win0, HH, HH, HH};
    sd.d[7] = {gru0_Wh + 256 * HH, whn0, HH, HH, HH};
    sd.d[8] = {atom_gru_Wi + 256 * HH, wina, HH, HH, HH};
    sd.d[9] = {atom_gru_Wi + (size_t)H3 * HH + 256 * HH, wina + (size_t)HH * HH, HH, HH, HH};
    sd.d[10] = {atom_gru_Wh + 256 * HH, whna, HH, HH, HH};
    sd.d[11] = {atom_gru_Wh + (size_t)H3 * HH + 256 * HH, whna + (size_t)HH * HH, HH, HH, HH};
    sd.d[12] = {mol_gru_Wi + 256 * HH, winm, HH, HH, HH};
    sd.d[13] = {mol_gru_Wh + 256 * HH, whnm, HH, HH, HH};
    to_split_batch<<<dim3(14, 8), 256>>>(sd);

    CDescs cd;
    cd.d[0] = {gru0_Wi, gru0_Wh, wrz0, gru0_bi, gru0_bh, brz0};
    cd.d[1] = {atom_gru_Wi, atom_gru_Wh, wrza, atom_gru_bi, atom_gru_bh, brza};
    cd.d[2] = {atom_gru_Wi + (size_t)H3 * HH, atom_gru_Wh + (size_t)H3 * HH,
               wrza + 256 * 256, atom_gru_bi + H3, atom_gru_bh + H3, brza + 256};
    cd.d[3] = {mol_gru_Wi, mol_gru_Wh, wrzm, mol_gru_bi, mol_gru_bh, brzm};
    concat_rz_batch<<<dim3(4, 16), 256>>>(cd);

    to_split_x<<<cdiv(NN * 32, 256), 256>>>(x, sx);

    // ---- CSR + graph-pointer build ----
    cudaMemsetAsync(deg, 0, NN * sizeof(int));
    hist_kernel<<<cdiv(EE, 256), 256>>>(dst, deg, EE);
    scan_block<<<nscan, 256>>>(deg, ptr, bsum, NN);
    scan_bsum<<<1, 128>>>(bsum, nscan);
    scan_fixup<<<cdiv(NN, 256), 256>>>(ptr, bsum, cur, NN, EE);
    scatter_csr<<<cdiv(EE, 256), 256>>>(src, dst, cur, csr_src, EE);
    build_gptr<<<cdiv(NN, 256), 256>>>(batch, gptr, NN);

    GLaunch L;

    // x0 = lrelu(x @ lin1_W^T + b): fp32 + split into s_hx x-part
    L.j[0] = mkjob(wl1, lin1_b, x0, shx, 0, IN_CH, HH, 0, 256, 128, 1);
    L.jid[0] = 0; L.ctile[0] = 0;
    bgemm<<<dim3(1, rt_n), 128, BG_SMEM>>>(L, sx, IN_CH, NN);

    // ---- GATEConv: merged wg1 (-> gih temp) + wg2 (-> xw) ----
    L.j[0] = mkjob(wg1, nullptr, gih, nullptr, 128, HH, HH, 0, 0, 0, 0);
    L.j[1] = mkjob(wg2, nullptr, xw, nullptr, 128, HH, HH, 0, 0, 0, 0);
    L.jid[0] = 0; L.ctile[0] = 0;
    L.jid[1] = 1; L.ctile[1] = 0;
    bgemm<<<dim3(2, rt_n), 128, BG_SMEM>>>(L, shx, 256, NN);
    gate_node_atts<<<wpb_n, 256>>>(gih, gate_W1, gate_att_l, x0, gate_att_r, asrc, adst, NN);
    gat_aggregate<<<wpb_n, 256>>>(ptr, csr_src, asrc, adst, xw, gate_bias, shx, NN);
    // merged GRU gemms: rz (2 tiles) + in + hn
    L.j[0] = mkjob(wrz0, brz0, grz, nullptr, 0, 256, 256, 0, 0, 0, 0);
    L.j[1] = mkjob(win0, gru0_bi + 256, gih, nullptr, 0, HH, 256, 0, 0, 0, 0);
    L.j[2] = mkjob(whn0, gru0_bh + 256, gih, nullptr, 128, HH, 256, 128, 0, 0, 0);
    L.jid[0] = 0; L.ctile[0] = 0;
    L.jid[1] = 0; L.ctile[1] = 1;
    L.jid[2] = 1; L.ctile[2] = 0;
    L.jid[3] = 2; L.ctile[3] = 0;
    bgemm<<<dim3(4, rt_n), 128, BG_SMEM>>>(L, shx, 256, NN);
    gru_combine2<<<cdiv(NN * 64, 256), 256>>>(grz, gih, x0, xc, shx, NN);

    // ---- extra atom GAT + GRU layers ----
    for (int l = 0; l < 2; l++) {
        L.j[0] = mkjob(watom + (size_t)l * HH * HH, nullptr, xw, nullptr, 128, HH, HH, 0, 0, 0, 0);
        L.jid[0] = 0; L.ctile[0] = 0;
        bgemm<<<dim3(1, rt_n), 128, BG_SMEM>>>(L, shx, 256, NN);
        node_two_dots<<<wpb_n, 256>>>(xw, atom_att_src + l * HH, atom_att_dst + l * HH, asrc, adst, NN);
        gat_aggregate<<<wpb_n, 256>>>(ptr, csr_src, asrc, adst, xw, atom_bias + l * HH, shx, NN);
        L.j[0] = mkjob(wrza + (size_t)l * 256 * 256, brza + l * 256, grz, nullptr, 0, 256, 256, 0, 0, 0, 0);
        L.j[1] = mkjob(wina + (size_t)l * HH * HH, atom_gru_bi + l * H3 + 256, gih, nullptr, 0, HH, 256, 0, 0, 0, 0);
        L.j[2] = mkjob(whna + (size_t)l * HH * HH, atom_gru_bh + l * H3 + 256, gih, nullptr, 128, HH, 256, 128, 0, 0, 0);
        L.jid[0] = 0; L.ctile[0] = 0;
        L.jid[1] = 0; L.ctile[1] = 1;
        L.jid[2] = 1; L.ctile[2] = 0;
        L.jid[3] = 2; L.ctile[3] = 0;
        bgemm<<<dim3(4, rt_n), 128, BG_SMEM>>>(L, shx, 256, NN);
        gru_combine2<<<cdiv(NN * 64, 256), 256>>>(grz, gih, xc, xc, shx, NN);
    }

    // ---- molecule readout ----
    graph_sum<<<wpb_g, 256>>>(xc, gptr, outG, shxG, GG);
    L.j[0] = mkjob(wmol, nullptr, xw, nullptr, 128, HH, HH, 0, 0, 0, 0);
    L.jid[0] = 0; L.ctile[0] = 0;
    bgemm<<<dim3(1, rt_n), 128, BG_SMEM>>>(L, shx, 256, NN);
    node_one_dot<<<wpb_n, 256>>>(xw, mol_att_src, asrc, NN);
    compute_vvec<<<1, HH>>>(mol_W, mol_att_dst, vvec);

    for (int t = 0; t < 2; t++) {
        mol_timestep<<<wpb_g, 256>>>(outG, vvec, gptr, asrc, xw, mol_bias, shxG, GG);
        L.j[0] = mkjob(wrzm, brzm, grzG, nullptr, 0, 256, 256, 0, 0, 0, 0);
        L.j[1] = mkjob(winm, mol_gru_bi + 256, gihG, nullptr, 0, HH, 256, 0, 0, 0, 0);
        L.j[2] = mkjob(whnm, mol_gru_bh + 256, gihG, nullptr, 128, HH, 256, 128, 0, 0, 0);
        L.jid[0] = 0; L.ctile[0] = 0;
        L.jid[1] = 0; L.ctile[1] = 1;
        L.jid[2] = 1; L.ctile[2] = 0;
        L.jid[3] = 2; L.ctile[3] = 0;
        bgemm<<<dim3(4, rt_g), 128, BG_SMEM>>>(L, shxG, 256, GG);
        gru_combine2<<<cdiv(GG * 64, 256), 256>>>(grzG, gihG, outG, outG, shxG, GG);
    }

    final_out<<<wpb_g, 256>>>(outG, lin2_W, lin2_b, (float*)d_out, GG);
}